// round 8
// baseline (speedup 1.0000x reference)
#include <cuda_runtime.h>
#include <cuda_bf16.h>
#include <cstdint>

#define NTOK 4096
#define HID 256
#define NHEADS 8
#define HD 32
#define EPSBN 1e-5f
#define QSCALE 0.17677669529663687f       // 1/sqrt(32)
#define LOG2E  1.4426950408889634f
#define QK2SCALE (QSCALE * LOG2E)         // folded so softmax uses exp2

// ------------------- scratch (device globals; no allocation) -------------------
__device__ __nv_bfloat16 g_Qh[NTOK * HID];
__device__ __nv_bfloat16 g_Ql[NTOK * HID];
__device__ __nv_bfloat16 g_Kh[NTOK * HID];
__device__ __nv_bfloat16 g_Kl[NTOK * HID];
__device__ __nv_bfloat16 g_Vh[NTOK * HID];
__device__ __nv_bfloat16 g_Vl[NTOK * HID];
__device__ float g_AO[NTOK * HID];
__device__ float g_X[NTOK * HID];
__device__ float g_X1[NTOK * HID];
__device__ float g_Mid[NTOK * 2 * HID];
__device__ float g_F[NTOK * HID];
__device__ float g_psum[128 * HID];
__device__ float g_psq[128 * HID];
__device__ float g_scaleC[HID];
__device__ float g_shiftC[HID];

// ------------------- helpers -------------------
__device__ __forceinline__ void mma_bf16(float* c, const uint32_t* a, const uint32_t* b)
{
    asm volatile(
        "mma.sync.aligned.m16n8k16.row.col.f32.bf16.bf16.f32 "
        "{%0,%1,%2,%3}, {%4,%5,%6,%7}, {%8,%9}, {%0,%1,%2,%3};"
        : "+f"(c[0]), "+f"(c[1]), "+f"(c[2]), "+f"(c[3])
        : "r"(a[0]), "r"(a[1]), "r"(a[2]), "r"(a[3]), "r"(b[0]), "r"(b[1]));
}

// pack {lo=x, hi=y} to bf16x2 hi; residual pair to lo.
__device__ __forceinline__ void split_pack(float x, float y, uint32_t& hi, uint32_t& lo)
{
    uint32_t h;
    asm("cvt.rn.bf16x2.f32 %0, %1, %2;" : "=r"(h) : "f"(y), "f"(x));
    float xr = __uint_as_float(h << 16);
    float yr = __uint_as_float(h & 0xffff0000u);
    float xl = x - xr, yl = y - yr;
    uint32_t l;
    asm("cvt.rn.bf16x2.f32 %0, %1, %2;" : "=r"(l) : "f"(yl), "f"(xl));
    hi = h; lo = l;
}

__device__ __forceinline__ float ex2(float x)
{
    float r;
    asm("ex2.approx.ftz.f32 %0, %1;" : "=f"(r) : "f"(x));
    return r;
}

__device__ __forceinline__ uint32_t scvta(const void* p)
{
    return (uint32_t)__cvta_generic_to_shared(p);
}

__device__ __forceinline__ void ldsm_x4(uint32_t* d, uint32_t addr)
{
    asm volatile("ldmatrix.sync.aligned.m8n8.x4.shared.b16 {%0,%1,%2,%3}, [%4];"
                 : "=r"(d[0]), "=r"(d[1]), "=r"(d[2]), "=r"(d[3]) : "r"(addr));
}

__device__ __forceinline__ void ldsm_x4_t(uint32_t* d, uint32_t addr)
{
    asm volatile("ldmatrix.sync.aligned.m8n8.x4.trans.shared.b16 {%0,%1,%2,%3}, [%4];"
                 : "=r"(d[0]), "=r"(d[1]), "=r"(d[2]), "=r"(d[3]) : "r"(addr));
}

// ------------------- tensor-core GEMM -------------------
// mode 0: C = (A@W^T + bias)*scale [opt relu] as f32
// mode 1: same value, stored as bf16 hi/lo split planes Ch, Cl
#define GKP 40

__device__ __forceinline__ void gemm_body(
    const float* __restrict__ A, const float* __restrict__ W,
    const float* __restrict__ bias, float* __restrict__ C,
    __nv_bfloat16* __restrict__ Ch, __nv_bfloat16* __restrict__ Cl,
    int Nout, int K, float scale, int relu, int mode,
    __nv_bfloat16* Ah, __nv_bfloat16* Al, __nv_bfloat16* Wh, __nv_bfloat16* Wl)
{
    const int tid = threadIdx.x, w = tid >> 5, lane = tid & 31;
    const int qr = lane >> 2, qc2 = (lane & 3) * 2;
    const int i0 = blockIdx.y * 128, j0 = blockIdx.x * 64;
    const int r0 = w * 16;

    float acc[8][4] = {};

    const int arow = r0 + ((lane >> 3) & 1) * 8 + (lane & 7);
    const int acol = (lane >> 4) * 8;
    const int brow = (lane & 7);
    const int bcol = (lane >> 3) * 8;

    const uint32_t ahb = scvta(Ah), alb = scvta(Al);
    const uint32_t whb = scvta(Wh), wlb = scvta(Wl);

    for (int kk = 0; kk < K; kk += 32) {
        #pragma unroll
        for (int t = 0; t < 4; t++) {
            int j = tid + t * 256;
            int r = j >> 3, c4 = (j & 7) * 4;
            float4 av = *(const float4*)&A[(size_t)(i0 + r) * K + kk + c4];
            uint32_t h01, l01, h23, l23;
            split_pack(av.x, av.y, h01, l01);
            split_pack(av.z, av.w, h23, l23);
            *(uint32_t*)&Ah[r * GKP + c4]     = h01;
            *(uint32_t*)&Ah[r * GKP + c4 + 2] = h23;
            *(uint32_t*)&Al[r * GKP + c4]     = l01;
            *(uint32_t*)&Al[r * GKP + c4 + 2] = l23;
        }
        #pragma unroll
        for (int t = 0; t < 2; t++) {
            int j = tid + t * 256;
            int r = j >> 3, c4 = (j & 7) * 4;
            float4 wv = *(const float4*)&W[(size_t)(j0 + r) * K + kk + c4];
            uint32_t h01, l01, h23, l23;
            split_pack(wv.x, wv.y, h01, l01);
            split_pack(wv.z, wv.w, h23, l23);
            *(uint32_t*)&Wh[r * GKP + c4]     = h01;
            *(uint32_t*)&Wh[r * GKP + c4 + 2] = h23;
            *(uint32_t*)&Wl[r * GKP + c4]     = l01;
            *(uint32_t*)&Wl[r * GKP + c4 + 2] = l23;
        }
        __syncthreads();

        uint32_t ah[2][4], al[2][4];
        #pragma unroll
        for (int ks = 0; ks < 2; ks++) {
            uint32_t off = (uint32_t)((arow * GKP + ks * 16 + acol) * 2);
            ldsm_x4(ah[ks], ahb + off);
            ldsm_x4(al[ks], alb + off);
        }
        #pragma unroll
        for (int nt = 0; nt < 8; nt++) {
            uint32_t bh[4], bl[4];
            uint32_t off = (uint32_t)(((nt * 8 + brow) * GKP + bcol) * 2);
            ldsm_x4(bh, whb + off);
            ldsm_x4(bl, wlb + off);
            mma_bf16(acc[nt], ah[0], bh);
            mma_bf16(acc[nt], al[0], bh);
            mma_bf16(acc[nt], ah[0], bl);
            mma_bf16(acc[nt], ah[1], bh + 2);
            mma_bf16(acc[nt], al[1], bh + 2);
            mma_bf16(acc[nt], ah[1], bl + 2);
        }
        __syncthreads();
    }

    const int ra = i0 + r0 + qr, rb = ra + 8;
    #pragma unroll
    for (int nt = 0; nt < 8; nt++) {
        int j = j0 + nt * 8 + qc2;
        float b0 = bias[j], b1 = bias[j + 1];
        float v00 = (acc[nt][0] + b0) * scale;
        float v01 = (acc[nt][1] + b1) * scale;
        float v10 = (acc[nt][2] + b0) * scale;
        float v11 = (acc[nt][3] + b1) * scale;
        if (relu) {
            v00 = fmaxf(v00, 0.f); v01 = fmaxf(v01, 0.f);
            v10 = fmaxf(v10, 0.f); v11 = fmaxf(v11, 0.f);
        }
        if (mode == 0) {
            *(float2*)&C[(size_t)ra * Nout + j] = make_float2(v00, v01);
            *(float2*)&C[(size_t)rb * Nout + j] = make_float2(v10, v11);
        } else {
            uint32_t h0, l0, h1, l1;
            split_pack(v00, v01, h0, l0);
            split_pack(v10, v11, h1, l1);
            *(uint32_t*)&Ch[(size_t)ra * Nout + j] = h0;
            *(uint32_t*)&Cl[(size_t)ra * Nout + j] = l0;
            *(uint32_t*)&Ch[(size_t)rb * Nout + j] = h1;
            *(uint32_t*)&Cl[(size_t)rb * Nout + j] = l1;
        }
    }
}

__global__ void __launch_bounds__(256, 2)
gemm_one(const float* __restrict__ A, const float* __restrict__ W,
         const float* __restrict__ bias, float* __restrict__ C,
         int Nout, int K, float scale, int relu)
{
    __shared__ __align__(16) __nv_bfloat16 Ah[128 * GKP], Al[128 * GKP];
    __shared__ __align__(16) __nv_bfloat16 Wh[64 * GKP],  Wl[64 * GKP];
    gemm_body(A, W, bias, C, nullptr, nullptr, Nout, K, scale, relu, 0, Ah, Al, Wh, Wl);
}

__global__ void __launch_bounds__(256, 2)
gemm_qkv(const float* __restrict__ h,
         const float* __restrict__ Wq, const float* __restrict__ bq,
         __nv_bfloat16* __restrict__ Qh, __nv_bfloat16* __restrict__ Ql,
         const float* __restrict__ Wk, const float* __restrict__ bk,
         __nv_bfloat16* __restrict__ Kh, __nv_bfloat16* __restrict__ Kl,
         const float* __restrict__ Wv, const float* __restrict__ bv,
         __nv_bfloat16* __restrict__ Vh, __nv_bfloat16* __restrict__ Vl)
{
    __shared__ __align__(16) __nv_bfloat16 Ah[128 * GKP], Al[128 * GKP];
    __shared__ __align__(16) __nv_bfloat16 Wh[64 * GKP],  Wl[64 * GKP];
    const float* W; const float* b; __nv_bfloat16 *Ch, *Cl; float sc;
    if (blockIdx.z == 0)      { W = Wq; b = bq; Ch = Qh; Cl = Ql; sc = QK2SCALE; }
    else if (blockIdx.z == 1) { W = Wk; b = bk; Ch = Kh; Cl = Kl; sc = 1.f; }
    else                      { W = Wv; b = bv; Ch = Vh; Cl = Vl; sc = 1.f; }
    gemm_body(h, W, b, nullptr, Ch, Cl, HID, HID, sc, 0, 1, Ah, Al, Wh, Wl);
}

// ------------------- tensor-core flash attention -------------------
// Inputs pre-split (bf16 hi/lo planes). No online max; exp2 with log2e folded into Q.
// Pitch 56 elems (112B): conflict-free for STS.128 staging, ldmatrix, ldmatrix.trans.
#define KP 56

__global__ void __launch_bounds__(256, 2)
flash_attn_mma(const __nv_bfloat16* __restrict__ Qhg, const __nv_bfloat16* __restrict__ Qlg,
               const __nv_bfloat16* __restrict__ Khg, const __nv_bfloat16* __restrict__ Klg,
               const __nv_bfloat16* __restrict__ Vhg, const __nv_bfloat16* __restrict__ Vlg,
               const float* __restrict__ Amat, float* __restrict__ Of)
{
    __shared__ __align__(16) __nv_bfloat16 Khs[64 * KP], Kls[64 * KP];
    __shared__ __align__(16) __nv_bfloat16 Vhs[64 * KP], Vls[64 * KP];

    const int tid  = threadIdx.x;
    const int w    = tid >> 5;
    const int lane = tid & 31;
    const int qr   = lane >> 2;
    const int qc2  = (lane & 3) * 2;

    const int hh   = blockIdx.y;
    const int row0 = blockIdx.x * 128;
    const int r0   = w * 16;

    const size_t hbase = (size_t)hh * NTOK * HD;

    // Q fragments: direct uint32 loads from pre-split planes
    uint32_t aQh[2][4], aQl[2][4];
    {
        const size_t ra = hbase + (size_t)(row0 + r0 + qr) * HD;
        const size_t rb = ra + 8 * HD;
        #pragma unroll
        for (int ks = 0; ks < 2; ks++) {
            int cb = ks * 16 + qc2;
            aQh[ks][0] = *(const uint32_t*)&Qhg[ra + cb];
            aQh[ks][1] = *(const uint32_t*)&Qhg[rb + cb];
            aQh[ks][2] = *(const uint32_t*)&Qhg[ra + cb + 8];
            aQh[ks][3] = *(const uint32_t*)&Qhg[rb + cb + 8];
            aQl[ks][0] = *(const uint32_t*)&Qlg[ra + cb];
            aQl[ks][1] = *(const uint32_t*)&Qlg[rb + cb];
            aQl[ks][2] = *(const uint32_t*)&Qlg[ra + cb + 8];
            aQl[ks][3] = *(const uint32_t*)&Qlg[rb + cb + 8];
        }
    }

    float oacc[4][4] = {};
    float ls0 = 0.f, ls1 = 0.f;

    const int ga = (row0 + r0 + qr) * NTOK;
    const int gb = (row0 + r0 + qr + 8) * NTOK;

    const uint32_t khb = scvta(Khs), klb = scvta(Kls);
    const uint32_t vhb = scvta(Vhs), vlb = scvta(Vls);
    const uint32_t koff = (uint32_t)(((lane & 7) * KP + (lane >> 3) * 8) * 2);
    const uint32_t vtoff = (uint32_t)(lane * KP * 2);

    // staging: 4 arrays x 256 uint4; this thread copies (tid&63)+64t of array tid>>6
    const int sarr = tid >> 6;
    const int sidx0 = tid & 63;
    const uint4* gsrcA;
    __nv_bfloat16* sdstA;
    if (sarr == 0)      { gsrcA = (const uint4*)(Khg + hbase); sdstA = Khs; }
    else if (sarr == 1) { gsrcA = (const uint4*)(Klg + hbase); sdstA = Kls; }
    else if (sarr == 2) { gsrcA = (const uint4*)(Vhg + hbase); sdstA = Vhs; }
    else                { gsrcA = (const uint4*)(Vlg + hbase); sdstA = Vls; }

    for (int mt = 0; mt < NTOK / 64; mt++) {
        const int m0 = mt * 64;
        __syncthreads();
        // ---- stage K,V tiles: pure 16B copies (tile is contiguous in gmem) ----
        {
            const uint4* src = gsrcA + m0 * (HD / 8);
            #pragma unroll
            for (int t = 0; t < 4; t++) {
                int idx = sidx0 + t * 64;
                int r = idx >> 2, c8 = (idx & 3) * 8;
                *(uint4*)&sdstA[r * KP + c8] = src[idx];
            }
        }
        __syncthreads();

        // ---- prefetch adjacency rows ----
        float2 Ar[8], Br[8];
        #pragma unroll
        for (int nt = 0; nt < 8; nt++) {
            int gc = m0 + nt * 8 + qc2;
            Ar[nt] = *(const float2*)&Amat[(size_t)ga + gc];
            Br[nt] = *(const float2*)&Amat[(size_t)gb + gc];
        }

        // ---- S = Q·Kᵀ ----
        float sacc[8][4];
        #pragma unroll
        for (int nt = 0; nt < 8; nt++) {
            sacc[nt][0] = sacc[nt][1] = sacc[nt][2] = sacc[nt][3] = 0.f;
            uint32_t off = koff + (uint32_t)(nt * 8 * KP * 2);
            uint32_t bh[4], bl[4];
            ldsm_x4(bh, khb + off);
            ldsm_x4(bl, klb + off);
            mma_bf16(sacc[nt], aQh[0], bh);
            mma_bf16(sacc[nt], aQl[0], bh);
            mma_bf16(sacc[nt], aQh[0], bl);
            mma_bf16(sacc[nt], aQh[1], bh + 2);
            mma_bf16(sacc[nt], aQl[1], bh + 2);
            mma_bf16(sacc[nt], aQh[1], bl + 2);
        }

        // ---- p = exp2(s*A); lane-local row sums ----
        #pragma unroll
        for (int nt = 0; nt < 8; nt++) {
            sacc[nt][0] = ex2(sacc[nt][0] * Ar[nt].x);
            sacc[nt][1] = ex2(sacc[nt][1] * Ar[nt].y);
            sacc[nt][2] = ex2(sacc[nt][2] * Br[nt].x);
            sacc[nt][3] = ex2(sacc[nt][3] * Br[nt].y);
            ls0 += sacc[nt][0] + sacc[nt][1];
            ls1 += sacc[nt][2] + sacc[nt][3];
        }

        // ---- split P to bf16 hi/lo fragments ----
        uint32_t ph[4][4], pl_[4][4];
        #pragma unroll
        for (int kc = 0; kc < 4; kc++) {
            split_pack(sacc[2 * kc][0],     sacc[2 * kc][1],     ph[kc][0], pl_[kc][0]);
            split_pack(sacc[2 * kc][2],     sacc[2 * kc][3],     ph[kc][1], pl_[kc][1]);
            split_pack(sacc[2 * kc + 1][0], sacc[2 * kc + 1][1], ph[kc][2], pl_[kc][2]);
            split_pack(sacc[2 * kc + 1][2], sacc[2 * kc + 1][3], ph[kc][3], pl_[kc][3]);
        }

        // ---- O += P·V via ldmatrix.x4.trans ----
        #pragma unroll
        for (int nt = 0; nt < 4; nt++) {
            uint32_t off = vtoff + (uint32_t)(nt * 16);
            uint32_t bh[8], bl[8];
            ldsm_x4_t(bh,     vhb + off);
            ldsm_x4_t(bh + 4, vhb + off + 32 * KP * 2);
            ldsm_x4_t(bl,     vlb + off);
            ldsm_x4_t(bl + 4, vlb + off + 32 * KP * 2);
            #pragma unroll
            for (int kc = 0; kc < 4; kc++) {
                mma_bf16(oacc[nt], ph[kc],  bh + kc * 2);
                mma_bf16(oacc[nt], pl_[kc], bh + kc * 2);
                mma_bf16(oacc[nt], ph[kc],  bl + kc * 2);
            }
        }
    }

    // ---- final row-sum reduce + normalize ----
    ls0 += __shfl_xor_sync(0xffffffffu, ls0, 1);
    ls0 += __shfl_xor_sync(0xffffffffu, ls0, 2);
    ls1 += __shfl_xor_sync(0xffffffffu, ls1, 1);
    ls1 += __shfl_xor_sync(0xffffffffu, ls1, 2);
    float inv0 = 1.f / ls0, inv1 = 1.f / ls1;

    const size_t ra = hbase + (size_t)(row0 + r0 + qr) * HD;
    const size_t rb = ra + 8 * HD;
    #pragma unroll
    for (int nt = 0; nt < 4; nt++) {
        int c = nt * 8 + qc2;
        *(float2*)&Of[ra + c] = make_float2(oacc[nt][0] * inv0, oacc[nt][1] * inv0);
        *(float2*)&Of[rb + c] = make_float2(oacc[nt][2] * inv1, oacc[nt][3] * inv1);
    }
}

// ------------------- batchnorm helpers -------------------
// 64 threads/block, float4 per thread, 32 rows per block
__global__ void col_partial(const float* __restrict__ a, const float* __restrict__ b,
                            float* __restrict__ psum, float* __restrict__ psq)
{
    int c4 = threadIdx.x * 4;
    int blk = blockIdx.x;
    float4 s = {0.f, 0.f, 0.f, 0.f}, q = {0.f, 0.f, 0.f, 0.f};
    #pragma unroll 8
    for (int r = 0; r < 32; r++) {
        size_t i = (size_t)(blk * 32 + r) * HID + c4;
        float4 av = *(const float4*)&a[i];
        float4 bv = *(const float4*)&b[i];
        float vx = av.x + bv.x, vy = av.y + bv.y, vz = av.z + bv.z, vw = av.w + bv.w;
        s.x += vx; s.y += vy; s.z += vz; s.w += vw;
        q.x += vx * vx; q.y += vy * vy; q.z += vz * vz; q.w += vw * vw;
    }
    *(float4*)&psum[blk * HID + c4] = s;
    *(float4*)&psq[blk * HID + c4]  = q;
}

__global__ void col_finalize(const float* __restrict__ psum, const float* __restrict__ psq,
                             const float* __restrict__ g, const float* __restrict__ be,
                             float* __restrict__ scaleC, float* __restrict__ shiftC)
{
    int j = threadIdx.x;
    float s = 0.f, q = 0.f;
    #pragma unroll
    for (int b = 0; b < 128; b++) { s += psum[b * HID + j]; q += psq[b * HID + j]; }
    float m = s * (1.f / NTOK);
    float var = q * (1.f / NTOK) - m * m;
    var = fmaxf(var, 0.f);
    float sc = rsqrtf(var + EPSBN) * g[j];
    scaleC[j] = sc;
    shiftC[j] = be[j] - m * sc;
}

__global__ void bn_apply(const float* __restrict__ a, const float* __restrict__ b,
                         const float* __restrict__ scaleC, const float* __restrict__ shiftC,
                         float* __restrict__ out)
{
    int idx = (blockIdx.x * blockDim.x + threadIdx.x) * 4;
    int j = idx & (HID - 1);
    float4 av = *(const float4*)&a[idx];
    float4 bv = *(const float4*)&b[idx];
    float4 sc = *(const float4*)&scaleC[j];
    float4 sh = *(const float4*)&shiftC[j];
    float4 ov;
    ov.x = (av.x + bv.x) * sc.x + sh.x;
    ov.y = (av.y + bv.y) * sc.y + sh.y;
    ov.z = (av.z + bv.z) * sc.z + sh.z;
    ov.w = (av.w + bv.w) * sc.w + sh.w;
    *(float4*)&out[idx] = ov;
}

// ------------------- launch -------------------
extern "C" void kernel_launch(void* const* d_in, const int* in_sizes, int n_in,
                              void* d_out, int out_size)
{
    const float* A   = (const float*)d_in[0];
    const float* h   = (const float*)d_in[1];
    const float* Wq  = (const float*)d_in[2];
    const float* bq  = (const float*)d_in[3];
    const float* Wk  = (const float*)d_in[4];
    const float* bk  = (const float*)d_in[5];
    const float* Wv  = (const float*)d_in[6];
    const float* bv  = (const float*)d_in[7];
    const float* Wo  = (const float*)d_in[8];
    const float* bo  = (const float*)d_in[9];
    const float* W1  = (const float*)d_in[10];
    const float* c1  = (const float*)d_in[11];
    const float* W2  = (const float*)d_in[12];
    const float* c2  = (const float*)d_in[13];
    const float* g1  = (const float*)d_in[14];
    const float* be1 = (const float*)d_in[15];
    const float* g2  = (const float*)d_in[16];
    const float* be2 = (const float*)d_in[17];
    float* out = (float*)d_out;

    __nv_bfloat16 *Qh, *Ql, *Kh, *Kl, *Vh, *Vl;
    float *AO, *X, *X1, *Mid, *F, *psum, *psq, *scaleC, *shiftC;
    cudaGetSymbolAddress((void**)&Qh, g_Qh);
    cudaGetSymbolAddress((void**)&Ql, g_Ql);
    cudaGetSymbolAddress((void**)&Kh, g_Kh);
    cudaGetSymbolAddress((void**)&Kl, g_Kl);
    cudaGetSymbolAddress((void**)&Vh, g_Vh);
    cudaGetSymbolAddress((void**)&Vl, g_Vl);
    cudaGetSymbolAddress((void**)&AO,  g_AO);
    cudaGetSymbolAddress((void**)&X,   g_X);
    cudaGetSymbolAddress((void**)&X1,  g_X1);
    cudaGetSymbolAddress((void**)&Mid, g_Mid);
    cudaGetSymbolAddress((void**)&F,   g_F);
    cudaGetSymbolAddress((void**)&psum,   g_psum);
    cudaGetSymbolAddress((void**)&psq,    g_psq);
    cudaGetSymbolAddress((void**)&scaleC, g_scaleC);
    cudaGetSymbolAddress((void**)&shiftC, g_shiftC);

    dim3 gqkv(HID / 64, NTOK / 128, 3);
    dim3 gproj(HID / 64, NTOK / 128);
    dim3 gffn1(2 * HID / 64, NTOK / 128);
    dim3 gattn(NTOK / 128, NHEADS);

    // fused QKV projections, outputs pre-split bf16 hi/lo (Q carries qscale*log2e)
    gemm_qkv<<<gqkv, 256>>>(h, Wq, bq, Qh, Ql, Wk, bk, Kh, Kl, Wv, bv, Vh, Vl);

    // flash attention
    flash_attn_mma<<<gattn, 256>>>(Qh, Ql, Kh, Kl, Vh, Vl, A, AO);

    // output projection
    gemm_one<<<gproj, 256>>>(AO, Wo, bo, X, HID, HID, 1.f, 0);

    // BN1 over (X + h)
    col_partial<<<128, 64>>>(X, h, psum, psq);
    col_finalize<<<1, HID>>>(psum, psq, g1, be1, scaleC, shiftC);
    bn_apply<<<NTOK * HID / 1024, 256>>>(X, h, scaleC, shiftC, X1);

    // FFN
    gemm_one<<<gffn1, 256>>>(X1, W1, c1, Mid, 2 * HID, HID, 1.f, 1);
    gemm_one<<<gproj, 256>>>(Mid, W2, c2, F, HID, 2 * HID, 1.f, 0);

    // BN2 over (X1 + F) -> out
    col_partial<<<128, 64>>>(X1, F, psum, psq);
    col_finalize<<<1, HID>>>(psum, psq, g2, be2, scaleC, shiftC);
    bn_apply<<<NTOK * HID / 1024, 256>>>(X1, F, scaleC, shiftC, out);
}

// round 10
// speedup vs baseline: 1.0875x; 1.0875x over previous
#include <cuda_runtime.h>
#include <cuda_bf16.h>
#include <cstdint>

#define NTOK 4096
#define HID 256
#define NHEADS 8
#define HD 32
#define EPSBN 1e-5f
#define QSCALE 0.17677669529663687f       // 1/sqrt(32)
#define LOG2E  1.4426950408889634f
#define QK2SCALE (QSCALE * LOG2E)         // folded so softmax uses exp2

// ------------------- scratch (device globals; no allocation) -------------------
__device__ __nv_bfloat16 g_Qh[NTOK * HID];
__device__ __nv_bfloat16 g_Ql[NTOK * HID];
__device__ __nv_bfloat16 g_Kh[NTOK * HID];
__device__ __nv_bfloat16 g_Kl[NTOK * HID];
__device__ __nv_bfloat16 g_Vh[NTOK * HID];
__device__ __nv_bfloat16 g_Vl[NTOK * HID];
__device__ float g_AO[NTOK * HID];
__device__ float g_X[NTOK * HID];
__device__ float g_X1[NTOK * HID];
__device__ float g_Mid[NTOK * 2 * HID];
__device__ float g_F[NTOK * HID];
__device__ float g_psum[128 * HID];
__device__ float g_psq[128 * HID];
__device__ float g_scaleC[HID];
__device__ float g_shiftC[HID];

// ------------------- helpers -------------------
__device__ __forceinline__ void mma_bf16(float* c, const uint32_t* a, const uint32_t* b)
{
    asm volatile(
        "mma.sync.aligned.m16n8k16.row.col.f32.bf16.bf16.f32 "
        "{%0,%1,%2,%3}, {%4,%5,%6,%7}, {%8,%9}, {%0,%1,%2,%3};"
        : "+f"(c[0]), "+f"(c[1]), "+f"(c[2]), "+f"(c[3])
        : "r"(a[0]), "r"(a[1]), "r"(a[2]), "r"(a[3]), "r"(b[0]), "r"(b[1]));
}

// pack {lo=x, hi=y} to bf16x2 hi; residual pair to lo.
__device__ __forceinline__ void split_pack(float x, float y, uint32_t& hi, uint32_t& lo)
{
    uint32_t h;
    asm("cvt.rn.bf16x2.f32 %0, %1, %2;" : "=r"(h) : "f"(y), "f"(x));
    float xr = __uint_as_float(h << 16);
    float yr = __uint_as_float(h & 0xffff0000u);
    float xl = x - xr, yl = y - yr;
    uint32_t l;
    asm("cvt.rn.bf16x2.f32 %0, %1, %2;" : "=r"(l) : "f"(yl), "f"(xl));
    hi = h; lo = l;
}

__device__ __forceinline__ float ex2(float x)
{
    float r;
    asm("ex2.approx.ftz.f32 %0, %1;" : "=f"(r) : "f"(x));
    return r;
}

__device__ __forceinline__ uint32_t scvta(const void* p)
{
    return (uint32_t)__cvta_generic_to_shared(p);
}

__device__ __forceinline__ void ldsm_x4(uint32_t* d, uint32_t addr)
{
    asm volatile("ldmatrix.sync.aligned.m8n8.x4.shared.b16 {%0,%1,%2,%3}, [%4];"
                 : "=r"(d[0]), "=r"(d[1]), "=r"(d[2]), "=r"(d[3]) : "r"(addr));
}

__device__ __forceinline__ void ldsm_x4_t(uint32_t* d, uint32_t addr)
{
    asm volatile("ldmatrix.sync.aligned.m8n8.x4.trans.shared.b16 {%0,%1,%2,%3}, [%4];"
                 : "=r"(d[0]), "=r"(d[1]), "=r"(d[2]), "=r"(d[3]) : "r"(addr));
}

__device__ __forceinline__ void cp_async16(uint32_t dst, const void* src)
{
    asm volatile("cp.async.cg.shared.global [%0], [%1], 16;" :: "r"(dst), "l"(src));
}

__device__ __forceinline__ void cp_commit() { asm volatile("cp.async.commit_group;"); }
__device__ __forceinline__ void cp_wait0()  { asm volatile("cp.async.wait_group 0;"); }

// ------------------- tensor-core GEMM -------------------
// mode 0: C = (A@W^T + bias)*scale [opt relu] as f32
// mode 1: same value, stored as bf16 hi/lo split planes Ch, Cl
#define GKP 40

__device__ __forceinline__ void gemm_body(
    const float* __restrict__ A, const float* __restrict__ W,
    const float* __restrict__ bias, float* __restrict__ C,
    __nv_bfloat16* __restrict__ Ch, __nv_bfloat16* __restrict__ Cl,
    int Nout, int K, float scale, int relu, int mode,
    __nv_bfloat16* Ah, __nv_bfloat16* Al, __nv_bfloat16* Wh, __nv_bfloat16* Wl)
{
    const int tid = threadIdx.x, w = tid >> 5, lane = tid & 31;
    const int qr = lane >> 2, qc2 = (lane & 3) * 2;
    const int i0 = blockIdx.y * 128, j0 = blockIdx.x * 64;
    const int r0 = w * 16;

    float acc[8][4] = {};

    const int arow = r0 + ((lane >> 3) & 1) * 8 + (lane & 7);
    const int acol = (lane >> 4) * 8;
    const int brow = (lane & 7);
    const int bcol = (lane >> 3) * 8;

    const uint32_t ahb = scvta(Ah), alb = scvta(Al);
    const uint32_t whb = scvta(Wh), wlb = scvta(Wl);

    for (int kk = 0; kk < K; kk += 32) {
        #pragma unroll
        for (int t = 0; t < 4; t++) {
            int j = tid + t * 256;
            int r = j >> 3, c4 = (j & 7) * 4;
            float4 av = *(const float4*)&A[(size_t)(i0 + r) * K + kk + c4];
            uint32_t h01, l01, h23, l23;
            split_pack(av.x, av.y, h01, l01);
            split_pack(av.z, av.w, h23, l23);
            *(uint32_t*)&Ah[r * GKP + c4]     = h01;
            *(uint32_t*)&Ah[r * GKP + c4 + 2] = h23;
            *(uint32_t*)&Al[r * GKP + c4]     = l01;
            *(uint32_t*)&Al[r * GKP + c4 + 2] = l23;
        }
        #pragma unroll
        for (int t = 0; t < 2; t++) {
            int j = tid + t * 256;
            int r = j >> 3, c4 = (j & 7) * 4;
            float4 wv = *(const float4*)&W[(size_t)(j0 + r) * K + kk + c4];
            uint32_t h01, l01, h23, l23;
            split_pack(wv.x, wv.y, h01, l01);
            split_pack(wv.z, wv.w, h23, l23);
            *(uint32_t*)&Wh[r * GKP + c4]     = h01;
            *(uint32_t*)&Wh[r * GKP + c4 + 2] = h23;
            *(uint32_t*)&Wl[r * GKP + c4]     = l01;
            *(uint32_t*)&Wl[r * GKP + c4 + 2] = l23;
        }
        __syncthreads();

        uint32_t ah[2][4], al[2][4];
        #pragma unroll
        for (int ks = 0; ks < 2; ks++) {
            uint32_t off = (uint32_t)((arow * GKP + ks * 16 + acol) * 2);
            ldsm_x4(ah[ks], ahb + off);
            ldsm_x4(al[ks], alb + off);
        }
        #pragma unroll
        for (int nt = 0; nt < 8; nt++) {
            uint32_t bh[4], bl[4];
            uint32_t off = (uint32_t)(((nt * 8 + brow) * GKP + bcol) * 2);
            ldsm_x4(bh, whb + off);
            ldsm_x4(bl, wlb + off);
            mma_bf16(acc[nt], ah[0], bh);
            mma_bf16(acc[nt], al[0], bh);
            mma_bf16(acc[nt], ah[0], bl);
            mma_bf16(acc[nt], ah[1], bh + 2);
            mma_bf16(acc[nt], al[1], bh + 2);
            mma_bf16(acc[nt], ah[1], bl + 2);
        }
        __syncthreads();
    }

    const int ra = i0 + r0 + qr, rb = ra + 8;
    #pragma unroll
    for (int nt = 0; nt < 8; nt++) {
        int j = j0 + nt * 8 + qc2;
        float b0 = bias[j], b1 = bias[j + 1];
        float v00 = (acc[nt][0] + b0) * scale;
        float v01 = (acc[nt][1] + b1) * scale;
        float v10 = (acc[nt][2] + b0) * scale;
        float v11 = (acc[nt][3] + b1) * scale;
        if (relu) {
            v00 = fmaxf(v00, 0.f); v01 = fmaxf(v01, 0.f);
            v10 = fmaxf(v10, 0.f); v11 = fmaxf(v11, 0.f);
        }
        if (mode == 0) {
            *(float2*)&C[(size_t)ra * Nout + j] = make_float2(v00, v01);
            *(float2*)&C[(size_t)rb * Nout + j] = make_float2(v10, v11);
        } else {
            uint32_t h0, l0, h1, l1;
            split_pack(v00, v01, h0, l0);
            split_pack(v10, v11, h1, l1);
            *(uint32_t*)&Ch[(size_t)ra * Nout + j] = h0;
            *(uint32_t*)&Cl[(size_t)ra * Nout + j] = l0;
            *(uint32_t*)&Ch[(size_t)rb * Nout + j] = h1;
            *(uint32_t*)&Cl[(size_t)rb * Nout + j] = l1;
        }
    }
}

__global__ void __launch_bounds__(256, 2)
gemm_one(const float* __restrict__ A, const float* __restrict__ W,
         const float* __restrict__ bias, float* __restrict__ C,
         int Nout, int K, float scale, int relu)
{
    __shared__ __align__(16) __nv_bfloat16 Ah[128 * GKP], Al[128 * GKP];
    __shared__ __align__(16) __nv_bfloat16 Wh[64 * GKP],  Wl[64 * GKP];
    gemm_body(A, W, bias, C, nullptr, nullptr, Nout, K, scale, relu, 0, Ah, Al, Wh, Wl);
}

__global__ void __launch_bounds__(256, 2)
gemm_qkv(const float* __restrict__ h,
         const float* __restrict__ Wq, const float* __restrict__ bq,
         __nv_bfloat16* __restrict__ Qh, __nv_bfloat16* __restrict__ Ql,
         const float* __restrict__ Wk, const float* __restrict__ bk,
         __nv_bfloat16* __restrict__ Kh, __nv_bfloat16* __restrict__ Kl,
         const float* __restrict__ Wv, const float* __restrict__ bv,
         __nv_bfloat16* __restrict__ Vh, __nv_bfloat16* __restrict__ Vl)
{
    __shared__ __align__(16) __nv_bfloat16 Ah[128 * GKP], Al[128 * GKP];
    __shared__ __align__(16) __nv_bfloat16 Wh[64 * GKP],  Wl[64 * GKP];
    const float* W; const float* b; __nv_bfloat16 *Ch, *Cl; float sc;
    if (blockIdx.z == 0)      { W = Wq; b = bq; Ch = Qh; Cl = Ql; sc = QK2SCALE; }
    else if (blockIdx.z == 1) { W = Wk; b = bk; Ch = Kh; Cl = Kl; sc = 1.f; }
    else                      { W = Wv; b = bv; Ch = Vh; Cl = Vl; sc = 1.f; }
    gemm_body(h, W, b, nullptr, Ch, Cl, HID, HID, sc, 0, 1, Ah, Al, Wh, Wl);
}

// ------------------- tensor-core flash attention -------------------
// Pre-split bf16 hi/lo inputs. No online max; exp2 with log2e folded into Q.
// Double-buffered cp.async staging in DYNAMIC shared memory (57,344 B > 48 KB
// static limit). Layout: Kh[2], Kl[2], Vh[2], Vl[2], each [64*KP] bf16.
#define KP 56
#define BUFB (64 * KP * 2)             // bytes per buffer per array
#define FLASH_SMEM (8 * BUFB)          // 57344 bytes

__global__ void __launch_bounds__(256, 2)
flash_attn_mma(const __nv_bfloat16* __restrict__ Qhg, const __nv_bfloat16* __restrict__ Qlg,
               const __nv_bfloat16* __restrict__ Khg, const __nv_bfloat16* __restrict__ Klg,
               const __nv_bfloat16* __restrict__ Vhg, const __nv_bfloat16* __restrict__ Vlg,
               const float* __restrict__ Amat, float* __restrict__ Of)
{
    extern __shared__ __align__(16) char smemraw[];
    __nv_bfloat16* Khs = (__nv_bfloat16*)(smemraw);
    __nv_bfloat16* Kls = (__nv_bfloat16*)(smemraw + 2 * BUFB);
    __nv_bfloat16* Vhs = (__nv_bfloat16*)(smemraw + 4 * BUFB);
    __nv_bfloat16* Vls = (__nv_bfloat16*)(smemraw + 6 * BUFB);

    const int tid  = threadIdx.x;
    const int w    = tid >> 5;
    const int lane = tid & 31;
    const int qr   = lane >> 2;
    const int qc2  = (lane & 3) * 2;

    const int hh   = blockIdx.y;
    const int row0 = blockIdx.x * 128;
    const int r0   = w * 16;

    const size_t hbase = (size_t)hh * NTOK * HD;

    // Q fragments: direct uint32 loads from pre-split planes
    uint32_t aQh[2][4], aQl[2][4];
    {
        const size_t ra = hbase + (size_t)(row0 + r0 + qr) * HD;
        const size_t rb = ra + 8 * HD;
        #pragma unroll
        for (int ks = 0; ks < 2; ks++) {
            int cb = ks * 16 + qc2;
            aQh[ks][0] = *(const uint32_t*)&Qhg[ra + cb];
            aQh[ks][1] = *(const uint32_t*)&Qhg[rb + cb];
            aQh[ks][2] = *(const uint32_t*)&Qhg[ra + cb + 8];
            aQh[ks][3] = *(const uint32_t*)&Qhg[rb + cb + 8];
            aQl[ks][0] = *(const uint32_t*)&Qlg[ra + cb];
            aQl[ks][1] = *(const uint32_t*)&Qlg[rb + cb];
            aQl[ks][2] = *(const uint32_t*)&Qlg[ra + cb + 8];
            aQl[ks][3] = *(const uint32_t*)&Qlg[rb + cb + 8];
        }
    }

    float oacc[4][4] = {};
    float ls0 = 0.f, ls1 = 0.f;

    const int ga = (row0 + r0 + qr) * NTOK;
    const int gb = (row0 + r0 + qr + 8) * NTOK;

    const uint32_t khb = scvta(Khs), klb = scvta(Kls);
    const uint32_t vhb = scvta(Vhs), vlb = scvta(Vls);
    const uint32_t koff = (uint32_t)(((lane & 7) * KP + (lane >> 3) * 8) * 2);
    const uint32_t vtoff = (uint32_t)(lane * KP * 2);

    // staging: tid>>6 selects array; tid&63 copies 4 x 16B via cp.async
    const int sarr = tid >> 6;
    const int sidx0 = tid & 63;
    const char* gsrc;
    uint32_t sdstb;
    if (sarr == 0)      { gsrc = (const char*)(Khg + hbase); sdstb = khb; }
    else if (sarr == 1) { gsrc = (const char*)(Klg + hbase); sdstb = klb; }
    else if (sarr == 2) { gsrc = (const char*)(Vhg + hbase); sdstb = vhb; }
    else                { gsrc = (const char*)(Vlg + hbase); sdstb = vlb; }

    // per-thread smem offsets (4 chunks)
    uint32_t soff[4];
    #pragma unroll
    for (int t = 0; t < 4; t++) {
        int idx = sidx0 + t * 64;
        int r = idx >> 2, c8 = (idx & 3) * 8;
        soff[t] = (uint32_t)((r * KP + c8) * 2);
    }

    // preload tile 0 into buffer 0
    #pragma unroll
    for (int t = 0; t < 4; t++)
        cp_async16(sdstb + soff[t], gsrc + (size_t)(sidx0 + t * 64) * 16);
    cp_commit();
    cp_wait0();
    __syncthreads();

    int p = 0;
    for (int mt = 0; mt < NTOK / 64; mt++) {
        const int m0 = mt * 64;
        const uint32_t pofs = (uint32_t)p * BUFB;

        // ---- prefetch next tile into the other buffer (overlaps compute) ----
        if (mt < NTOK / 64 - 1) {
            const char* src = gsrc + (size_t)(mt + 1) * 64 * HD * 2;
            uint32_t dstb = sdstb + (pofs ^ BUFB);
            #pragma unroll
            for (int t = 0; t < 4; t++)
                cp_async16(dstb + soff[t], src + (size_t)(sidx0 + t * 64) * 16);
        }
        cp_commit();

        // ---- prefetch adjacency rows ----
        float2 Ar[8], Br[8];
        #pragma unroll
        for (int nt = 0; nt < 8; nt++) {
            int gc = m0 + nt * 8 + qc2;
            Ar[nt] = *(const float2*)&Amat[(size_t)ga + gc];
            Br[nt] = *(const float2*)&Amat[(size_t)gb + gc];
        }

        // ---- S = Q·Kᵀ ----
        float sacc[8][4];
        #pragma unroll
        for (int nt = 0; nt < 8; nt++) {
            sacc[nt][0] = sacc[nt][1] = sacc[nt][2] = sacc[nt][3] = 0.f;
            uint32_t off = koff + pofs + (uint32_t)(nt * 8 * KP * 2);
            uint32_t bh[4], bl[4];
            ldsm_x4(bh, khb + off);
            ldsm_x4(bl, klb + off);
            mma_bf16(sacc[nt], aQh[0], bh);
            mma_bf16(sacc[nt], aQl[0], bh);
            mma_bf16(sacc[nt], aQh[0], bl);
            mma_bf16(sacc[nt], aQh[1], bh + 2);
            mma_bf16(sacc[nt], aQl[1], bh + 2);
            mma_bf16(sacc[nt], aQh[1], bl + 2);
        }

        // ---- p = exp2(s*A); lane-local row sums ----
        #pragma unroll
        for (int nt = 0; nt < 8; nt++) {
            sacc[nt][0] = ex2(sacc[nt][0] * Ar[nt].x);
            sacc[nt][1] = ex2(sacc[nt][1] * Ar[nt].y);
            sacc[nt][2] = ex2(sacc[nt][2] * Br[nt].x);
            sacc[nt][3] = ex2(sacc[nt][3] * Br[nt].y);
            ls0 += sacc[nt][0] + sacc[nt][1];
            ls1 += sacc[nt][2] + sacc[nt][3];
        }

        // ---- split P to bf16 hi/lo fragments ----
        uint32_t ph[4][4], pl_[4][4];
        #pragma unroll
        for (int kc = 0; kc < 4; kc++) {
            split_pack(sacc[2 * kc][0],     sacc[2 * kc][1],     ph[kc][0], pl_[kc][0]);
            split_pack(sacc[2 * kc][2],     sacc[2 * kc][3],     ph[kc][1], pl_[kc][1]);
            split_pack(sacc[2 * kc + 1][0], sacc[2 * kc + 1][1], ph[kc][2], pl_[kc][2]);
            split_pack(sacc[2 * kc + 1][2], sacc[2 * kc + 1][3], ph[kc][3], pl_[kc][3]);
        }

        // ---- O += P·V via ldmatrix.x4.trans ----
        #pragma unroll
        for (int nt = 0; nt < 4; nt++) {
            uint32_t off = vtoff + pofs + (uint32_t)(nt * 16);
            uint32_t bh[8], bl[8];
            ldsm_x4_t(bh,     vhb + off);
            ldsm_x4_t(bh + 4, vhb + off + 32 * KP * 2);
            ldsm_x4_t(bl,     vlb + off);
            ldsm_x4_t(bl + 4, vlb + off + 32 * KP * 2);
            #pragma unroll
            for (int kc = 0; kc < 4; kc++) {
                mma_bf16(oacc[nt], ph[kc],  bh + kc * 2);
                mma_bf16(oacc[nt], pl_[kc], bh + kc * 2);
                mma_bf16(oacc[nt], ph[kc],  bl + kc * 2);
            }
        }

        // ---- close pipeline stage ----
        cp_wait0();
        __syncthreads();
        p ^= 1;
    }

    // ---- final row-sum reduce + normalize ----
    ls0 += __shfl_xor_sync(0xffffffffu, ls0, 1);
    ls0 += __shfl_xor_sync(0xffffffffu, ls0, 2);
    ls1 += __shfl_xor_sync(0xffffffffu, ls1, 1);
    ls1 += __shfl_xor_sync(0xffffffffu, ls1, 2);
    float inv0 = 1.f / ls0, inv1 = 1.f / ls1;

    const size_t ra = hbase + (size_t)(row0 + r0 + qr) * HD;
    const size_t rb = ra + 8 * HD;
    #pragma unroll
    for (int nt = 0; nt < 4; nt++) {
        int c = nt * 8 + qc2;
        *(float2*)&Of[ra + c] = make_float2(oacc[nt][0] * inv0, oacc[nt][1] * inv0);
        *(float2*)&Of[rb + c] = make_float2(oacc[nt][2] * inv1, oacc[nt][3] * inv1);
    }
}

// ------------------- batchnorm helpers -------------------
// 256 threads/block, float4 lanes, 4-way row split + smem reduce. 32 rows/block.
__global__ void col_partial(const float* __restrict__ a, const float* __restrict__ b,
                            float* __restrict__ psum, float* __restrict__ psq)
{
    __shared__ float4 ssum[4][64], ssq[4][64];
    int q = threadIdx.x & 63;
    int rg = threadIdx.x >> 6;
    int c4 = q * 4;
    int blk = blockIdx.x;
    float4 s = {0.f, 0.f, 0.f, 0.f}, sq = {0.f, 0.f, 0.f, 0.f};
    #pragma unroll
    for (int k = 0; k < 8; k++) {
        int r = rg * 8 + k;
        size_t i = (size_t)(blk * 32 + r) * HID + c4;
        float4 av = *(const float4*)&a[i];
        float4 bv = *(const float4*)&b[i];
        float vx = av.x + bv.x, vy = av.y + bv.y, vz = av.z + bv.z, vw = av.w + bv.w;
        s.x += vx; s.y += vy; s.z += vz; s.w += vw;
        sq.x += vx * vx; sq.y += vy * vy; sq.z += vz * vz; sq.w += vw * vw;
    }
    ssum[rg][q] = s; ssq[rg][q] = sq;
    __syncthreads();
    if (rg == 0) {
        #pragma unroll
        for (int k = 1; k < 4; k++) {
            float4 t1 = ssum[k][q], t2 = ssq[k][q];
            s.x += t1.x; s.y += t1.y; s.z += t1.z; s.w += t1.w;
            sq.x += t2.x; sq.y += t2.y; sq.z += t2.z; sq.w += t2.w;
        }
        *(float4*)&psum[blk * HID + c4] = s;
        *(float4*)&psq[blk * HID + c4]  = sq;
    }
}

__global__ void col_finalize(const float* __restrict__ psum, const float* __restrict__ psq,
                             const float* __restrict__ g, const float* __restrict__ be,
                             float* __restrict__ scaleC, float* __restrict__ shiftC)
{
    int j = threadIdx.x;
    float s = 0.f, q = 0.f;
    #pragma unroll
    for (int b = 0; b < 128; b++) { s += psum[b * HID + j]; q += psq[b * HID + j]; }
    float m = s * (1.f / NTOK);
    float var = q * (1.f / NTOK) - m * m;
    var = fmaxf(var, 0.f);
    float sc = rsqrtf(var + EPSBN) * g[j];
    scaleC[j] = sc;
    shiftC[j] = be[j] - m * sc;
}

__global__ void bn_apply(const float* __restrict__ a, const float* __restrict__ b,
                         const float* __restrict__ scaleC, const float* __restrict__ shiftC,
                         float* __restrict__ out)
{
    int idx = (blockIdx.x * blockDim.x + threadIdx.x) * 4;
    int j = idx & (HID - 1);
    float4 av = *(const float4*)&a[idx];
    float4 bv = *(const float4*)&b[idx];
    float4 sc = *(const float4*)&scaleC[j];
    float4 sh = *(const float4*)&shiftC[j];
    float4 ov;
    ov.x = (av.x + bv.x) * sc.x + sh.x;
    ov.y = (av.y + bv.y) * sc.y + sh.y;
    ov.z = (av.z + bv.z) * sc.z + sh.z;
    ov.w = (av.w + bv.w) * sc.w + sh.w;
    *(float4*)&out[idx] = ov;
}

// ------------------- launch -------------------
extern "C" void kernel_launch(void* const* d_in, const int* in_sizes, int n_in,
                              void* d_out, int out_size)
{
    const float* A   = (const float*)d_in[0];
    const float* h   = (const float*)d_in[1];
    const float* Wq  = (const float*)d_in[2];
    const float* bq  = (const float*)d_in[3];
    const float* Wk  = (const float*)d_in[4];
    const float* bk  = (const float*)d_in[5];
    const float* Wv  = (const float*)d_in[6];
    const float* bv  = (const float*)d_in[7];
    const float* Wo  = (const float*)d_in[8];
    const float* bo  = (const float*)d_in[9];
    const float* W1  = (const float*)d_in[10];
    const float* c1  = (const float*)d_in[11];
    const float* W2  = (const float*)d_in[12];
    const float* c2  = (const float*)d_in[13];
    const float* g1  = (const float*)d_in[14];
    const float* be1 = (const float*)d_in[15];
    const float* g2  = (const float*)d_in[16];
    const float* be2 = (const float*)d_in[17];
    float* out = (float*)d_out;

    __nv_bfloat16 *Qh, *Ql, *Kh, *Kl, *Vh, *Vl;
    float *AO, *X, *X1, *Mid, *F, *psum, *psq, *scaleC, *shiftC;
    cudaGetSymbolAddress((void**)&Qh, g_Qh);
    cudaGetSymbolAddress((void**)&Ql, g_Ql);
    cudaGetSymbolAddress((void**)&Kh, g_Kh);
    cudaGetSymbolAddress((void**)&Kl, g_Kl);
    cudaGetSymbolAddress((void**)&Vh, g_Vh);
    cudaGetSymbolAddress((void**)&Vl, g_Vl);
    cudaGetSymbolAddress((void**)&AO,  g_AO);
    cudaGetSymbolAddress((void**)&X,   g_X);
    cudaGetSymbolAddress((void**)&X1,  g_X1);
    cudaGetSymbolAddress((void**)&Mid, g_Mid);
    cudaGetSymbolAddress((void**)&F,   g_F);
    cudaGetSymbolAddress((void**)&psum,   g_psum);
    cudaGetSymbolAddress((void**)&psq,    g_psq);
    cudaGetSymbolAddress((void**)&scaleC, g_scaleC);
    cudaGetSymbolAddress((void**)&shiftC, g_shiftC);

    // allow >48KB dynamic smem for flash (idempotent; not an allocation)
    cudaFuncSetAttribute(flash_attn_mma,
                         cudaFuncAttributeMaxDynamicSharedMemorySize, FLASH_SMEM);

    dim3 gqkv(HID / 64, NTOK / 128, 3);
    dim3 gproj(HID / 64, NTOK / 128);
    dim3 gffn1(2 * HID / 64, NTOK / 128);
    dim3 gattn(NTOK / 128, NHEADS);

    // fused QKV projections, outputs pre-split bf16 hi/lo (Q carries qscale*log2e)
    gemm_qkv<<<gqkv, 256>>>(h, Wq, bq, Qh, Ql, Wk, bk, Kh, Kl, Wv, bv, Vh, Vl);

    // flash attention (double-buffered cp.async pipeline, dynamic smem)
    flash_attn_mma<<<gattn, 256, FLASH_SMEM>>>(Qh, Ql, Kh, Kl, Vh, Vl, A, AO);

    // output projection
    gemm_one<<<gproj, 256>>>(AO, Wo, bo, X, HID, HID, 1.f, 0);

    // BN1 over (X + h)
    col_partial<<<128, 256>>>(X, h, psum, psq);
    col_finalize<<<1, HID>>>(psum, psq, g1, be1, scaleC, shiftC);
    bn_apply<<<NTOK * HID / 1024, 256>>>(X, h, scaleC, shiftC, X1);

    // FFN
    gemm_one<<<gffn1, 256>>>(X1, W1, c1, Mid, 2 * HID, HID, 1.f, 1);
    gemm_one<<<gproj, 256>>>(Mid, W2, c2, F, HID, 2 * HID, 1.f, 0);

    // BN2 over (X1 + F) -> out
    col_partial<<<128, 256>>>(X1, F, psum, psq);
    col_finalize<<<1, HID>>>(psum, psq, g2, be2, scaleC, shiftC);
    bn_apply<<<NTOK * HID / 1024, 256>>>(X1, F, scaleC, shiftC, out);
}

// round 11
// speedup vs baseline: 1.0917x; 1.0039x over previous
#include <cuda_runtime.h>
#include <cuda_bf16.h>
#include <cstdint>

#define NTOK 4096
#define HID 256
#define NHEADS 8
#define HD 32
#define EPSBN 1e-5f
#define QSCALE 0.17677669529663687f       // 1/sqrt(32)
#define LOG2E  1.4426950408889634f
#define QK2SCALE (QSCALE * LOG2E)         // folded so softmax uses exp2

// ------------------- scratch (device globals; no allocation) -------------------
// pre-split input/weight planes
__device__ __nv_bfloat16 g_hh[NTOK * HID],  g_hl[NTOK * HID];
__device__ __nv_bfloat16 g_Wqh[HID * HID],  g_Wql[HID * HID];
__device__ __nv_bfloat16 g_Wkh[HID * HID],  g_Wkl[HID * HID];
__device__ __nv_bfloat16 g_Wvh[HID * HID],  g_Wvl[HID * HID];
__device__ __nv_bfloat16 g_Woh[HID * HID],  g_Wol[HID * HID];
__device__ __nv_bfloat16 g_W1h[2 * HID * HID], g_W1l[2 * HID * HID];
__device__ __nv_bfloat16 g_W2h[2 * HID * HID], g_W2l[2 * HID * HID];
// activations
__device__ __nv_bfloat16 g_Qh[NTOK * HID], g_Ql[NTOK * HID];
__device__ __nv_bfloat16 g_Kh[NTOK * HID], g_Kl[NTOK * HID];
__device__ __nv_bfloat16 g_Vh[NTOK * HID], g_Vl[NTOK * HID];
__device__ __nv_bfloat16 g_AOh[NTOK * HID], g_AOl[NTOK * HID];
__device__ __nv_bfloat16 g_X1h[NTOK * HID], g_X1l[NTOK * HID];
__device__ __nv_bfloat16 g_Mh[NTOK * 2 * HID], g_Ml[NTOK * 2 * HID];
__device__ float g_X[NTOK * HID];
__device__ float g_X1[NTOK * HID];
__device__ float g_F[NTOK * HID];
__device__ float g_psum[128 * HID];
__device__ float g_psq[128 * HID];
__device__ float g_scaleC[HID];
__device__ float g_shiftC[HID];

// ------------------- helpers -------------------
__device__ __forceinline__ void mma_bf16(float* c, const uint32_t* a, const uint32_t* b)
{
    asm volatile(
        "mma.sync.aligned.m16n8k16.row.col.f32.bf16.bf16.f32 "
        "{%0,%1,%2,%3}, {%4,%5,%6,%7}, {%8,%9}, {%0,%1,%2,%3};"
        : "+f"(c[0]), "+f"(c[1]), "+f"(c[2]), "+f"(c[3])
        : "r"(a[0]), "r"(a[1]), "r"(a[2]), "r"(a[3]), "r"(b[0]), "r"(b[1]));
}

__device__ __forceinline__ void split_pack(float x, float y, uint32_t& hi, uint32_t& lo)
{
    uint32_t h;
    asm("cvt.rn.bf16x2.f32 %0, %1, %2;" : "=r"(h) : "f"(y), "f"(x));
    float xr = __uint_as_float(h << 16);
    float yr = __uint_as_float(h & 0xffff0000u);
    float xl = x - xr, yl = y - yr;
    uint32_t l;
    asm("cvt.rn.bf16x2.f32 %0, %1, %2;" : "=r"(l) : "f"(yl), "f"(xl));
    hi = h; lo = l;
}

__device__ __forceinline__ float ex2(float x)
{
    float r;
    asm("ex2.approx.ftz.f32 %0, %1;" : "=f"(r) : "f"(x));
    return r;
}

__device__ __forceinline__ uint32_t scvta(const void* p)
{
    return (uint32_t)__cvta_generic_to_shared(p);
}

__device__ __forceinline__ void ldsm_x4(uint32_t* d, uint32_t addr)
{
    asm volatile("ldmatrix.sync.aligned.m8n8.x4.shared.b16 {%0,%1,%2,%3}, [%4];"
                 : "=r"(d[0]), "=r"(d[1]), "=r"(d[2]), "=r"(d[3]) : "r"(addr));
}

__device__ __forceinline__ void ldsm_x4_t(uint32_t* d, uint32_t addr)
{
    asm volatile("ldmatrix.sync.aligned.m8n8.x4.trans.shared.b16 {%0,%1,%2,%3}, [%4];"
                 : "=r"(d[0]), "=r"(d[1]), "=r"(d[2]), "=r"(d[3]) : "r"(addr));
}

__device__ __forceinline__ void cp_async16(uint32_t dst, const void* src)
{
    asm volatile("cp.async.cg.shared.global [%0], [%1], 16;" :: "r"(dst), "l"(src));
}

__device__ __forceinline__ void cp_commit() { asm volatile("cp.async.commit_group;"); }
__device__ __forceinline__ void cp_wait0()  { asm volatile("cp.async.wait_group 0;"); }

// ------------------- split_all: f32 -> bf16 hi/lo planes (h + 6 weights) ----------
struct SplitJob { const float* src; __nv_bfloat16* hi; __nv_bfloat16* lo; int n4; };
struct SplitJobs { SplitJob j[7]; };

__global__ void split_all(SplitJobs jobs)
{
    SplitJob job = jobs.j[blockIdx.y];
    for (int i = blockIdx.x * blockDim.x + threadIdx.x; i < job.n4;
         i += gridDim.x * blockDim.x) {
        float4 v = *(const float4*)&job.src[(size_t)i * 4];
        uint32_t h01, l01, h23, l23;
        split_pack(v.x, v.y, h01, l01);
        split_pack(v.z, v.w, h23, l23);
        *(uint32_t*)&job.hi[(size_t)i * 4]     = h01;
        *(uint32_t*)&job.hi[(size_t)i * 4 + 2] = h23;
        *(uint32_t*)&job.lo[(size_t)i * 4]     = l01;
        *(uint32_t*)&job.lo[(size_t)i * 4 + 2] = l23;
    }
}

// ------------------- tensor-core GEMM on pre-split planes -------------------
// C = (A@W^T + bias)*scale [opt relu]; mode 0 -> f32 C, mode 1 -> planes Ch/Cl.
// Double-buffered cp.async staging of pre-split A and W tiles (pure copies).
#define GKP 40
#define GAB (128 * GKP * 2)      // A plane bytes per buffer
#define GWB (64 * GKP * 2)       // W plane bytes per buffer
#define GBUF (2 * GAB + 2 * GWB) // 30720 B
#define GEMM_SMEM (2 * GBUF)     // 61440 B

__device__ __forceinline__ void gemm_stage(
    const __nv_bfloat16* __restrict__ Ahp, const __nv_bfloat16* __restrict__ Alp,
    const __nv_bfloat16* __restrict__ Whp, const __nv_bfloat16* __restrict__ Wlp,
    int i0, int j0, int K, int kk, uint32_t bufb, int tid)
{
    #pragma unroll
    for (int t = 0; t < 4; t++) {
        int pg = tid + t * 256;
        const __nv_bfloat16* src = (t >= 2) ? Alp : Ahp;
        int idx = pg & 511, r = idx >> 2, c8 = (idx & 3) * 8;
        cp_async16(bufb + (uint32_t)((t >= 2) ? GAB : 0) + (uint32_t)((r * GKP + c8) * 2),
                   src + (size_t)(i0 + r) * K + kk + c8);
    }
    #pragma unroll
    for (int t = 0; t < 2; t++) {
        int pg = tid + t * 256;
        const __nv_bfloat16* src = t ? Wlp : Whp;
        int idx = pg & 255, r = idx >> 2, c8 = (idx & 3) * 8;
        cp_async16(bufb + (uint32_t)(2 * GAB) + (uint32_t)(t ? GWB : 0)
                        + (uint32_t)((r * GKP + c8) * 2),
                   src + (size_t)(j0 + r) * K + kk + c8);
    }
}

__device__ __forceinline__ void gemm_body(
    const __nv_bfloat16* __restrict__ Ahp, const __nv_bfloat16* __restrict__ Alp,
    const __nv_bfloat16* __restrict__ Whp, const __nv_bfloat16* __restrict__ Wlp,
    const float* __restrict__ bias, float* __restrict__ C,
    __nv_bfloat16* __restrict__ Ch, __nv_bfloat16* __restrict__ Cl,
    int Nout, int K, float scale, int relu, int mode, char* smemraw)
{
    const int tid = threadIdx.x, w = tid >> 5, lane = tid & 31;
    const int qr = lane >> 2, qc2 = (lane & 3) * 2;
    const int i0 = blockIdx.y * 128, j0 = blockIdx.x * 64;
    const int r0 = w * 16;

    float acc[8][4] = {};

    const int arow = r0 + ((lane >> 3) & 1) * 8 + (lane & 7);
    const int acol = (lane >> 4) * 8;
    const int brow = (lane & 7);
    const int bcol = (lane >> 3) * 8;

    const uint32_t smb = scvta(smemraw);
    const int nch = K / 32;

    gemm_stage(Ahp, Alp, Whp, Wlp, i0, j0, K, 0, smb, tid);
    cp_commit(); cp_wait0(); __syncthreads();

    int p = 0;
    for (int c = 0; c < nch; c++) {
        if (c + 1 < nch)
            gemm_stage(Ahp, Alp, Whp, Wlp, i0, j0, K, (c + 1) * 32,
                       smb + (uint32_t)((p ^ 1) * GBUF), tid);
        cp_commit();

        const uint32_t base = smb + (uint32_t)(p * GBUF);
        uint32_t ah[2][4], al[2][4];
        #pragma unroll
        for (int ks = 0; ks < 2; ks++) {
            uint32_t off = (uint32_t)((arow * GKP + ks * 16 + acol) * 2);
            ldsm_x4(ah[ks], base + off);
            ldsm_x4(al[ks], base + GAB + off);
        }
        #pragma unroll
        for (int nt = 0; nt < 8; nt++) {
            uint32_t bh[4], bl[4];
            uint32_t off = (uint32_t)(((nt * 8 + brow) * GKP + bcol) * 2);
            ldsm_x4(bh, base + 2 * GAB + off);
            ldsm_x4(bl, base + 2 * GAB + GWB + off);
            mma_bf16(acc[nt], ah[0], bh);
            mma_bf16(acc[nt], al[0], bh);
            mma_bf16(acc[nt], ah[0], bl);
            mma_bf16(acc[nt], ah[1], bh + 2);
            mma_bf16(acc[nt], al[1], bh + 2);
            mma_bf16(acc[nt], ah[1], bl + 2);
        }
        cp_wait0();
        __syncthreads();
        p ^= 1;
    }

    const int ra = i0 + r0 + qr, rb = ra + 8;
    #pragma unroll
    for (int nt = 0; nt < 8; nt++) {
        int j = j0 + nt * 8 + qc2;
        float b0 = bias[j], b1 = bias[j + 1];
        float v00 = (acc[nt][0] + b0) * scale;
        float v01 = (acc[nt][1] + b1) * scale;
        float v10 = (acc[nt][2] + b0) * scale;
        float v11 = (acc[nt][3] + b1) * scale;
        if (relu) {
            v00 = fmaxf(v00, 0.f); v01 = fmaxf(v01, 0.f);
            v10 = fmaxf(v10, 0.f); v11 = fmaxf(v11, 0.f);
        }
        if (mode == 0) {
            *(float2*)&C[(size_t)ra * Nout + j] = make_float2(v00, v01);
            *(float2*)&C[(size_t)rb * Nout + j] = make_float2(v10, v11);
        } else {
            uint32_t h0, l0, h1, l1;
            split_pack(v00, v01, h0, l0);
            split_pack(v10, v11, h1, l1);
            *(uint32_t*)&Ch[(size_t)ra * Nout + j] = h0;
            *(uint32_t*)&Cl[(size_t)ra * Nout + j] = l0;
            *(uint32_t*)&Ch[(size_t)rb * Nout + j] = h1;
            *(uint32_t*)&Cl[(size_t)rb * Nout + j] = l1;
        }
    }
}

__global__ void __launch_bounds__(256, 2)
gemm_plane(const __nv_bfloat16* Ahp, const __nv_bfloat16* Alp,
           const __nv_bfloat16* Whp, const __nv_bfloat16* Wlp,
           const float* bias, float* C, __nv_bfloat16* Ch, __nv_bfloat16* Cl,
           int Nout, int K, float scale, int relu, int mode)
{
    extern __shared__ __align__(16) char smemraw[];
    gemm_body(Ahp, Alp, Whp, Wlp, bias, C, Ch, Cl, Nout, K, scale, relu, mode, smemraw);
}

__global__ void __launch_bounds__(256, 2)
gemm_qkv(const __nv_bfloat16* hh, const __nv_bfloat16* hl,
         const __nv_bfloat16* Wqh, const __nv_bfloat16* Wql, const float* bq,
         __nv_bfloat16* Qh, __nv_bfloat16* Ql,
         const __nv_bfloat16* Wkh, const __nv_bfloat16* Wkl, const float* bk,
         __nv_bfloat16* Kh, __nv_bfloat16* Kl,
         const __nv_bfloat16* Wvh, const __nv_bfloat16* Wvl, const float* bv,
         __nv_bfloat16* Vh, __nv_bfloat16* Vl)
{
    extern __shared__ __align__(16) char smemraw[];
    const __nv_bfloat16 *Wh, *Wl; const float* b; __nv_bfloat16 *Ch, *Cl; float sc;
    if (blockIdx.z == 0)      { Wh = Wqh; Wl = Wql; b = bq; Ch = Qh; Cl = Ql; sc = QK2SCALE; }
    else if (blockIdx.z == 1) { Wh = Wkh; Wl = Wkl; b = bk; Ch = Kh; Cl = Kl; sc = 1.f; }
    else                      { Wh = Wvh; Wl = Wvl; b = bv; Ch = Vh; Cl = Vl; sc = 1.f; }
    gemm_body(hh, hl, Wh, Wl, b, nullptr, Ch, Cl, HID, HID, sc, 0, 1, smemraw);
}

// ------------------- tensor-core flash attention -------------------
// Pre-split bf16 hi/lo inputs. No online max; exp2 with log2e folded into Q.
// Double-buffered cp.async staging in dynamic smem. Epilogue emits AO planes.
#define KP 56
#define BUFB (64 * KP * 2)
#define FLASH_SMEM (8 * BUFB)          // 57344 bytes

__global__ void __launch_bounds__(256, 2)
flash_attn_mma(const __nv_bfloat16* __restrict__ Qhg, const __nv_bfloat16* __restrict__ Qlg,
               const __nv_bfloat16* __restrict__ Khg, const __nv_bfloat16* __restrict__ Klg,
               const __nv_bfloat16* __restrict__ Vhg, const __nv_bfloat16* __restrict__ Vlg,
               const float* __restrict__ Amat,
               __nv_bfloat16* __restrict__ AOh, __nv_bfloat16* __restrict__ AOl)
{
    extern __shared__ __align__(16) char smemraw[];
    __nv_bfloat16* Khs = (__nv_bfloat16*)(smemraw);
    __nv_bfloat16* Kls = (__nv_bfloat16*)(smemraw + 2 * BUFB);
    __nv_bfloat16* Vhs = (__nv_bfloat16*)(smemraw + 4 * BUFB);
    __nv_bfloat16* Vls = (__nv_bfloat16*)(smemraw + 6 * BUFB);

    const int tid  = threadIdx.x;
    const int w    = tid >> 5;
    const int lane = tid & 31;
    const int qr   = lane >> 2;
    const int qc2  = (lane & 3) * 2;

    const int hh   = blockIdx.y;
    const int row0 = blockIdx.x * 128;
    const int r0   = w * 16;

    const size_t hbase = (size_t)hh * NTOK * HD;

    uint32_t aQh[2][4], aQl[2][4];
    {
        const size_t ra = hbase + (size_t)(row0 + r0 + qr) * HD;
        const size_t rb = ra + 8 * HD;
        #pragma unroll
        for (int ks = 0; ks < 2; ks++) {
            int cb = ks * 16 + qc2;
            aQh[ks][0] = *(const uint32_t*)&Qhg[ra + cb];
            aQh[ks][1] = *(const uint32_t*)&Qhg[rb + cb];
            aQh[ks][2] = *(const uint32_t*)&Qhg[ra + cb + 8];
            aQh[ks][3] = *(const uint32_t*)&Qhg[rb + cb + 8];
            aQl[ks][0] = *(const uint32_t*)&Qlg[ra + cb];
            aQl[ks][1] = *(const uint32_t*)&Qlg[rb + cb];
            aQl[ks][2] = *(const uint32_t*)&Qlg[ra + cb + 8];
            aQl[ks][3] = *(const uint32_t*)&Qlg[rb + cb + 8];
        }
    }

    float oacc[4][4] = {};
    float ls0 = 0.f, ls1 = 0.f;

    const int ga = (row0 + r0 + qr) * NTOK;
    const int gb = (row0 + r0 + qr + 8) * NTOK;

    const uint32_t khb = scvta(Khs), klb = scvta(Kls);
    const uint32_t vhb = scvta(Vhs), vlb = scvta(Vls);
    const uint32_t koff = (uint32_t)(((lane & 7) * KP + (lane >> 3) * 8) * 2);
    const uint32_t vtoff = (uint32_t)(lane * KP * 2);

    const int sarr = tid >> 6;
    const int sidx0 = tid & 63;
    const char* gsrc;
    uint32_t sdstb;
    if (sarr == 0)      { gsrc = (const char*)(Khg + hbase); sdstb = khb; }
    else if (sarr == 1) { gsrc = (const char*)(Klg + hbase); sdstb = klb; }
    else if (sarr == 2) { gsrc = (const char*)(Vhg + hbase); sdstb = vhb; }
    else                { gsrc = (const char*)(Vlg + hbase); sdstb = vlb; }

    uint32_t soff[4];
    #pragma unroll
    for (int t = 0; t < 4; t++) {
        int idx = sidx0 + t * 64;
        int r = idx >> 2, c8 = (idx & 3) * 8;
        soff[t] = (uint32_t)((r * KP + c8) * 2);
    }

    #pragma unroll
    for (int t = 0; t < 4; t++)
        cp_async16(sdstb + soff[t], gsrc + (size_t)(sidx0 + t * 64) * 16);
    cp_commit();
    cp_wait0();
    __syncthreads();

    int p = 0;
    for (int mt = 0; mt < NTOK / 64; mt++) {
        const int m0 = mt * 64;
        const uint32_t pofs = (uint32_t)p * BUFB;

        if (mt < NTOK / 64 - 1) {
            const char* src = gsrc + (size_t)(mt + 1) * 64 * HD * 2;
            uint32_t dstb = sdstb + (pofs ^ BUFB);
            #pragma unroll
            for (int t = 0; t < 4; t++)
                cp_async16(dstb + soff[t], src + (size_t)(sidx0 + t * 64) * 16);
        }
        cp_commit();

        float2 Ar[8], Br[8];
        #pragma unroll
        for (int nt = 0; nt < 8; nt++) {
            int gc = m0 + nt * 8 + qc2;
            Ar[nt] = *(const float2*)&Amat[(size_t)ga + gc];
            Br[nt] = *(const float2*)&Amat[(size_t)gb + gc];
        }

        float sacc[8][4];
        #pragma unroll
        for (int nt = 0; nt < 8; nt++) {
            sacc[nt][0] = sacc[nt][1] = sacc[nt][2] = sacc[nt][3] = 0.f;
            uint32_t off = koff + pofs + (uint32_t)(nt * 8 * KP * 2);
            uint32_t bh[4], bl[4];
            ldsm_x4(bh, khb + off);
            ldsm_x4(bl, klb + off);
            mma_bf16(sacc[nt], aQh[0], bh);
            mma_bf16(sacc[nt], aQl[0], bh);
            mma_bf16(sacc[nt], aQh[0], bl);
            mma_bf16(sacc[nt], aQh[1], bh + 2);
            mma_bf16(sacc[nt], aQl[1], bh + 2);
            mma_bf16(sacc[nt], aQh[1], bl + 2);
        }

        #pragma unroll
        for (int nt = 0; nt < 8; nt++) {
            sacc[nt][0] = ex2(sacc[nt][0] * Ar[nt].x);
            sacc[nt][1] = ex2(sacc[nt][1] * Ar[nt].y);
            sacc[nt][2] = ex2(sacc[nt][2] * Br[nt].x);
            sacc[nt][3] = ex2(sacc[nt][3] * Br[nt].y);
            ls0 += sacc[nt][0] + sacc[nt][1];
            ls1 += sacc[nt][2] + sacc[nt][3];
        }

        uint32_t ph[4][4], pl_[4][4];
        #pragma unroll
        for (int kc = 0; kc < 4; kc++) {
            split_pack(sacc[2 * kc][0],     sacc[2 * kc][1],     ph[kc][0], pl_[kc][0]);
            split_pack(sacc[2 * kc][2],     sacc[2 * kc][3],     ph[kc][1], pl_[kc][1]);
            split_pack(sacc[2 * kc + 1][0], sacc[2 * kc + 1][1], ph[kc][2], pl_[kc][2]);
            split_pack(sacc[2 * kc + 1][2], sacc[2 * kc + 1][3], ph[kc][3], pl_[kc][3]);
        }

        #pragma unroll
        for (int nt = 0; nt < 4; nt++) {
            uint32_t off = vtoff + pofs + (uint32_t)(nt * 16);
            uint32_t bh[8], bl[8];
            ldsm_x4_t(bh,     vhb + off);
            ldsm_x4_t(bh + 4, vhb + off + 32 * KP * 2);
            ldsm_x4_t(bl,     vlb + off);
            ldsm_x4_t(bl + 4, vlb + off + 32 * KP * 2);
            #pragma unroll
            for (int kc = 0; kc < 4; kc++) {
                mma_bf16(oacc[nt], ph[kc],  bh + kc * 2);
                mma_bf16(oacc[nt], pl_[kc], bh + kc * 2);
                mma_bf16(oacc[nt], ph[kc],  bl + kc * 2);
            }
        }

        cp_wait0();
        __syncthreads();
        p ^= 1;
    }

    ls0 += __shfl_xor_sync(0xffffffffu, ls0, 1);
    ls0 += __shfl_xor_sync(0xffffffffu, ls0, 2);
    ls1 += __shfl_xor_sync(0xffffffffu, ls1, 1);
    ls1 += __shfl_xor_sync(0xffffffffu, ls1, 2);
    float inv0 = 1.f / ls0, inv1 = 1.f / ls1;

    const size_t ra = hbase + (size_t)(row0 + r0 + qr) * HD;
    const size_t rb = ra + 8 * HD;
    #pragma unroll
    for (int nt = 0; nt < 4; nt++) {
        int c = nt * 8 + qc2;
        uint32_t h0, l0, h1, l1;
        split_pack(oacc[nt][0] * inv0, oacc[nt][1] * inv0, h0, l0);
        split_pack(oacc[nt][2] * inv1, oacc[nt][3] * inv1, h1, l1);
        *(uint32_t*)&AOh[ra + c] = h0;
        *(uint32_t*)&AOl[ra + c] = l0;
        *(uint32_t*)&AOh[rb + c] = h1;
        *(uint32_t*)&AOl[rb + c] = l1;
    }
}

// ------------------- batchnorm helpers -------------------
__global__ void col_partial(const float* __restrict__ a, const float* __restrict__ b,
                            float* __restrict__ psum, float* __restrict__ psq)
{
    __shared__ float4 ssum[4][64], ssq[4][64];
    int q = threadIdx.x & 63;
    int rg = threadIdx.x >> 6;
    int c4 = q * 4;
    int blk = blockIdx.x;
    float4 s = {0.f, 0.f, 0.f, 0.f}, sq = {0.f, 0.f, 0.f, 0.f};
    #pragma unroll
    for (int k = 0; k < 8; k++) {
        int r = rg * 8 + k;
        size_t i = (size_t)(blk * 32 + r) * HID + c4;
        float4 av = *(const float4*)&a[i];
        float4 bv = *(const float4*)&b[i];
        float vx = av.x + bv.x, vy = av.y + bv.y, vz = av.z + bv.z, vw = av.w + bv.w;
        s.x += vx; s.y += vy; s.z += vz; s.w += vw;
        sq.x += vx * vx; sq.y += vy * vy; sq.z += vz * vz; sq.w += vw * vw;
    }
    ssum[rg][q] = s; ssq[rg][q] = sq;
    __syncthreads();
    if (rg == 0) {
        #pragma unroll
        for (int k = 1; k < 4; k++) {
            float4 t1 = ssum[k][q], t2 = ssq[k][q];
            s.x += t1.x; s.y += t1.y; s.z += t1.z; s.w += t1.w;
            sq.x += t2.x; sq.y += t2.y; sq.z += t2.z; sq.w += t2.w;
        }
        *(float4*)&psum[blk * HID + c4] = s;
        *(float4*)&psq[blk * HID + c4]  = sq;
    }
}

__global__ void col_finalize(const float* __restrict__ psum, const float* __restrict__ psq,
                             const float* __restrict__ g, const float* __restrict__ be,
                             float* __restrict__ scaleC, float* __restrict__ shiftC)
{
    int j = threadIdx.x;
    float s = 0.f, q = 0.f;
    #pragma unroll
    for (int b = 0; b < 128; b++) { s += psum[b * HID + j]; q += psq[b * HID + j]; }
    float m = s * (1.f / NTOK);
    float var = q * (1.f / NTOK) - m * m;
    var = fmaxf(var, 0.f);
    float sc = rsqrtf(var + EPSBN) * g[j];
    scaleC[j] = sc;
    shiftC[j] = be[j] - m * sc;
}

// BN apply; optionally also emit bf16 hi/lo planes of the result
__global__ void bn_apply(const float* __restrict__ a, const float* __restrict__ b,
                         const float* __restrict__ scaleC, const float* __restrict__ shiftC,
                         float* __restrict__ out,
                         __nv_bfloat16* __restrict__ oh, __nv_bfloat16* __restrict__ ol,
                         int emit_planes)
{
    int idx = (blockIdx.x * blockDim.x + threadIdx.x) * 4;
    int j = idx & (HID - 1);
    float4 av = *(const float4*)&a[idx];
    float4 bv = *(const float4*)&b[idx];
    float4 sc = *(const float4*)&scaleC[j];
    float4 sh = *(const float4*)&shiftC[j];
    float4 ov;
    ov.x = (av.x + bv.x) * sc.x + sh.x;
    ov.y = (av.y + bv.y) * sc.y + sh.y;
    ov.z = (av.z + bv.z) * sc.z + sh.z;
    ov.w = (av.w + bv.w) * sc.w + sh.w;
    *(float4*)&out[idx] = ov;
    if (emit_planes) {
        uint32_t h01, l01, h23, l23;
        split_pack(ov.x, ov.y, h01, l01);
        split_pack(ov.z, ov.w, h23, l23);
        *(uint32_t*)&oh[idx]     = h01;
        *(uint32_t*)&oh[idx + 2] = h23;
        *(uint32_t*)&ol[idx]     = l01;
        *(uint32_t*)&ol[idx + 2] = l23;
    }
}

// ------------------- launch -------------------
extern "C" void kernel_launch(void* const* d_in, const int* in_sizes, int n_in,
                              void* d_out, int out_size)
{
    const float* A   = (const float*)d_in[0];
    const float* h   = (const float*)d_in[1];
    const float* Wq  = (const float*)d_in[2];
    const float* bq  = (const float*)d_in[3];
    const float* Wk  = (const float*)d_in[4];
    const float* bk  = (const float*)d_in[5];
    const float* Wv  = (const float*)d_in[6];
    const float* bv  = (const float*)d_in[7];
    const float* Wo  = (const float*)d_in[8];
    const float* bo  = (const float*)d_in[9];
    const float* W1  = (const float*)d_in[10];
    const float* c1  = (const float*)d_in[11];
    const float* W2  = (const float*)d_in[12];
    const float* c2  = (const float*)d_in[13];
    const float* g1  = (const float*)d_in[14];
    const float* be1 = (const float*)d_in[15];
    const float* g2  = (const float*)d_in[16];
    const float* be2 = (const float*)d_in[17];
    float* out = (float*)d_out;

    __nv_bfloat16 *hh, *hl, *Wqh, *Wql, *Wkh, *Wkl, *Wvh, *Wvl, *Woh, *Wol,
                  *W1h, *W1l, *W2h, *W2l,
                  *Qh, *Ql, *Kh, *Kl, *Vh, *Vl, *AOh, *AOl, *X1h, *X1l, *Mh, *Ml;
    float *X, *X1, *F, *psum, *psq, *scaleC, *shiftC;
    cudaGetSymbolAddress((void**)&hh,  g_hh);  cudaGetSymbolAddress((void**)&hl,  g_hl);
    cudaGetSymbolAddress((void**)&Wqh, g_Wqh); cudaGetSymbolAddress((void**)&Wql, g_Wql);
    cudaGetSymbolAddress((void**)&Wkh, g_Wkh); cudaGetSymbolAddress((void**)&Wkl, g_Wkl);
    cudaGetSymbolAddress((void**)&Wvh, g_Wvh); cudaGetSymbolAddress((void**)&Wvl, g_Wvl);
    cudaGetSymbolAddress((void**)&Woh, g_Woh); cudaGetSymbolAddress((void**)&Wol, g_Wol);
    cudaGetSymbolAddress((void**)&W1h, g_W1h); cudaGetSymbolAddress((void**)&W1l, g_W1l);
    cudaGetSymbolAddress((void**)&W2h, g_W2h); cudaGetSymbolAddress((void**)&W2l, g_W2l);
    cudaGetSymbolAddress((void**)&Qh, g_Qh);   cudaGetSymbolAddress((void**)&Ql, g_Ql);
    cudaGetSymbolAddress((void**)&Kh, g_Kh);   cudaGetSymbolAddress((void**)&Kl, g_Kl);
    cudaGetSymbolAddress((void**)&Vh, g_Vh);   cudaGetSymbolAddress((void**)&Vl, g_Vl);
    cudaGetSymbolAddress((void**)&AOh, g_AOh); cudaGetSymbolAddress((void**)&AOl, g_AOl);
    cudaGetSymbolAddress((void**)&X1h, g_X1h); cudaGetSymbolAddress((void**)&X1l, g_X1l);
    cudaGetSymbolAddress((void**)&Mh, g_Mh);   cudaGetSymbolAddress((void**)&Ml, g_Ml);
    cudaGetSymbolAddress((void**)&X,   g_X);
    cudaGetSymbolAddress((void**)&X1,  g_X1);
    cudaGetSymbolAddress((void**)&F,   g_F);
    cudaGetSymbolAddress((void**)&psum,   g_psum);
    cudaGetSymbolAddress((void**)&psq,    g_psq);
    cudaGetSymbolAddress((void**)&scaleC, g_scaleC);
    cudaGetSymbolAddress((void**)&shiftC, g_shiftC);

    cudaFuncSetAttribute(flash_attn_mma,
                         cudaFuncAttributeMaxDynamicSharedMemorySize, FLASH_SMEM);
    cudaFuncSetAttribute(gemm_plane,
                         cudaFuncAttributeMaxDynamicSharedMemorySize, GEMM_SMEM);
    cudaFuncSetAttribute(gemm_qkv,
                         cudaFuncAttributeMaxDynamicSharedMemorySize, GEMM_SMEM);

    dim3 gqkv(HID / 64, NTOK / 128, 3);
    dim3 gproj(HID / 64, NTOK / 128);
    dim3 gffn1(2 * HID / 64, NTOK / 128);
    dim3 gattn(NTOK / 128, NHEADS);

    // pre-split h + all weights into bf16 hi/lo planes
    SplitJobs jobs;
    jobs.j[0] = { h,  hh,  hl,  NTOK * HID / 4 };
    jobs.j[1] = { Wq, Wqh, Wql, HID * HID / 4 };
    jobs.j[2] = { Wk, Wkh, Wkl, HID * HID / 4 };
    jobs.j[3] = { Wv, Wvh, Wvl, HID * HID / 4 };
    jobs.j[4] = { Wo, Woh, Wol, HID * HID / 4 };
    jobs.j[5] = { W1, W1h, W1l, 2 * HID * HID / 4 };
    jobs.j[6] = { W2, W2h, W2l, 2 * HID * HID / 4 };
    split_all<<<dim3(64, 7), 256>>>(jobs);

    // fused QKV projections (Q carries qscale*log2e)
    gemm_qkv<<<gqkv, 256, GEMM_SMEM>>>(hh, hl, Wqh, Wql, bq, Qh, Ql,
                                       Wkh, Wkl, bk, Kh, Kl,
                                       Wvh, Wvl, bv, Vh, Vl);

    // flash attention -> AO planes
    flash_attn_mma<<<gattn, 256, FLASH_SMEM>>>(Qh, Ql, Kh, Kl, Vh, Vl, A, AOh, AOl);

    // output projection -> X f32
    gemm_plane<<<gproj, 256, GEMM_SMEM>>>(AOh, AOl, Woh, Wol, bo,
                                          X, nullptr, nullptr, HID, HID, 1.f, 0, 0);

    // BN1 over (X + h) -> X1 f32 + planes
    col_partial<<<128, 256>>>(X, h, psum, psq);
    col_finalize<<<1, HID>>>(psum, psq, g1, be1, scaleC, shiftC);
    bn_apply<<<NTOK * HID / 1024, 256>>>(X, h, scaleC, shiftC, X1, X1h, X1l, 1);

    // FFN1 -> Mid planes (relu)
    gemm_plane<<<gffn1, 256, GEMM_SMEM>>>(X1h, X1l, W1h, W1l, c1,
                                          nullptr, Mh, Ml, 2 * HID, HID, 1.f, 1, 1);
    // FFN2 -> F f32
    gemm_plane<<<gproj, 256, GEMM_SMEM>>>(Mh, Ml, W2h, W2l, c2,
                                          F, nullptr, nullptr, HID, 2 * HID, 1.f, 0, 0);

    // BN2 over (X1 + F) -> out
    col_partial<<<128, 256>>>(X1, F, psum, psq);
    col_finalize<<<1, HID>>>(psum, psq, g2, be2, scaleC, shiftC);
    bn_apply<<<NTOK * HID / 1024, 256>>>(X1, F, scaleC, shiftC, out, nullptr, nullptr, 0);
}

// round 12
// speedup vs baseline: 1.2461x; 1.1414x over previous
#include <cuda_runtime.h>
#include <cuda_bf16.h>
#include <cstdint>

#define NTOK 4096
#define HID 256
#define NHEADS 8
#define HD 32
#define EPSBN 1e-5f
#define QSCALE 0.17677669529663687f       // 1/sqrt(32)
#define LOG2E  1.4426950408889634f
#define QK2SCALE (QSCALE * LOG2E)         // folded so softmax uses exp2

// ------------------- scratch (device globals; no allocation) -------------------
__device__ __nv_bfloat16 g_hh[NTOK * HID],  g_hl[NTOK * HID];
__device__ __nv_bfloat16 g_Wqh[HID * HID],  g_Wql[HID * HID];
__device__ __nv_bfloat16 g_Wkh[HID * HID],  g_Wkl[HID * HID];
__device__ __nv_bfloat16 g_Wvh[HID * HID],  g_Wvl[HID * HID];
__device__ __nv_bfloat16 g_Woh[HID * HID],  g_Wol[HID * HID];
__device__ __nv_bfloat16 g_W1h[2 * HID * HID], g_W1l[2 * HID * HID];
__device__ __nv_bfloat16 g_W2h[2 * HID * HID], g_W2l[2 * HID * HID];
__device__ __nv_bfloat16 g_Qh[NTOK * HID], g_Ql[NTOK * HID];
__device__ __nv_bfloat16 g_Kh[NTOK * HID], g_Kl[NTOK * HID];
__device__ __nv_bfloat16 g_Vh[NTOK * HID], g_Vl[NTOK * HID];
__device__ __nv_bfloat16 g_AOh[NTOK * HID], g_AOl[NTOK * HID];
__device__ __nv_bfloat16 g_X1h[NTOK * HID], g_X1l[NTOK * HID];
__device__ __nv_bfloat16 g_Mh[NTOK * 2 * HID], g_Ml[NTOK * 2 * HID];
__device__ float g_X[NTOK * HID];
__device__ float g_X1[NTOK * HID];
__device__ float g_F[NTOK * HID];
__device__ float g_psum[128 * HID];
__device__ float g_psq[128 * HID];
__device__ float g_scaleC[HID];
__device__ float g_shiftC[HID];

// ------------------- helpers -------------------
__device__ __forceinline__ void mma_bf16(float* c, const uint32_t* a, const uint32_t* b)
{
    asm volatile(
        "mma.sync.aligned.m16n8k16.row.col.f32.bf16.bf16.f32 "
        "{%0,%1,%2,%3}, {%4,%5,%6,%7}, {%8,%9}, {%0,%1,%2,%3};"
        : "+f"(c[0]), "+f"(c[1]), "+f"(c[2]), "+f"(c[3])
        : "r"(a[0]), "r"(a[1]), "r"(a[2]), "r"(a[3]), "r"(b[0]), "r"(b[1]));
}

__device__ __forceinline__ void split_pack(float x, float y, uint32_t& hi, uint32_t& lo)
{
    uint32_t h;
    asm("cvt.rn.bf16x2.f32 %0, %1, %2;" : "=r"(h) : "f"(y), "f"(x));
    float xr = __uint_as_float(h << 16);
    float yr = __uint_as_float(h & 0xffff0000u);
    float xl = x - xr, yl = y - yr;
    uint32_t l;
    asm("cvt.rn.bf16x2.f32 %0, %1, %2;" : "=r"(l) : "f"(yl), "f"(xl));
    hi = h; lo = l;
}

__device__ __forceinline__ uint32_t pack_bf16(float x, float y)
{
    uint32_t h;
    asm("cvt.rn.bf16x2.f32 %0, %1, %2;" : "=r"(h) : "f"(y), "f"(x));
    return h;
}

__device__ __forceinline__ float ex2(float x)
{
    float r;
    asm("ex2.approx.ftz.f32 %0, %1;" : "=f"(r) : "f"(x));
    return r;
}

__device__ __forceinline__ uint32_t scvta(const void* p)
{
    return (uint32_t)__cvta_generic_to_shared(p);
}

__device__ __forceinline__ void ldsm_x4(uint32_t* d, uint32_t addr)
{
    asm volatile("ldmatrix.sync.aligned.m8n8.x4.shared.b16 {%0,%1,%2,%3}, [%4];"
                 : "=r"(d[0]), "=r"(d[1]), "=r"(d[2]), "=r"(d[3]) : "r"(addr));
}

__device__ __forceinline__ void ldsm_x4_t(uint32_t* d, uint32_t addr)
{
    asm volatile("ldmatrix.sync.aligned.m8n8.x4.trans.shared.b16 {%0,%1,%2,%3}, [%4];"
                 : "=r"(d[0]), "=r"(d[1]), "=r"(d[2]), "=r"(d[3]) : "r"(addr));
}

__device__ __forceinline__ void cp_async16(uint32_t dst, const void* src)
{
    asm volatile("cp.async.cg.shared.global [%0], [%1], 16;" :: "r"(dst), "l"(src));
}

__device__ __forceinline__ void cp_commit() { asm volatile("cp.async.commit_group;"); }
__device__ __forceinline__ void cp_wait0()  { asm volatile("cp.async.wait_group 0;"); }

// ------------------- split_all: f32 -> bf16 hi/lo planes (h + 6 weights) ----------
struct SplitJob { const float* src; __nv_bfloat16* hi; __nv_bfloat16* lo; int n4; };
struct SplitJobs { SplitJob j[7]; };

__global__ void split_all(SplitJobs jobs)
{
    SplitJob job = jobs.j[blockIdx.y];
    for (int i = blockIdx.x * blockDim.x + threadIdx.x; i < job.n4;
         i += gridDim.x * blockDim.x) {
        float4 v = *(const float4*)&job.src[(size_t)i * 4];
        uint32_t h01, l01, h23, l23;
        split_pack(v.x, v.y, h01, l01);
        split_pack(v.z, v.w, h23, l23);
        *(uint32_t*)&job.hi[(size_t)i * 4]     = h01;
        *(uint32_t*)&job.hi[(size_t)i * 4 + 2] = h23;
        *(uint32_t*)&job.lo[(size_t)i * 4]     = l01;
        *(uint32_t*)&job.lo[(size_t)i * 4 + 2] = l23;
    }
}

// ------------------- tensor-core GEMM on pre-split planes -------------------
#define GKP 40
#define GAB (128 * GKP * 2)
#define GWB (64 * GKP * 2)
#define GBUF (2 * GAB + 2 * GWB)
#define GEMM_SMEM (2 * GBUF)

__device__ __forceinline__ void gemm_stage(
    const __nv_bfloat16* __restrict__ Ahp, const __nv_bfloat16* __restrict__ Alp,
    const __nv_bfloat16* __restrict__ Whp, const __nv_bfloat16* __restrict__ Wlp,
    int i0, int j0, int K, int kk, uint32_t bufb, int tid)
{
    #pragma unroll
    for (int t = 0; t < 4; t++) {
        int pg = tid + t * 256;
        const __nv_bfloat16* src = (t >= 2) ? Alp : Ahp;
        int idx = pg & 511, r = idx >> 2, c8 = (idx & 3) * 8;
        cp_async16(bufb + (uint32_t)((t >= 2) ? GAB : 0) + (uint32_t)((r * GKP + c8) * 2),
                   src + (size_t)(i0 + r) * K + kk + c8);
    }
    #pragma unroll
    for (int t = 0; t < 2; t++) {
        int pg = tid + t * 256;
        const __nv_bfloat16* src = t ? Wlp : Whp;
        int idx = pg & 255, r = idx >> 2, c8 = (idx & 3) * 8;
        cp_async16(bufb + (uint32_t)(2 * GAB) + (uint32_t)(t ? GWB : 0)
                        + (uint32_t)((r * GKP + c8) * 2),
                   src + (size_t)(j0 + r) * K + kk + c8);
    }
}

__device__ __forceinline__ void gemm_body(
    const __nv_bfloat16* __restrict__ Ahp, const __nv_bfloat16* __restrict__ Alp,
    const __nv_bfloat16* __restrict__ Whp, const __nv_bfloat16* __restrict__ Wlp,
    const float* __restrict__ bias, float* __restrict__ C,
    __nv_bfloat16* __restrict__ Ch, __nv_bfloat16* __restrict__ Cl,
    int Nout, int K, float scale, int relu, int mode, char* smemraw)
{
    const int tid = threadIdx.x, w = tid >> 5, lane = tid & 31;
    const int qr = lane >> 2, qc2 = (lane & 3) * 2;
    const int i0 = blockIdx.y * 128, j0 = blockIdx.x * 64;
    const int r0 = w * 16;

    float acc[8][4] = {};

    const int arow = r0 + ((lane >> 3) & 1) * 8 + (lane & 7);
    const int acol = (lane >> 4) * 8;
    const int brow = (lane & 7);
    const int bcol = (lane >> 3) * 8;

    const uint32_t smb = scvta(smemraw);
    const int nch = K / 32;

    gemm_stage(Ahp, Alp, Whp, Wlp, i0, j0, K, 0, smb, tid);
    cp_commit(); cp_wait0(); __syncthreads();

    int p = 0;
    for (int c = 0; c < nch; c++) {
        if (c + 1 < nch)
            gemm_stage(Ahp, Alp, Whp, Wlp, i0, j0, K, (c + 1) * 32,
                       smb + (uint32_t)((p ^ 1) * GBUF), tid);
        cp_commit();

        const uint32_t base = smb + (uint32_t)(p * GBUF);
        uint32_t ah[2][4], al[2][4];
        #pragma unroll
        for (int ks = 0; ks < 2; ks++) {
            uint32_t off = (uint32_t)((arow * GKP + ks * 16 + acol) * 2);
            ldsm_x4(ah[ks], base + off);
            ldsm_x4(al[ks], base + GAB + off);
        }
        #pragma unroll
        for (int nt = 0; nt < 8; nt++) {
            uint32_t bh[4], bl[4];
            uint32_t off = (uint32_t)(((nt * 8 + brow) * GKP + bcol) * 2);
            ldsm_x4(bh, base + 2 * GAB + off);
            ldsm_x4(bl, base + 2 * GAB + GWB + off);
            mma_bf16(acc[nt], ah[0], bh);
            mma_bf16(acc[nt], al[0], bh);
            mma_bf16(acc[nt], ah[0], bl);
            mma_bf16(acc[nt], ah[1], bh + 2);
            mma_bf16(acc[nt], al[1], bh + 2);
            mma_bf16(acc[nt], ah[1], bl + 2);
        }
        cp_wait0();
        __syncthreads();
        p ^= 1;
    }

    const int ra = i0 + r0 + qr, rb = ra + 8;
    #pragma unroll
    for (int nt = 0; nt < 8; nt++) {
        int j = j0 + nt * 8 + qc2;
        float b0 = bias[j], b1 = bias[j + 1];
        float v00 = (acc[nt][0] + b0) * scale;
        float v01 = (acc[nt][1] + b1) * scale;
        float v10 = (acc[nt][2] + b0) * scale;
        float v11 = (acc[nt][3] + b1) * scale;
        if (relu) {
            v00 = fmaxf(v00, 0.f); v01 = fmaxf(v01, 0.f);
            v10 = fmaxf(v10, 0.f); v11 = fmaxf(v11, 0.f);
        }
        if (mode == 0) {
            *(float2*)&C[(size_t)ra * Nout + j] = make_float2(v00, v01);
            *(float2*)&C[(size_t)rb * Nout + j] = make_float2(v10, v11);
        } else {
            uint32_t h0, l0, h1, l1;
            split_pack(v00, v01, h0, l0);
            split_pack(v10, v11, h1, l1);
            *(uint32_t*)&Ch[(size_t)ra * Nout + j] = h0;
            *(uint32_t*)&Cl[(size_t)ra * Nout + j] = l0;
            *(uint32_t*)&Ch[(size_t)rb * Nout + j] = h1;
            *(uint32_t*)&Cl[(size_t)rb * Nout + j] = l1;
        }
    }
}

__global__ void __launch_bounds__(256, 2)
gemm_plane(const __nv_bfloat16* Ahp, const __nv_bfloat16* Alp,
           const __nv_bfloat16* Whp, const __nv_bfloat16* Wlp,
           const float* bias, float* C, __nv_bfloat16* Ch, __nv_bfloat16* Cl,
           int Nout, int K, float scale, int relu, int mode)
{
    extern __shared__ __align__(16) char smemraw[];
    gemm_body(Ahp, Alp, Whp, Wlp, bias, C, Ch, Cl, Nout, K, scale, relu, mode, smemraw);
}

__global__ void __launch_bounds__(256, 2)
gemm_qkv(const __nv_bfloat16* hh, const __nv_bfloat16* hl,
         const __nv_bfloat16* Wqh, const __nv_bfloat16* Wql, const float* bq,
         __nv_bfloat16* Qh, __nv_bfloat16* Ql,
         const __nv_bfloat16* Wkh, const __nv_bfloat16* Wkl, const float* bk,
         __nv_bfloat16* Kh, __nv_bfloat16* Kl,
         const __nv_bfloat16* Wvh, const __nv_bfloat16* Wvl, const float* bv,
         __nv_bfloat16* Vh, __nv_bfloat16* Vl)
{
    extern __shared__ __align__(16) char smemraw[];
    const __nv_bfloat16 *Wh, *Wl; const float* b; __nv_bfloat16 *Ch, *Cl; float sc;
    if (blockIdx.z == 0)      { Wh = Wqh; Wl = Wql; b = bq; Ch = Qh; Cl = Ql; sc = QK2SCALE; }
    else if (blockIdx.z == 1) { Wh = Wkh; Wl = Wkl; b = bk; Ch = Kh; Cl = Kl; sc = 1.f; }
    else                      { Wh = Wvh; Wl = Wvl; b = bv; Ch = Vh; Cl = Vl; sc = 1.f; }
    gemm_body(hh, hl, Wh, Wl, b, nullptr, Ch, Cl, HID, HID, sc, 0, 1, smemraw);
}

// ------------------- tensor-core flash attention -------------------
// QK keeps 3-term bf16 split (errors don't average). PV uses SINGLE bf16 term
// (P positive, errors average over ~1e3 keys -> ~1e-4 output error).
// V lo plane unused. 3 smem arrays, double-buffered cp.async, dynamic smem.
#define KP 56
#define BUFB (64 * KP * 2)
#define FLASH_SMEM (6 * BUFB)          // 43008 bytes

__global__ void __launch_bounds__(256, 2)
flash_attn_mma(const __nv_bfloat16* __restrict__ Qhg, const __nv_bfloat16* __restrict__ Qlg,
               const __nv_bfloat16* __restrict__ Khg, const __nv_bfloat16* __restrict__ Klg,
               const __nv_bfloat16* __restrict__ Vhg,
               const float* __restrict__ Amat,
               __nv_bfloat16* __restrict__ AOh, __nv_bfloat16* __restrict__ AOl)
{
    extern __shared__ __align__(16) char smemraw[];
    __nv_bfloat16* Khs = (__nv_bfloat16*)(smemraw);
    __nv_bfloat16* Kls = (__nv_bfloat16*)(smemraw + 2 * BUFB);
    __nv_bfloat16* Vhs = (__nv_bfloat16*)(smemraw + 4 * BUFB);

    const int tid  = threadIdx.x;
    const int w    = tid >> 5;
    const int lane = tid & 31;
    const int qr   = lane >> 2;
    const int qc2  = (lane & 3) * 2;

    const int hh   = blockIdx.y;
    const int row0 = blockIdx.x * 128;
    const int r0   = w * 16;

    const size_t hbase = (size_t)hh * NTOK * HD;

    uint32_t aQh[2][4], aQl[2][4];
    {
        const size_t ra = hbase + (size_t)(row0 + r0 + qr) * HD;
        const size_t rb = ra + 8 * HD;
        #pragma unroll
        for (int ks = 0; ks < 2; ks++) {
            int cb = ks * 16 + qc2;
            aQh[ks][0] = *(const uint32_t*)&Qhg[ra + cb];
            aQh[ks][1] = *(const uint32_t*)&Qhg[rb + cb];
            aQh[ks][2] = *(const uint32_t*)&Qhg[ra + cb + 8];
            aQh[ks][3] = *(const uint32_t*)&Qhg[rb + cb + 8];
            aQl[ks][0] = *(const uint32_t*)&Qlg[ra + cb];
            aQl[ks][1] = *(const uint32_t*)&Qlg[rb + cb];
            aQl[ks][2] = *(const uint32_t*)&Qlg[ra + cb + 8];
            aQl[ks][3] = *(const uint32_t*)&Qlg[rb + cb + 8];
        }
    }

    float oacc[4][4] = {};
    float ls0 = 0.f, ls1 = 0.f;

    const int ga = (row0 + r0 + qr) * NTOK;
    const int gb = (row0 + r0 + qr + 8) * NTOK;

    const uint32_t khb = scvta(Khs), klb = scvta(Kls);
    const uint32_t vhb = scvta(Vhs);
    const uint32_t koff = (uint32_t)(((lane & 7) * KP + (lane >> 3) * 8) * 2);
    const uint32_t vtoff = (uint32_t)(lane * KP * 2);

    // staging: each thread copies chunk tid of each of the 3 arrays (256 chunks ea)
    const char* gA[3] = { (const char*)(Khg + hbase), (const char*)(Klg + hbase),
                          (const char*)(Vhg + hbase) };
    const uint32_t sA[3] = { khb, klb, vhb };
    const uint32_t soff = (uint32_t)((((tid >> 2) * KP) + (tid & 3) * 8) * 2);

    #pragma unroll
    for (int a = 0; a < 3; a++)
        cp_async16(sA[a] + soff, gA[a] + (size_t)tid * 16);
    cp_commit();
    cp_wait0();
    __syncthreads();

    int p = 0;
    for (int mt = 0; mt < NTOK / 64; mt++) {
        const int m0 = mt * 64;
        const uint32_t pofs = (uint32_t)p * BUFB;

        if (mt < NTOK / 64 - 1) {
            const size_t goff = (size_t)(mt + 1) * 64 * HD * 2;
            const uint32_t db = pofs ^ BUFB;
            #pragma unroll
            for (int a = 0; a < 3; a++)
                cp_async16(sA[a] + db + soff, gA[a] + goff + (size_t)tid * 16);
        }
        cp_commit();

        float2 Ar[8], Br[8];
        #pragma unroll
        for (int nt = 0; nt < 8; nt++) {
            int gc = m0 + nt * 8 + qc2;
            Ar[nt] = *(const float2*)&Amat[(size_t)ga + gc];
            Br[nt] = *(const float2*)&Amat[(size_t)gb + gc];
        }

        // ---- S = Q·Kᵀ (3-term split) ----
        float sacc[8][4];
        #pragma unroll
        for (int nt = 0; nt < 8; nt++) {
            sacc[nt][0] = sacc[nt][1] = sacc[nt][2] = sacc[nt][3] = 0.f;
            uint32_t off = koff + pofs + (uint32_t)(nt * 8 * KP * 2);
            uint32_t bh[4], bl[4];
            ldsm_x4(bh, khb + off);
            ldsm_x4(bl, klb + off);
            mma_bf16(sacc[nt], aQh[0], bh);
            mma_bf16(sacc[nt], aQl[0], bh);
            mma_bf16(sacc[nt], aQh[0], bl);
            mma_bf16(sacc[nt], aQh[1], bh + 2);
            mma_bf16(sacc[nt], aQl[1], bh + 2);
            mma_bf16(sacc[nt], aQh[1], bl + 2);
        }

        // ---- p = exp2(s*A); lane-local row sums (exact f32) ----
        #pragma unroll
        for (int nt = 0; nt < 8; nt++) {
            sacc[nt][0] = ex2(sacc[nt][0] * Ar[nt].x);
            sacc[nt][1] = ex2(sacc[nt][1] * Ar[nt].y);
            sacc[nt][2] = ex2(sacc[nt][2] * Br[nt].x);
            sacc[nt][3] = ex2(sacc[nt][3] * Br[nt].y);
            ls0 += sacc[nt][0] + sacc[nt][1];
            ls1 += sacc[nt][2] + sacc[nt][3];
        }

        // ---- pack P to bf16 (single term) ----
        uint32_t ph[4][4];
        #pragma unroll
        for (int kc = 0; kc < 4; kc++) {
            ph[kc][0] = pack_bf16(sacc[2 * kc][0],     sacc[2 * kc][1]);
            ph[kc][1] = pack_bf16(sacc[2 * kc][2],     sacc[2 * kc][3]);
            ph[kc][2] = pack_bf16(sacc[2 * kc + 1][0], sacc[2 * kc + 1][1]);
            ph[kc][3] = pack_bf16(sacc[2 * kc + 1][2], sacc[2 * kc + 1][3]);
        }

        // ---- O += P·V (single bf16 term) ----
        #pragma unroll
        for (int nt = 0; nt < 4; nt++) {
            uint32_t off = vtoff + pofs + (uint32_t)(nt * 16);
            uint32_t bh[8];
            ldsm_x4_t(bh,     vhb + off);
            ldsm_x4_t(bh + 4, vhb + off + 32 * KP * 2);
            #pragma unroll
            for (int kc = 0; kc < 4; kc++)
                mma_bf16(oacc[nt], ph[kc], bh + kc * 2);
        }

        cp_wait0();
        __syncthreads();
        p ^= 1;
    }

    ls0 += __shfl_xor_sync(0xffffffffu, ls0, 1);
    ls0 += __shfl_xor_sync(0xffffffffu, ls0, 2);
    ls1 += __shfl_xor_sync(0xffffffffu, ls1, 1);
    ls1 += __shfl_xor_sync(0xffffffffu, ls1, 2);
    float inv0 = 1.f / ls0, inv1 = 1.f / ls1;

    const size_t ra = hbase + (size_t)(row0 + r0 + qr) * HD;
    const size_t rb = ra + 8 * HD;
    #pragma unroll
    for (int nt = 0; nt < 4; nt++) {
        int c = nt * 8 + qc2;
        uint32_t h0, l0, h1, l1;
        split_pack(oacc[nt][0] * inv0, oacc[nt][1] * inv0, h0, l0);
        split_pack(oacc[nt][2] * inv1, oacc[nt][3] * inv1, h1, l1);
        *(uint32_t*)&AOh[ra + c] = h0;
        *(uint32_t*)&AOl[ra + c] = l0;
        *(uint32_t*)&AOh[rb + c] = h1;
        *(uint32_t*)&AOl[rb + c] = l1;
    }
}

// ------------------- batchnorm helpers -------------------
__global__ void col_partial(const float* __restrict__ a, const float* __restrict__ b,
                            float* __restrict__ psum, float* __restrict__ psq)
{
    __shared__ float4 ssum[4][64], ssq[4][64];
    int q = threadIdx.x & 63;
    int rg = threadIdx.x >> 6;
    int c4 = q * 4;
    int blk = blockIdx.x;
    float4 s = {0.f, 0.f, 0.f, 0.f}, sq = {0.f, 0.f, 0.f, 0.f};
    #pragma unroll
    for (int k = 0; k < 8; k++) {
        int r = rg * 8 + k;
        size_t i = (size_t)(blk * 32 + r) * HID + c4;
        float4 av = *(const float4*)&a[i];
        float4 bv = *(const float4*)&b[i];
        float vx = av.x + bv.x, vy = av.y + bv.y, vz = av.z + bv.z, vw = av.w + bv.w;
        s.x += vx; s.y += vy; s.z += vz; s.w += vw;
        sq.x += vx * vx; sq.y += vy * vy; sq.z += vz * vz; sq.w += vw * vw;
    }
    ssum[rg][q] = s; ssq[rg][q] = sq;
    __syncthreads();
    if (rg == 0) {
        #pragma unroll
        for (int k = 1; k < 4; k++) {
            float4 t1 = ssum[k][q], t2 = ssq[k][q];
            s.x += t1.x; s.y += t1.y; s.z += t1.z; s.w += t1.w;
            sq.x += t2.x; sq.y += t2.y; sq.z += t2.z; sq.w += t2.w;
        }
        *(float4*)&psum[blk * HID + c4] = s;
        *(float4*)&psq[blk * HID + c4]  = sq;
    }
}

__global__ void col_finalize(const float* __restrict__ psum, const float* __restrict__ psq,
                             const float* __restrict__ g, const float* __restrict__ be,
                             float* __restrict__ scaleC, float* __restrict__ shiftC)
{
    int j = threadIdx.x;
    float s = 0.f, q = 0.f;
    #pragma unroll
    for (int b = 0; b < 128; b++) { s += psum[b * HID + j]; q += psq[b * HID + j]; }
    float m = s * (1.f / NTOK);
    float var = q * (1.f / NTOK) - m * m;
    var = fmaxf(var, 0.f);
    float sc = rsqrtf(var + EPSBN) * g[j];
    scaleC[j] = sc;
    shiftC[j] = be[j] - m * sc;
}

__global__ void bn_apply(const float* __restrict__ a, const float* __restrict__ b,
                         const float* __restrict__ scaleC, const float* __restrict__ shiftC,
                         float* __restrict__ out,
                         __nv_bfloat16* __restrict__ oh, __nv_bfloat16* __restrict__ ol,
                         int emit_planes)
{
    int idx = (blockIdx.x * blockDim.x + threadIdx.x) * 4;
    int j = idx & (HID - 1);
    float4 av = *(const float4*)&a[idx];
    float4 bv = *(const float4*)&b[idx];
    float4 sc = *(const float4*)&scaleC[j];
    float4 sh = *(const float4*)&shiftC[j];
    float4 ov;
    ov.x = (av.x + bv.x) * sc.x + sh.x;
    ov.y = (av.y + bv.y) * sc.y + sh.y;
    ov.z = (av.z + bv.z) * sc.z + sh.z;
    ov.w = (av.w + bv.w) * sc.w + sh.w;
    *(float4*)&out[idx] = ov;
    if (emit_planes) {
        uint32_t h01, l01, h23, l23;
        split_pack(ov.x, ov.y, h01, l01);
        split_pack(ov.z, ov.w, h23, l23);
        *(uint32_t*)&oh[idx]     = h01;
        *(uint32_t*)&oh[idx + 2] = h23;
        *(uint32_t*)&ol[idx]     = l01;
        *(uint32_t*)&ol[idx + 2] = l23;
    }
}

// ------------------- launch -------------------
extern "C" void kernel_launch(void* const* d_in, const int* in_sizes, int n_in,
                              void* d_out, int out_size)
{
    const float* A   = (const float*)d_in[0];
    const float* h   = (const float*)d_in[1];
    const float* Wq  = (const float*)d_in[2];
    const float* bq  = (const float*)d_in[3];
    const float* Wk  = (const float*)d_in[4];
    const float* bk  = (const float*)d_in[5];
    const float* Wv  = (const float*)d_in[6];
    const float* bv  = (const float*)d_in[7];
    const float* Wo  = (const float*)d_in[8];
    const float* bo  = (const float*)d_in[9];
    const float* W1  = (const float*)d_in[10];
    const float* c1  = (const float*)d_in[11];
    const float* W2  = (const float*)d_in[12];
    const float* c2  = (const float*)d_in[13];
    const float* g1  = (const float*)d_in[14];
    const float* be1 = (const float*)d_in[15];
    const float* g2  = (const float*)d_in[16];
    const float* be2 = (const float*)d_in[17];
    float* out = (float*)d_out;

    __nv_bfloat16 *hh, *hl, *Wqh, *Wql, *Wkh, *Wkl, *Wvh, *Wvl, *Woh, *Wol,
                  *W1h, *W1l, *W2h, *W2l,
                  *Qh, *Ql, *Kh, *Kl, *Vh, *Vl, *AOh, *AOl, *X1h, *X1l, *Mh, *Ml;
    float *X, *X1, *F, *psum, *psq, *scaleC, *shiftC;
    cudaGetSymbolAddress((void**)&hh,  g_hh);  cudaGetSymbolAddress((void**)&hl,  g_hl);
    cudaGetSymbolAddress((void**)&Wqh, g_Wqh); cudaGetSymbolAddress((void**)&Wql, g_Wql);
    cudaGetSymbolAddress((void**)&Wkh, g_Wkh); cudaGetSymbolAddress((void**)&Wkl, g_Wkl);
    cudaGetSymbolAddress((void**)&Wvh, g_Wvh); cudaGetSymbolAddress((void**)&Wvl, g_Wvl);
    cudaGetSymbolAddress((void**)&Woh, g_Woh); cudaGetSymbolAddress((void**)&Wol, g_Wol);
    cudaGetSymbolAddress((void**)&W1h, g_W1h); cudaGetSymbolAddress((void**)&W1l, g_W1l);
    cudaGetSymbolAddress((void**)&W2h, g_W2h); cudaGetSymbolAddress((void**)&W2l, g_W2l);
    cudaGetSymbolAddress((void**)&Qh, g_Qh);   cudaGetSymbolAddress((void**)&Ql, g_Ql);
    cudaGetSymbolAddress((void**)&Kh, g_Kh);   cudaGetSymbolAddress((void**)&Kl, g_Kl);
    cudaGetSymbolAddress((void**)&Vh, g_Vh);   cudaGetSymbolAddress((void**)&Vl, g_Vl);
    cudaGetSymbolAddress((void**)&AOh, g_AOh); cudaGetSymbolAddress((void**)&AOl, g_AOl);
    cudaGetSymbolAddress((void**)&X1h, g_X1h); cudaGetSymbolAddress((void**)&X1l, g_X1l);
    cudaGetSymbolAddress((void**)&Mh, g_Mh);   cudaGetSymbolAddress((void**)&Ml, g_Ml);
    cudaGetSymbolAddress((void**)&X,   g_X);
    cudaGetSymbolAddress((void**)&X1,  g_X1);
    cudaGetSymbolAddress((void**)&F,   g_F);
    cudaGetSymbolAddress((void**)&psum,   g_psum);
    cudaGetSymbolAddress((void**)&psq,    g_psq);
    cudaGetSymbolAddress((void**)&scaleC, g_scaleC);
    cudaGetSymbolAddress((void**)&shiftC, g_shiftC);

    cudaFuncSetAttribute(flash_attn_mma,
                         cudaFuncAttributeMaxDynamicSharedMemorySize, FLASH_SMEM);
    cudaFuncSetAttribute(gemm_plane,
                         cudaFuncAttributeMaxDynamicSharedMemorySize, GEMM_SMEM);
    cudaFuncSetAttribute(gemm_qkv,
                         cudaFuncAttributeMaxDynamicSharedMemorySize, GEMM_SMEM);

    dim3 gqkv(HID / 64, NTOK / 128, 3);
    dim3 gproj(HID / 64, NTOK / 128);
    dim3 gffn1(2 * HID / 64, NTOK / 128);
    dim3 gattn(NTOK / 128, NHEADS);

    SplitJobs jobs;
    jobs.j[0] = { h,  hh,  hl,  NTOK * HID / 4 };
    jobs.j[1] = { Wq, Wqh, Wql, HID * HID / 4 };
    jobs.j[2] = { Wk, Wkh, Wkl, HID * HID / 4 };
    jobs.j[3] = { Wv, Wvh, Wvl, HID * HID / 4 };
    jobs.j[4] = { Wo, Woh, Wol, HID * HID / 4 };
    jobs.j[5] = { W1, W1h, W1l, 2 * HID * HID / 4 };
    jobs.j[6] = { W2, W2h, W2l, 2 * HID * HID / 4 };
    split_all<<<dim3(64, 7), 256>>>(jobs);

    gemm_qkv<<<gqkv, 256, GEMM_SMEM>>>(hh, hl, Wqh, Wql, bq, Qh, Ql,
                                       Wkh, Wkl, bk, Kh, Kl,
                                       Wvh, Wvl, bv, Vh, Vl);

    flash_attn_mma<<<gattn, 256, FLASH_SMEM>>>(Qh, Ql, Kh, Kl, Vh, A, AOh, AOl);

    gemm_plane<<<gproj, 256, GEMM_SMEM>>>(AOh, AOl, Woh, Wol, bo,
                                          X, nullptr, nullptr, HID, HID, 1.f, 0, 0);

    col_partial<<<128, 256>>>(X, h, psum, psq);
    col_finalize<<<1, HID>>>(psum, psq, g1, be1, scaleC, shiftC);
    bn_apply<<<NTOK * HID / 1024, 256>>>(X, h, scaleC, shiftC, X1, X1h, X1l, 1);

    gemm_plane<<<gffn1, 256, GEMM_SMEM>>>(X1h, X1l, W1h, W1l, c1,
                                          nullptr, Mh, Ml, 2 * HID, HID, 1.f, 1, 1);
    gemm_plane<<<gproj, 256, GEMM_SMEM>>>(Mh, Ml, W2h, W2l, c2,
                                          F, nullptr, nullptr, HID, 2 * HID, 1.f, 0, 0);

    col_partial<<<128, 256>>>(X1, F, psum, psq);
    col_finalize<<<1, HID>>>(psum, psq, g2, be2, scaleC, shiftC);
    bn_apply<<<NTOK * HID / 1024, 256>>>(X1, F, scaleC, shiftC, out, nullptr, nullptr, 0);
}

// round 13
// speedup vs baseline: 1.4153x; 1.1357x over previous
#include <cuda_runtime.h>
#include <cuda_bf16.h>
#include <cstdint>

#define NTOK 4096
#define HID 256
#define NHEADS 8
#define HD 32
#define EPSBN 1e-5f
#define QSCALE 0.17677669529663687f       // 1/sqrt(32)
#define LOG2E  1.4426950408889634f
#define QK2SCALE (QSCALE * LOG2E)         // folded so softmax uses exp2

// ------------------- scratch (device globals; no allocation) -------------------
__device__ __nv_bfloat16 g_hh[NTOK * HID],  g_hl[NTOK * HID];
__device__ __nv_bfloat16 g_Wqh[HID * HID],  g_Wql[HID * HID];
__device__ __nv_bfloat16 g_Wkh[HID * HID],  g_Wkl[HID * HID];
__device__ __nv_bfloat16 g_Wvh[HID * HID],  g_Wvl[HID * HID];
__device__ __nv_bfloat16 g_Woh[HID * HID],  g_Wol[HID * HID];
__device__ __nv_bfloat16 g_W1h[2 * HID * HID], g_W1l[2 * HID * HID];
__device__ __nv_bfloat16 g_W2h[2 * HID * HID], g_W2l[2 * HID * HID];
__device__ __nv_bfloat16 g_Qh[NTOK * HID], g_Ql[NTOK * HID];
__device__ __nv_bfloat16 g_Kh[NTOK * HID], g_Kl[NTOK * HID];
__device__ __nv_bfloat16 g_Vh[NTOK * HID], g_Vl[NTOK * HID];
__device__ __nv_bfloat16 g_AOh[NTOK * HID], g_AOl[NTOK * HID];
__device__ __nv_bfloat16 g_X1h[NTOK * HID], g_X1l[NTOK * HID];
__device__ __nv_bfloat16 g_Mh[NTOK * 2 * HID], g_Ml[NTOK * 2 * HID];
__device__ float g_X[NTOK * HID];
__device__ float g_X1[NTOK * HID];
__device__ float g_F[NTOK * HID];
__device__ float g_psum[128 * HID];
__device__ float g_psq[128 * HID];
__device__ float g_scaleC[HID];
__device__ float g_shiftC[HID];

// ------------------- helpers -------------------
__device__ __forceinline__ void mma_bf16(float* c, const uint32_t* a, const uint32_t* b)
{
    asm volatile(
        "mma.sync.aligned.m16n8k16.row.col.f32.bf16.bf16.f32 "
        "{%0,%1,%2,%3}, {%4,%5,%6,%7}, {%8,%9}, {%0,%1,%2,%3};"
        : "+f"(c[0]), "+f"(c[1]), "+f"(c[2]), "+f"(c[3])
        : "r"(a[0]), "r"(a[1]), "r"(a[2]), "r"(a[3]), "r"(b[0]), "r"(b[1]));
}

__device__ __forceinline__ void split_pack(float x, float y, uint32_t& hi, uint32_t& lo)
{
    uint32_t h;
    asm("cvt.rn.bf16x2.f32 %0, %1, %2;" : "=r"(h) : "f"(y), "f"(x));
    float xr = __uint_as_float(h << 16);
    float yr = __uint_as_float(h & 0xffff0000u);
    float xl = x - xr, yl = y - yr;
    uint32_t l;
    asm("cvt.rn.bf16x2.f32 %0, %1, %2;" : "=r"(l) : "f"(yl), "f"(xl));
    hi = h; lo = l;
}

__device__ __forceinline__ uint32_t pack_bf16(float x, float y)
{
    uint32_t h;
    asm("cvt.rn.bf16x2.f32 %0, %1, %2;" : "=r"(h) : "f"(y), "f"(x));
    return h;
}

__device__ __forceinline__ float ex2(float x)
{
    float r;
    asm("ex2.approx.ftz.f32 %0, %1;" : "=f"(r) : "f"(x));
    return r;
}

__device__ __forceinline__ uint32_t scvta(const void* p)
{
    return (uint32_t)__cvta_generic_to_shared(p);
}

__device__ __forceinline__ void ldsm_x4(uint32_t* d, uint32_t addr)
{
    asm volatile("ldmatrix.sync.aligned.m8n8.x4.shared.b16 {%0,%1,%2,%3}, [%4];"
                 : "=r"(d[0]), "=r"(d[1]), "=r"(d[2]), "=r"(d[3]) : "r"(addr));
}

__device__ __forceinline__ void ldsm_x4_t(uint32_t* d, uint32_t addr)
{
    asm volatile("ldmatrix.sync.aligned.m8n8.x4.trans.shared.b16 {%0,%1,%2,%3}, [%4];"
                 : "=r"(d[0]), "=r"(d[1]), "=r"(d[2]), "=r"(d[3]) : "r"(addr));
}

__device__ __forceinline__ void cp_async16(uint32_t dst, const void* src)
{
    asm volatile("cp.async.cg.shared.global [%0], [%1], 16;" :: "r"(dst), "l"(src));
}

__device__ __forceinline__ void cp_commit() { asm volatile("cp.async.commit_group;"); }
__device__ __forceinline__ void cp_wait0()  { asm volatile("cp.async.wait_group 0;"); }

// ------------------- split_all: f32 -> bf16 hi/lo planes (h + 6 weights) ----------
struct SplitJob { const float* src; __nv_bfloat16* hi; __nv_bfloat16* lo; int n4; };
struct SplitJobs { SplitJob j[7]; };

__global__ void split_all(SplitJobs jobs)
{
    SplitJob job = jobs.j[blockIdx.y];
    for (int i = blockIdx.x * blockDim.x + threadIdx.x; i < job.n4;
         i += gridDim.x * blockDim.x) {
        float4 v = *(const float4*)&job.src[(size_t)i * 4];
        uint32_t h01, l01, h23, l23;
        split_pack(v.x, v.y, h01, l01);
        split_pack(v.z, v.w, h23, l23);
        *(uint32_t*)&job.hi[(size_t)i * 4]     = h01;
        *(uint32_t*)&job.hi[(size_t)i * 4 + 2] = h23;
        *(uint32_t*)&job.lo[(size_t)i * 4]     = l01;
        *(uint32_t*)&job.lo[(size_t)i * 4 + 2] = l23;
    }
}

// ------------------- tensor-core GEMM on pre-split planes (BM=64, 128 thr) -------
#define GKP 40
#define GPB (64 * GKP * 2)       // one plane buffer (A or W): 5120 B
#define GBUF (4 * GPB)           // Ah|Al|Wh|Wl = 20480 B
#define GEMM_SMEM (2 * GBUF)     // 40960 B

__device__ __forceinline__ void gemm_stage(
    const __nv_bfloat16* __restrict__ Ahp, const __nv_bfloat16* __restrict__ Alp,
    const __nv_bfloat16* __restrict__ Whp, const __nv_bfloat16* __restrict__ Wlp,
    int i0, int j0, int K, int kk, uint32_t bufb, int tid)
{
    #pragma unroll
    for (int t = 0; t < 4; t++) {
        const __nv_bfloat16* src = (t >= 2) ? Alp : Ahp;
        int idx = tid + ((t & 1) << 7);      // 0..255
        int r = idx >> 2, c8 = (idx & 3) * 8;
        cp_async16(bufb + (uint32_t)((t >= 2) ? GPB : 0) + (uint32_t)((r * GKP + c8) * 2),
                   src + (size_t)(i0 + r) * K + kk + c8);
    }
    #pragma unroll
    for (int t = 0; t < 4; t++) {
        const __nv_bfloat16* src = (t >= 2) ? Wlp : Whp;
        int idx = tid + ((t & 1) << 7);
        int r = idx >> 2, c8 = (idx & 3) * 8;
        cp_async16(bufb + (uint32_t)(2 * GPB) + (uint32_t)((t >= 2) ? GPB : 0)
                        + (uint32_t)((r * GKP + c8) * 2),
                   src + (size_t)(j0 + r) * K + kk + c8);
    }
}

__device__ __forceinline__ void gemm_body(
    const __nv_bfloat16* __restrict__ Ahp, const __nv_bfloat16* __restrict__ Alp,
    const __nv_bfloat16* __restrict__ Whp, const __nv_bfloat16* __restrict__ Wlp,
    const float* __restrict__ bias, float* __restrict__ C,
    __nv_bfloat16* __restrict__ Ch, __nv_bfloat16* __restrict__ Cl,
    int Nout, int K, float scale, int relu, int mode, char* smemraw)
{
    const int tid = threadIdx.x, w = tid >> 5, lane = tid & 31;
    const int qr = lane >> 2, qc2 = (lane & 3) * 2;
    const int i0 = blockIdx.y * 64, j0 = blockIdx.x * 64;
    const int r0 = w * 16;

    float acc[8][4] = {};

    const int arow = r0 + ((lane >> 3) & 1) * 8 + (lane & 7);
    const int acol = (lane >> 4) * 8;
    const int brow = (lane & 7);
    const int bcol = (lane >> 3) * 8;

    const uint32_t smb = scvta(smemraw);
    const int nch = K / 32;

    gemm_stage(Ahp, Alp, Whp, Wlp, i0, j0, K, 0, smb, tid);
    cp_commit(); cp_wait0(); __syncthreads();

    int p = 0;
    for (int c = 0; c < nch; c++) {
        if (c + 1 < nch)
            gemm_stage(Ahp, Alp, Whp, Wlp, i0, j0, K, (c + 1) * 32,
                       smb + (uint32_t)((p ^ 1) * GBUF), tid);
        cp_commit();

        const uint32_t base = smb + (uint32_t)(p * GBUF);
        uint32_t ah[2][4], al[2][4];
        #pragma unroll
        for (int ks = 0; ks < 2; ks++) {
            uint32_t off = (uint32_t)((arow * GKP + ks * 16 + acol) * 2);
            ldsm_x4(ah[ks], base + off);
            ldsm_x4(al[ks], base + GPB + off);
        }
        #pragma unroll
        for (int nt = 0; nt < 8; nt++) {
            uint32_t bh[4], bl[4];
            uint32_t off = (uint32_t)(((nt * 8 + brow) * GKP + bcol) * 2);
            ldsm_x4(bh, base + 2 * GPB + off);
            ldsm_x4(bl, base + 3 * GPB + off);
            mma_bf16(acc[nt], ah[0], bh);
            mma_bf16(acc[nt], al[0], bh);
            mma_bf16(acc[nt], ah[0], bl);
            mma_bf16(acc[nt], ah[1], bh + 2);
            mma_bf16(acc[nt], al[1], bh + 2);
            mma_bf16(acc[nt], ah[1], bl + 2);
        }
        cp_wait0();
        __syncthreads();
        p ^= 1;
    }

    const int ra = i0 + r0 + qr, rb = ra + 8;
    #pragma unroll
    for (int nt = 0; nt < 8; nt++) {
        int j = j0 + nt * 8 + qc2;
        float b0 = bias[j], b1 = bias[j + 1];
        float v00 = (acc[nt][0] + b0) * scale;
        float v01 = (acc[nt][1] + b1) * scale;
        float v10 = (acc[nt][2] + b0) * scale;
        float v11 = (acc[nt][3] + b1) * scale;
        if (relu) {
            v00 = fmaxf(v00, 0.f); v01 = fmaxf(v01, 0.f);
            v10 = fmaxf(v10, 0.f); v11 = fmaxf(v11, 0.f);
        }
        if (mode == 0) {
            *(float2*)&C[(size_t)ra * Nout + j] = make_float2(v00, v01);
            *(float2*)&C[(size_t)rb * Nout + j] = make_float2(v10, v11);
        } else {
            uint32_t h0, l0, h1, l1;
            split_pack(v00, v01, h0, l0);
            split_pack(v10, v11, h1, l1);
            *(uint32_t*)&Ch[(size_t)ra * Nout + j] = h0;
            *(uint32_t*)&Cl[(size_t)ra * Nout + j] = l0;
            *(uint32_t*)&Ch[(size_t)rb * Nout + j] = h1;
            *(uint32_t*)&Cl[(size_t)rb * Nout + j] = l1;
        }
    }
}

__global__ void __launch_bounds__(128, 4)
gemm_plane(const __nv_bfloat16* Ahp, const __nv_bfloat16* Alp,
           const __nv_bfloat16* Whp, const __nv_bfloat16* Wlp,
           const float* bias, float* C, __nv_bfloat16* Ch, __nv_bfloat16* Cl,
           int Nout, int K, float scale, int relu, int mode)
{
    extern __shared__ __align__(16) char smemraw[];
    gemm_body(Ahp, Alp, Whp, Wlp, bias, C, Ch, Cl, Nout, K, scale, relu, mode, smemraw);
}

__global__ void __launch_bounds__(128, 4)
gemm_qkv(const __nv_bfloat16* hh, const __nv_bfloat16* hl,
         const __nv_bfloat16* Wqh, const __nv_bfloat16* Wql, const float* bq,
         __nv_bfloat16* Qh, __nv_bfloat16* Ql,
         const __nv_bfloat16* Wkh, const __nv_bfloat16* Wkl, const float* bk,
         __nv_bfloat16* Kh, __nv_bfloat16* Kl,
         const __nv_bfloat16* Wvh, const __nv_bfloat16* Wvl, const float* bv,
         __nv_bfloat16* Vh, __nv_bfloat16* Vl)
{
    extern __shared__ __align__(16) char smemraw[];
    const __nv_bfloat16 *Wh, *Wl; const float* b; __nv_bfloat16 *Ch, *Cl; float sc;
    if (blockIdx.z == 0)      { Wh = Wqh; Wl = Wql; b = bq; Ch = Qh; Cl = Ql; sc = QK2SCALE; }
    else if (blockIdx.z == 1) { Wh = Wkh; Wl = Wkl; b = bk; Ch = Kh; Cl = Kl; sc = 1.f; }
    else                      { Wh = Wvh; Wl = Wvl; b = bv; Ch = Vh; Cl = Vl; sc = 1.f; }
    gemm_body(hh, hl, Wh, Wl, b, nullptr, Ch, Cl, HID, HID, sc, 0, 1, smemraw);
}

// ------------------- tensor-core flash attention -------------------
// Pure bf16 QK (key-independent errors average in PV; uniform bias cancels in p/l),
// single-term bf16 PV, exact f32 row sums. 2 smem arrays (Kh, Vh), double-buffered.
#define KP 56
#define BUFB (64 * KP * 2)
#define FLASH_SMEM (4 * BUFB)          // 28672 bytes

__global__ void __launch_bounds__(256, 2)
flash_attn_mma(const __nv_bfloat16* __restrict__ Qhg,
               const __nv_bfloat16* __restrict__ Khg,
               const __nv_bfloat16* __restrict__ Vhg,
               const float* __restrict__ Amat,
               __nv_bfloat16* __restrict__ AOh, __nv_bfloat16* __restrict__ AOl)
{
    extern __shared__ __align__(16) char smemraw[];
    __nv_bfloat16* Khs = (__nv_bfloat16*)(smemraw);
    __nv_bfloat16* Vhs = (__nv_bfloat16*)(smemraw + 2 * BUFB);

    const int tid  = threadIdx.x;
    const int w    = tid >> 5;
    const int lane = tid & 31;
    const int qr   = lane >> 2;
    const int qc2  = (lane & 3) * 2;

    const int hh   = blockIdx.y;
    const int row0 = blockIdx.x * 128;
    const int r0   = w * 16;

    const size_t hbase = (size_t)hh * NTOK * HD;

    uint32_t aQh[2][4];
    {
        const size_t ra = hbase + (size_t)(row0 + r0 + qr) * HD;
        const size_t rb = ra + 8 * HD;
        #pragma unroll
        for (int ks = 0; ks < 2; ks++) {
            int cb = ks * 16 + qc2;
            aQh[ks][0] = *(const uint32_t*)&Qhg[ra + cb];
            aQh[ks][1] = *(const uint32_t*)&Qhg[rb + cb];
            aQh[ks][2] = *(const uint32_t*)&Qhg[ra + cb + 8];
            aQh[ks][3] = *(const uint32_t*)&Qhg[rb + cb + 8];
        }
    }

    float oacc[4][4] = {};
    float ls0 = 0.f, ls1 = 0.f;

    const int ga = (row0 + r0 + qr) * NTOK;
    const int gb = (row0 + r0 + qr + 8) * NTOK;

    const uint32_t khb = scvta(Khs);
    const uint32_t vhb = scvta(Vhs);
    const uint32_t koff = (uint32_t)(((lane & 7) * KP + (lane >> 3) * 8) * 2);
    const uint32_t vtoff = (uint32_t)(lane * KP * 2);

    // staging: 2 arrays x 256 chunks; thread copies 2 chunks of array tid>>7
    const int sarr = tid >> 7;
    const int sid0 = tid & 127;
    const char* gsrc = sarr ? (const char*)(Vhg + hbase) : (const char*)(Khg + hbase);
    const uint32_t sdstb = sarr ? vhb : khb;
    uint32_t soff[2];
    #pragma unroll
    for (int t = 0; t < 2; t++) {
        int idx = sid0 + t * 128;
        int r = idx >> 2, c8 = (idx & 3) * 8;
        soff[t] = (uint32_t)((r * KP + c8) * 2);
    }

    #pragma unroll
    for (int t = 0; t < 2; t++)
        cp_async16(sdstb + soff[t], gsrc + (size_t)(sid0 + t * 128) * 16);
    cp_commit();
    cp_wait0();
    __syncthreads();

    int p = 0;
    for (int mt = 0; mt < NTOK / 64; mt++) {
        const int m0 = mt * 64;
        const uint32_t pofs = (uint32_t)p * BUFB;

        if (mt < NTOK / 64 - 1) {
            const char* src = gsrc + (size_t)(mt + 1) * 64 * HD * 2;
            const uint32_t db = sdstb + (pofs ^ BUFB);
            #pragma unroll
            for (int t = 0; t < 2; t++)
                cp_async16(db + soff[t], src + (size_t)(sid0 + t * 128) * 16);
        }
        cp_commit();

        float2 Ar[8], Br[8];
        #pragma unroll
        for (int nt = 0; nt < 8; nt++) {
            int gc = m0 + nt * 8 + qc2;
            Ar[nt] = *(const float2*)&Amat[(size_t)ga + gc];
            Br[nt] = *(const float2*)&Amat[(size_t)gb + gc];
        }

        // ---- S = Q·Kᵀ (pure bf16) ----
        float sacc[8][4];
        #pragma unroll
        for (int nt = 0; nt < 8; nt++) {
            sacc[nt][0] = sacc[nt][1] = sacc[nt][2] = sacc[nt][3] = 0.f;
            uint32_t off = koff + pofs + (uint32_t)(nt * 8 * KP * 2);
            uint32_t bh[4];
            ldsm_x4(bh, khb + off);
            mma_bf16(sacc[nt], aQh[0], bh);
            mma_bf16(sacc[nt], aQh[1], bh + 2);
        }

        // ---- p = exp2(s*A); lane-local row sums (exact f32) ----
        #pragma unroll
        for (int nt = 0; nt < 8; nt++) {
            sacc[nt][0] = ex2(sacc[nt][0] * Ar[nt].x);
            sacc[nt][1] = ex2(sacc[nt][1] * Ar[nt].y);
            sacc[nt][2] = ex2(sacc[nt][2] * Br[nt].x);
            sacc[nt][3] = ex2(sacc[nt][3] * Br[nt].y);
            ls0 += sacc[nt][0] + sacc[nt][1];
            ls1 += sacc[nt][2] + sacc[nt][3];
        }

        // ---- pack P to bf16 ----
        uint32_t ph[4][4];
        #pragma unroll
        for (int kc = 0; kc < 4; kc++) {
            ph[kc][0] = pack_bf16(sacc[2 * kc][0],     sacc[2 * kc][1]);
            ph[kc][1] = pack_bf16(sacc[2 * kc][2],     sacc[2 * kc][3]);
            ph[kc][2] = pack_bf16(sacc[2 * kc + 1][0], sacc[2 * kc + 1][1]);
            ph[kc][3] = pack_bf16(sacc[2 * kc + 1][2], sacc[2 * kc + 1][3]);
        }

        // ---- O += P·V (bf16) ----
        #pragma unroll
        for (int nt = 0; nt < 4; nt++) {
            uint32_t off = vtoff + pofs + (uint32_t)(nt * 16);
            uint32_t bh[8];
            ldsm_x4_t(bh,     vhb + off);
            ldsm_x4_t(bh + 4, vhb + off + 32 * KP * 2);
            #pragma unroll
            for (int kc = 0; kc < 4; kc++)
                mma_bf16(oacc[nt], ph[kc], bh + kc * 2);
        }

        cp_wait0();
        __syncthreads();
        p ^= 1;
    }

    ls0 += __shfl_xor_sync(0xffffffffu, ls0, 1);
    ls0 += __shfl_xor_sync(0xffffffffu, ls0, 2);
    ls1 += __shfl_xor_sync(0xffffffffu, ls1, 1);
    ls1 += __shfl_xor_sync(0xffffffffu, ls1, 2);
    float inv0 = 1.f / ls0, inv1 = 1.f / ls1;

    const size_t ra = hbase + (size_t)(row0 + r0 + qr) * HD;
    const size_t rb = ra + 8 * HD;
    #pragma unroll
    for (int nt = 0; nt < 4; nt++) {
        int c = nt * 8 + qc2;
        uint32_t h0, l0, h1, l1;
        split_pack(oacc[nt][0] * inv0, oacc[nt][1] * inv0, h0, l0);
        split_pack(oacc[nt][2] * inv1, oacc[nt][3] * inv1, h1, l1);
        *(uint32_t*)&AOh[ra + c] = h0;
        *(uint32_t*)&AOl[ra + c] = l0;
        *(uint32_t*)&AOh[rb + c] = h1;
        *(uint32_t*)&AOl[rb + c] = l1;
    }
}

// ------------------- batchnorm helpers -------------------
__global__ void col_partial(const float* __restrict__ a, const float* __restrict__ b,
                            float* __restrict__ psum, float* __restrict__ psq)
{
    __shared__ float4 ssum[4][64], ssq[4][64];
    int q = threadIdx.x & 63;
    int rg = threadIdx.x >> 6;
    int c4 = q * 4;
    int blk = blockIdx.x;
    float4 s = {0.f, 0.f, 0.f, 0.f}, sq = {0.f, 0.f, 0.f, 0.f};
    #pragma unroll
    for (int k = 0; k < 8; k++) {
        int r = rg * 8 + k;
        size_t i = (size_t)(blk * 32 + r) * HID + c4;
        float4 av = *(const float4*)&a[i];
        float4 bv = *(const float4*)&b[i];
        float vx = av.x + bv.x, vy = av.y + bv.y, vz = av.z + bv.z, vw = av.w + bv.w;
        s.x += vx; s.y += vy; s.z += vz; s.w += vw;
        sq.x += vx * vx; sq.y += vy * vy; sq.z += vz * vz; sq.w += vw * vw;
    }
    ssum[rg][q] = s; ssq[rg][q] = sq;
    __syncthreads();
    if (rg == 0) {
        #pragma unroll
        for (int k = 1; k < 4; k++) {
            float4 t1 = ssum[k][q], t2 = ssq[k][q];
            s.x += t1.x; s.y += t1.y; s.z += t1.z; s.w += t1.w;
            sq.x += t2.x; sq.y += t2.y; sq.z += t2.z; sq.w += t2.w;
        }
        *(float4*)&psum[blk * HID + c4] = s;
        *(float4*)&psq[blk * HID + c4]  = sq;
    }
}

__global__ void col_finalize(const float* __restrict__ psum, const float* __restrict__ psq,
                             const float* __restrict__ g, const float* __restrict__ be,
                             float* __restrict__ scaleC, float* __restrict__ shiftC)
{
    int j = threadIdx.x;
    float s = 0.f, q = 0.f;
    #pragma unroll
    for (int b = 0; b < 128; b++) { s += psum[b * HID + j]; q += psq[b * HID + j]; }
    float m = s * (1.f / NTOK);
    float var = q * (1.f / NTOK) - m * m;
    var = fmaxf(var, 0.f);
    float sc = rsqrtf(var + EPSBN) * g[j];
    scaleC[j] = sc;
    shiftC[j] = be[j] - m * sc;
}

__global__ void bn_apply(const float* __restrict__ a, const float* __restrict__ b,
                         const float* __restrict__ scaleC, const float* __restrict__ shiftC,
                         float* __restrict__ out,
                         __nv_bfloat16* __restrict__ oh, __nv_bfloat16* __restrict__ ol,
                         int emit_planes)
{
    int idx = (blockIdx.x * blockDim.x + threadIdx.x) * 4;
    int j = idx & (HID - 1);
    float4 av = *(const float4*)&a[idx];
    float4 bv = *(const float4*)&b[idx];
    float4 sc = *(const float4*)&scaleC[j];
    float4 sh = *(const float4*)&shiftC[j];
    float4 ov;
    ov.x = (av.x + bv.x) * sc.x + sh.x;
    ov.y = (av.y + bv.y) * sc.y + sh.y;
    ov.z = (av.z + bv.z) * sc.z + sh.z;
    ov.w = (av.w + bv.w) * sc.w + sh.w;
    *(float4*)&out[idx] = ov;
    if (emit_planes) {
        uint32_t h01, l01, h23, l23;
        split_pack(ov.x, ov.y, h01, l01);
        split_pack(ov.z, ov.w, h23, l23);
        *(uint32_t*)&oh[idx]     = h01;
        *(uint32_t*)&oh[idx + 2] = h23;
        *(uint32_t*)&ol[idx]     = l01;
        *(uint32_t*)&ol[idx + 2] = l23;
    }
}

// ------------------- launch -------------------
extern "C" void kernel_launch(void* const* d_in, const int* in_sizes, int n_in,
                              void* d_out, int out_size)
{
    const float* A   = (const float*)d_in[0];
    const float* h   = (const float*)d_in[1];
    const float* Wq  = (const float*)d_in[2];
    const float* bq  = (const float*)d_in[3];
    const float* Wk  = (const float*)d_in[4];
    const float* bk  = (const float*)d_in[5];
    const float* Wv  = (const float*)d_in[6];
    const float* bv  = (const float*)d_in[7];
    const float* Wo  = (const float*)d_in[8];
    const float* bo  = (const float*)d_in[9];
    const float* W1  = (const float*)d_in[10];
    const float* c1  = (const float*)d_in[11];
    const float* W2  = (const float*)d_in[12];
    const float* c2  = (const float*)d_in[13];
    const float* g1  = (const float*)d_in[14];
    const float* be1 = (const float*)d_in[15];
    const float* g2  = (const float*)d_in[16];
    const float* be2 = (const float*)d_in[17];
    float* out = (float*)d_out;

    __nv_bfloat16 *hh, *hl, *Wqh, *Wql, *Wkh, *Wkl, *Wvh, *Wvl, *Woh, *Wol,
                  *W1h, *W1l, *W2h, *W2l,
                  *Qh, *Ql, *Kh, *Kl, *Vh, *Vl, *AOh, *AOl, *X1h, *X1l, *Mh, *Ml;
    float *X, *X1, *F, *psum, *psq, *scaleC, *shiftC;
    cudaGetSymbolAddress((void**)&hh,  g_hh);  cudaGetSymbolAddress((void**)&hl,  g_hl);
    cudaGetSymbolAddress((void**)&Wqh, g_Wqh); cudaGetSymbolAddress((void**)&Wql, g_Wql);
    cudaGetSymbolAddress((void**)&Wkh, g_Wkh); cudaGetSymbolAddress((void**)&Wkl, g_Wkl);
    cudaGetSymbolAddress((void**)&Wvh, g_Wvh); cudaGetSymbolAddress((void**)&Wvl, g_Wvl);
    cudaGetSymbolAddress((void**)&Woh, g_Woh); cudaGetSymbolAddress((void**)&Wol, g_Wol);
    cudaGetSymbolAddress((void**)&W1h, g_W1h); cudaGetSymbolAddress((void**)&W1l, g_W1l);
    cudaGetSymbolAddress((void**)&W2h, g_W2h); cudaGetSymbolAddress((void**)&W2l, g_W2l);
    cudaGetSymbolAddress((void**)&Qh, g_Qh);   cudaGetSymbolAddress((void**)&Ql, g_Ql);
    cudaGetSymbolAddress((void**)&Kh, g_Kh);   cudaGetSymbolAddress((void**)&Kl, g_Kl);
    cudaGetSymbolAddress((void**)&Vh, g_Vh);   cudaGetSymbolAddress((void**)&Vl, g_Vl);
    cudaGetSymbolAddress((void**)&AOh, g_AOh); cudaGetSymbolAddress((void**)&AOl, g_AOl);
    cudaGetSymbolAddress((void**)&X1h, g_X1h); cudaGetSymbolAddress((void**)&X1l, g_X1l);
    cudaGetSymbolAddress((void**)&Mh, g_Mh);   cudaGetSymbolAddress((void**)&Ml, g_Ml);
    cudaGetSymbolAddress((void**)&X,   g_X);
    cudaGetSymbolAddress((void**)&X1,  g_X1);
    cudaGetSymbolAddress((void**)&F,   g_F);
    cudaGetSymbolAddress((void**)&psum,   g_psum);
    cudaGetSymbolAddress((void**)&psq,    g_psq);
    cudaGetSymbolAddress((void**)&scaleC, g_scaleC);
    cudaGetSymbolAddress((void**)&shiftC, g_shiftC);

    cudaFuncSetAttribute(flash_attn_mma,
                         cudaFuncAttributeMaxDynamicSharedMemorySize, FLASH_SMEM);
    cudaFuncSetAttribute(gemm_plane,
                         cudaFuncAttributeMaxDynamicSharedMemorySize, GEMM_SMEM);
    cudaFuncSetAttribute(gemm_qkv,
                         cudaFuncAttributeMaxDynamicSharedMemorySize, GEMM_SMEM);

    dim3 gqkv(HID / 64, NTOK / 64, 3);      // 4 x 64 x 3
    dim3 gproj(HID / 64, NTOK / 64);        // 4 x 64
    dim3 gffn1(2 * HID / 64, NTOK / 64);    // 8 x 64
    dim3 gattn(NTOK / 128, NHEADS);         // 32 x 8

    SplitJobs jobs;
    jobs.j[0] = { h,  hh,  hl,  NTOK * HID / 4 };
    jobs.j[1] = { Wq, Wqh, Wql, HID * HID / 4 };
    jobs.j[2] = { Wk, Wkh, Wkl, HID * HID / 4 };
    jobs.j[3] = { Wv, Wvh, Wvl, HID * HID / 4 };
    jobs.j[4] = { Wo, Woh, Wol, HID * HID / 4 };
    jobs.j[5] = { W1, W1h, W1l, 2 * HID * HID / 4 };
    jobs.j[6] = { W2, W2h, W2l, 2 * HID * HID / 4 };
    split_all<<<dim3(64, 7), 256>>>(jobs);

    gemm_qkv<<<gqkv, 128, GEMM_SMEM>>>(hh, hl, Wqh, Wql, bq, Qh, Ql,
                                       Wkh, Wkl, bk, Kh, Kl,
                                       Wvh, Wvl, bv, Vh, Vl);

    flash_attn_mma<<<gattn, 256, FLASH_SMEM>>>(Qh, Kh, Vh, A, AOh, AOl);

    gemm_plane<<<gproj, 128, GEMM_SMEM>>>(AOh, AOl, Woh, Wol, bo,
                                          X, nullptr, nullptr, HID, HID, 1.f, 0, 0);

    col_partial<<<128, 256>>>(X, h, psum, psq);
    col_finalize<<<1, HID>>>(psum, psq, g1, be1, scaleC, shiftC);
    bn_apply<<<NTOK * HID / 1024, 256>>>(X, h, scaleC, shiftC, X1, X1h, X1l, 1);

    gemm_plane<<<gffn1, 128, GEMM_SMEM>>>(X1h, X1l, W1h, W1l, c1,
                                          nullptr, Mh, Ml, 2 * HID, HID, 1.f, 1, 1);
    gemm_plane<<<gproj, 128, GEMM_SMEM>>>(Mh, Ml, W2h, W2l, c2,
                                          F, nullptr, nullptr, HID, 2 * HID, 1.f, 0, 0);

    col_partial<<<128, 256>>>(X1, F, psum, psq);
    col_finalize<<<1, HID>>>(psum, psq, g2, be2, scaleC, shiftC);
    bn_apply<<<NTOK * HID / 1024, 256>>>(X1, F, scaleC, shiftC, out, nullptr, nullptr, 0);
}

// round 14
// speedup vs baseline: 1.4775x; 1.0440x over previous
#include <cuda_runtime.h>
#include <cuda_bf16.h>
#include <cstdint>

#define NTOK 4096
#define HID 256
#define NHEADS 8
#define HD 32
#define EPSBN 1e-5f
#define QSCALE 0.17677669529663687f       // 1/sqrt(32)
#define LOG2E  1.4426950408889634f
#define QK2SCALE (QSCALE * LOG2E)         // folded so softmax uses exp2

// ------------------- scratch (device globals; no allocation) -------------------
__device__ __nv_bfloat16 g_hh[NTOK * HID],  g_hl[NTOK * HID];
__device__ __nv_bfloat16 g_Wqh[HID * HID],  g_Wql[HID * HID];
__device__ __nv_bfloat16 g_Wkh[HID * HID],  g_Wkl[HID * HID];
__device__ __nv_bfloat16 g_Wvh[HID * HID],  g_Wvl[HID * HID];
__device__ __nv_bfloat16 g_Woh[HID * HID],  g_Wol[HID * HID];
__device__ __nv_bfloat16 g_W1h[2 * HID * HID], g_W1l[2 * HID * HID];
__device__ __nv_bfloat16 g_W2h[2 * HID * HID], g_W2l[2 * HID * HID];
__device__ __nv_bfloat16 g_Qh[NTOK * HID];
__device__ __nv_bfloat16 g_Kh[NTOK * HID];
__device__ __nv_bfloat16 g_Vh[NTOK * HID];
__device__ __nv_bfloat16 g_AOh[NTOK * HID], g_AOl[NTOK * HID];
__device__ __nv_bfloat16 g_X1h[NTOK * HID], g_X1l[NTOK * HID];
__device__ __nv_bfloat16 g_Mh[NTOK * 2 * HID], g_Ml[NTOK * 2 * HID];
__device__ float g_X[NTOK * HID];       // X' = O-proj + h (residual included)
__device__ float g_X1[NTOK * HID];
__device__ float g_X2[NTOK * HID];      // X2' = X1 + FFN2 (residual included)
__device__ float g_psum[64 * HID];
__device__ float g_psq[64 * HID];
__device__ float g_scaleC[HID];
__device__ float g_shiftC[HID];

// ------------------- helpers -------------------
__device__ __forceinline__ void mma_bf16(float* c, const uint32_t* a, const uint32_t* b)
{
    asm volatile(
        "mma.sync.aligned.m16n8k16.row.col.f32.bf16.bf16.f32 "
        "{%0,%1,%2,%3}, {%4,%5,%6,%7}, {%8,%9}, {%0,%1,%2,%3};"
        : "+f"(c[0]), "+f"(c[1]), "+f"(c[2]), "+f"(c[3])
        : "r"(a[0]), "r"(a[1]), "r"(a[2]), "r"(a[3]), "r"(b[0]), "r"(b[1]));
}

__device__ __forceinline__ void split_pack(float x, float y, uint32_t& hi, uint32_t& lo)
{
    uint32_t h;
    asm("cvt.rn.bf16x2.f32 %0, %1, %2;" : "=r"(h) : "f"(y), "f"(x));
    float xr = __uint_as_float(h << 16);
    float yr = __uint_as_float(h & 0xffff0000u);
    float xl = x - xr, yl = y - yr;
    uint32_t l;
    asm("cvt.rn.bf16x2.f32 %0, %1, %2;" : "=r"(l) : "f"(yl), "f"(xl));
    hi = h; lo = l;
}

__device__ __forceinline__ uint32_t pack_bf16(float x, float y)
{
    uint32_t h;
    asm("cvt.rn.bf16x2.f32 %0, %1, %2;" : "=r"(h) : "f"(y), "f"(x));
    return h;
}

__device__ __forceinline__ float ex2(float x)
{
    float r;
    asm("ex2.approx.ftz.f32 %0, %1;" : "=f"(r) : "f"(x));
    return r;
}

__device__ __forceinline__ uint32_t scvta(const void* p)
{
    return (uint32_t)__cvta_generic_to_shared(p);
}

__device__ __forceinline__ void ldsm_x4(uint32_t* d, uint32_t addr)
{
    asm volatile("ldmatrix.sync.aligned.m8n8.x4.shared.b16 {%0,%1,%2,%3}, [%4];"
                 : "=r"(d[0]), "=r"(d[1]), "=r"(d[2]), "=r"(d[3]) : "r"(addr));
}

__device__ __forceinline__ void ldsm_x4_t(uint32_t* d, uint32_t addr)
{
    asm volatile("ldmatrix.sync.aligned.m8n8.x4.trans.shared.b16 {%0,%1,%2,%3}, [%4];"
                 : "=r"(d[0]), "=r"(d[1]), "=r"(d[2]), "=r"(d[3]) : "r"(addr));
}

__device__ __forceinline__ void cp_async16(uint32_t dst, const void* src)
{
    asm volatile("cp.async.cg.shared.global [%0], [%1], 16;" :: "r"(dst), "l"(src));
}

__device__ __forceinline__ void cp_commit() { asm volatile("cp.async.commit_group;"); }
__device__ __forceinline__ void cp_wait0()  { asm volatile("cp.async.wait_group 0;"); }

// ------------------- split_all: f32 -> bf16 hi/lo planes (h + 6 weights) ----------
struct SplitJob { const float* src; __nv_bfloat16* hi; __nv_bfloat16* lo; int n4; };
struct SplitJobs { SplitJob j[7]; };

__global__ void split_all(SplitJobs jobs)
{
    SplitJob job = jobs.j[blockIdx.y];
    for (int i = blockIdx.x * blockDim.x + threadIdx.x; i < job.n4;
         i += gridDim.x * blockDim.x) {
        float4 v = *(const float4*)&job.src[(size_t)i * 4];
        uint32_t h01, l01, h23, l23;
        split_pack(v.x, v.y, h01, l01);
        split_pack(v.z, v.w, h23, l23);
        *(uint32_t*)&job.hi[(size_t)i * 4]     = h01;
        *(uint32_t*)&job.hi[(size_t)i * 4 + 2] = h23;
        *(uint32_t*)&job.lo[(size_t)i * 4]     = l01;
        *(uint32_t*)&job.lo[(size_t)i * 4 + 2] = l23;
    }
}

// ------------------- tensor-core GEMM on pre-split planes (BM=64, 128 thr) -------
// mode 0: C = acc+bias (f32). mode 1: planes Ch/Cl (opt relu). mode 2: C = acc+bias+Rin
//   (residual) AND per-(row-block, col) BN partial stats into psum/psq (no atomics).
#define GKP 40
#define GPB (64 * GKP * 2)
#define GBUF (4 * GPB)
#define GEMM_SMEM (2 * GBUF)     // 40960 B (also reused for epilogue reduce)

__device__ __forceinline__ void gemm_stage(
    const __nv_bfloat16* __restrict__ Ahp, const __nv_bfloat16* __restrict__ Alp,
    const __nv_bfloat16* __restrict__ Whp, const __nv_bfloat16* __restrict__ Wlp,
    int i0, int j0, int K, int kk, uint32_t bufb, int tid)
{
    #pragma unroll
    for (int t = 0; t < 4; t++) {
        const __nv_bfloat16* src = (t >= 2) ? Alp : Ahp;
        int idx = tid + ((t & 1) << 7);
        int r = idx >> 2, c8 = (idx & 3) * 8;
        cp_async16(bufb + (uint32_t)((t >= 2) ? GPB : 0) + (uint32_t)((r * GKP + c8) * 2),
                   src + (size_t)(i0 + r) * K + kk + c8);
    }
    #pragma unroll
    for (int t = 0; t < 4; t++) {
        const __nv_bfloat16* src = (t >= 2) ? Wlp : Whp;
        int idx = tid + ((t & 1) << 7);
        int r = idx >> 2, c8 = (idx & 3) * 8;
        cp_async16(bufb + (uint32_t)(2 * GPB) + (uint32_t)((t >= 2) ? GPB : 0)
                        + (uint32_t)((r * GKP + c8) * 2),
                   src + (size_t)(j0 + r) * K + kk + c8);
    }
}

__device__ __forceinline__ void gemm_body(
    const __nv_bfloat16* __restrict__ Ahp, const __nv_bfloat16* __restrict__ Alp,
    const __nv_bfloat16* __restrict__ Whp, const __nv_bfloat16* __restrict__ Wlp,
    const float* __restrict__ bias, float* __restrict__ C,
    __nv_bfloat16* __restrict__ Ch, __nv_bfloat16* __restrict__ Cl,
    const float* __restrict__ Rin, float* __restrict__ psum, float* __restrict__ psq,
    int Nout, int K, float scale, int relu, int mode, char* smemraw)
{
    const int tid = threadIdx.x, w = tid >> 5, lane = tid & 31;
    const int qr = lane >> 2, qc2 = (lane & 3) * 2;
    const int i0 = blockIdx.y * 64, j0 = blockIdx.x * 64;
    const int r0 = w * 16;

    float acc[8][4] = {};

    const int arow = r0 + ((lane >> 3) & 1) * 8 + (lane & 7);
    const int acol = (lane >> 4) * 8;
    const int brow = (lane & 7);
    const int bcol = (lane >> 3) * 8;

    const uint32_t smb = scvta(smemraw);
    const int nch = K / 32;

    gemm_stage(Ahp, Alp, Whp, Wlp, i0, j0, K, 0, smb, tid);
    cp_commit(); cp_wait0(); __syncthreads();

    int p = 0;
    for (int c = 0; c < nch; c++) {
        if (c + 1 < nch)
            gemm_stage(Ahp, Alp, Whp, Wlp, i0, j0, K, (c + 1) * 32,
                       smb + (uint32_t)((p ^ 1) * GBUF), tid);
        cp_commit();

        const uint32_t base = smb + (uint32_t)(p * GBUF);
        uint32_t ah[2][4], al[2][4];
        #pragma unroll
        for (int ks = 0; ks < 2; ks++) {
            uint32_t off = (uint32_t)((arow * GKP + ks * 16 + acol) * 2);
            ldsm_x4(ah[ks], base + off);
            ldsm_x4(al[ks], base + GPB + off);
        }
        #pragma unroll
        for (int nt = 0; nt < 8; nt++) {
            uint32_t bh[4], bl[4];
            uint32_t off = (uint32_t)(((nt * 8 + brow) * GKP + bcol) * 2);
            ldsm_x4(bh, base + 2 * GPB + off);
            ldsm_x4(bl, base + 3 * GPB + off);
            mma_bf16(acc[nt], ah[0], bh);
            mma_bf16(acc[nt], al[0], bh);
            mma_bf16(acc[nt], ah[0], bl);
            mma_bf16(acc[nt], ah[1], bh + 2);
            mma_bf16(acc[nt], al[1], bh + 2);
            mma_bf16(acc[nt], ah[1], bl + 2);
        }
        cp_wait0();
        __syncthreads();
        p ^= 1;
    }

    const int ra = i0 + r0 + qr, rb = ra + 8;

    if (mode != 2) {
        #pragma unroll
        for (int nt = 0; nt < 8; nt++) {
            int j = j0 + nt * 8 + qc2;
            float b0 = bias[j], b1 = bias[j + 1];
            float v00 = (acc[nt][0] + b0) * scale;
            float v01 = (acc[nt][1] + b1) * scale;
            float v10 = (acc[nt][2] + b0) * scale;
            float v11 = (acc[nt][3] + b1) * scale;
            if (relu) {
                v00 = fmaxf(v00, 0.f); v01 = fmaxf(v01, 0.f);
                v10 = fmaxf(v10, 0.f); v11 = fmaxf(v11, 0.f);
            }
            if (mode == 0) {
                *(float2*)&C[(size_t)ra * Nout + j] = make_float2(v00, v01);
                *(float2*)&C[(size_t)rb * Nout + j] = make_float2(v10, v11);
            } else {
                uint32_t h0, l0, h1, l1;
                split_pack(v00, v01, h0, l0);
                split_pack(v10, v11, h1, l1);
                *(uint32_t*)&Ch[(size_t)ra * Nout + j] = h0;
                *(uint32_t*)&Cl[(size_t)ra * Nout + j] = l0;
                *(uint32_t*)&Ch[(size_t)rb * Nout + j] = h1;
                *(uint32_t*)&Cl[(size_t)rb * Nout + j] = l1;
            }
        }
    } else {
        // mode 2: residual add + store + BN column partial stats (this row block)
        float cs[8][2], cq[8][2];   // per-thread column sums over its 2 rows
        #pragma unroll
        for (int nt = 0; nt < 8; nt++) {
            int j = j0 + nt * 8 + qc2;
            float b0 = bias[j], b1 = bias[j + 1];
            float2 r0v = *(const float2*)&Rin[(size_t)ra * Nout + j];
            float2 r1v = *(const float2*)&Rin[(size_t)rb * Nout + j];
            float x00 = acc[nt][0] + b0 + r0v.x;
            float x01 = acc[nt][1] + b1 + r0v.y;
            float x10 = acc[nt][2] + b0 + r1v.x;
            float x11 = acc[nt][3] + b1 + r1v.y;
            *(float2*)&C[(size_t)ra * Nout + j] = make_float2(x00, x01);
            *(float2*)&C[(size_t)rb * Nout + j] = make_float2(x10, x11);
            cs[nt][0] = x00 + x10;
            cs[nt][1] = x01 + x11;
            cq[nt][0] = x00 * x00 + x10 * x10;
            cq[nt][1] = x01 * x01 + x11 * x11;
        }
        // warp reduce over qr (lanes differing in bits 2..4 share columns)
        #pragma unroll
        for (int m = 4; m <= 16; m <<= 1) {
            #pragma unroll
            for (int nt = 0; nt < 8; nt++) {
                cs[nt][0] += __shfl_xor_sync(0xffffffffu, cs[nt][0], m);
                cs[nt][1] += __shfl_xor_sync(0xffffffffu, cs[nt][1], m);
                cq[nt][0] += __shfl_xor_sync(0xffffffffu, cq[nt][0], m);
                cq[nt][1] += __shfl_xor_sync(0xffffffffu, cq[nt][1], m);
            }
        }
        // cross-warp via smem (staging buffers are dead now; sync already passed)
        float* sred = (float*)smemraw;             // [4][64]
        float* qred = (float*)(smemraw + 4 * 64 * 4);
        if (lane < 4) {
            #pragma unroll
            for (int nt = 0; nt < 8; nt++) {
                int jj = nt * 8 + (lane & 3) * 2;
                sred[w * 64 + jj]     = cs[nt][0];
                sred[w * 64 + jj + 1] = cs[nt][1];
                qred[w * 64 + jj]     = cq[nt][0];
                qred[w * 64 + jj + 1] = cq[nt][1];
            }
        }
        __syncthreads();
        if (tid < 64) {
            float s = sred[tid] + sred[64 + tid] + sred[128 + tid] + sred[192 + tid];
            psum[(size_t)blockIdx.y * HID + j0 + tid] = s;
        } else if (tid < 128) {
            int t = tid - 64;
            float q = qred[t] + qred[64 + t] + qred[128 + t] + qred[192 + t];
            psq[(size_t)blockIdx.y * HID + j0 + t] = q;
        }
    }
}

__global__ void __launch_bounds__(128, 4)
gemm_plane(const __nv_bfloat16* Ahp, const __nv_bfloat16* Alp,
           const __nv_bfloat16* Whp, const __nv_bfloat16* Wlp,
           const float* bias, float* C, __nv_bfloat16* Ch, __nv_bfloat16* Cl,
           const float* Rin, float* psum, float* psq,
           int Nout, int K, float scale, int relu, int mode)
{
    extern __shared__ __align__(16) char smemraw[];
    gemm_body(Ahp, Alp, Whp, Wlp, bias, C, Ch, Cl, Rin, psum, psq,
              Nout, K, scale, relu, mode, smemraw);
}

__global__ void __launch_bounds__(128, 4)
gemm_qkv(const __nv_bfloat16* hh, const __nv_bfloat16* hl,
         const __nv_bfloat16* Wqh, const __nv_bfloat16* Wql, const float* bq,
         __nv_bfloat16* Qh,
         const __nv_bfloat16* Wkh, const __nv_bfloat16* Wkl, const float* bk,
         __nv_bfloat16* Kh,
         const __nv_bfloat16* Wvh, const __nv_bfloat16* Wvl, const float* bv,
         __nv_bfloat16* Vh)
{
    extern __shared__ __align__(16) char smemraw[];
    const __nv_bfloat16 *Wh, *Wl; const float* b; __nv_bfloat16* Ch; float sc;
    if (blockIdx.z == 0)      { Wh = Wqh; Wl = Wql; b = bq; Ch = Qh; sc = QK2SCALE; }
    else if (blockIdx.z == 1) { Wh = Wkh; Wl = Wkl; b = bk; Ch = Kh; sc = 1.f; }
    else                      { Wh = Wvh; Wl = Wvl; b = bv; Ch = Vh; sc = 1.f; }
    // mode 3 (local): plain bf16 output (hi only) — reuse mode 1 path w/ Cl=scratch
    // simpler: write planes but Cl unused? flash only reads hi. Use mode 1 with Cl=Ch?
    // Safe: mode 1 needs Cl; pass Ch for both is wrong. Use small inline epilogue via mode 4:
    gemm_body(hh, hl, Wh, Wl, b, nullptr, Ch, nullptr, nullptr, nullptr, nullptr,
              HID, HID, sc, 0, 4, smemraw);
}

// mode 4 epilogue (bf16 hi only) is handled inside gemm_body? No — add it:
// (Implemented by specializing: mode==4 falls into the mode!=2 branch with mode==1
//  but Cl==nullptr guard. To keep one body, we patch the branch below.)
// NOTE: gemm_body above: for mode==4 we need hi-only stores. Handled in the
// mode!=2 branch: mode==0 -> f32; else planes. For mode 4, Cl is nullptr, so we
// must not store lo. The branch below re-checks Cl.

// ------------------- tensor-core flash attention (unchanged from R13) -------------
#define KP 56
#define BUFB (64 * KP * 2)
#define FLASH_SMEM (4 * BUFB)

__global__ void __launch_bounds__(256, 2)
flash_attn_mma(const __nv_bfloat16* __restrict__ Qhg,
               const __nv_bfloat16* __restrict__ Khg,
               const __nv_bfloat16* __restrict__ Vhg,
               const float* __restrict__ Amat,
               __nv_bfloat16* __restrict__ AOh, __nv_bfloat16* __restrict__ AOl)
{
    extern __shared__ __align__(16) char smemraw[];
    __nv_bfloat16* Khs = (__nv_bfloat16*)(smemraw);
    __nv_bfloat16* Vhs = (__nv_bfloat16*)(smemraw + 2 * BUFB);

    const int tid  = threadIdx.x;
    const int w    = tid >> 5;
    const int lane = tid & 31;
    const int qr   = lane >> 2;
    const int qc2  = (lane & 3) * 2;

    const int hh   = blockIdx.y;
    const int row0 = blockIdx.x * 128;
    const int r0   = w * 16;

    const size_t hbase = (size_t)hh * NTOK * HD;

    uint32_t aQh[2][4];
    {
        const size_t ra = hbase + (size_t)(row0 + r0 + qr) * HD;
        const size_t rb = ra + 8 * HD;
        #pragma unroll
        for (int ks = 0; ks < 2; ks++) {
            int cb = ks * 16 + qc2;
            aQh[ks][0] = *(const uint32_t*)&Qhg[ra + cb];
            aQh[ks][1] = *(const uint32_t*)&Qhg[rb + cb];
            aQh[ks][2] = *(const uint32_t*)&Qhg[ra + cb + 8];
            aQh[ks][3] = *(const uint32_t*)&Qhg[rb + cb + 8];
        }
    }

    float oacc[4][4] = {};
    float ls0 = 0.f, ls1 = 0.f;

    const int ga = (row0 + r0 + qr) * NTOK;
    const int gb = (row0 + r0 + qr + 8) * NTOK;

    const uint32_t khb = scvta(Khs);
    const uint32_t vhb = scvta(Vhs);
    const uint32_t koff = (uint32_t)(((lane & 7) * KP + (lane >> 3) * 8) * 2);
    const uint32_t vtoff = (uint32_t)(lane * KP * 2);

    const int sarr = tid >> 7;
    const int sid0 = tid & 127;
    const char* gsrc = sarr ? (const char*)(Vhg + hbase) : (const char*)(Khg + hbase);
    const uint32_t sdstb = sarr ? vhb : khb;
    uint32_t soff[2];
    #pragma unroll
    for (int t = 0; t < 2; t++) {
        int idx = sid0 + t * 128;
        int r = idx >> 2, c8 = (idx & 3) * 8;
        soff[t] = (uint32_t)((r * KP + c8) * 2);
    }

    #pragma unroll
    for (int t = 0; t < 2; t++)
        cp_async16(sdstb + soff[t], gsrc + (size_t)(sid0 + t * 128) * 16);
    cp_commit();
    cp_wait0();
    __syncthreads();

    int p = 0;
    for (int mt = 0; mt < NTOK / 64; mt++) {
        const int m0 = mt * 64;
        const uint32_t pofs = (uint32_t)p * BUFB;

        if (mt < NTOK / 64 - 1) {
            const char* src = gsrc + (size_t)(mt + 1) * 64 * HD * 2;
            const uint32_t db = sdstb + (pofs ^ BUFB);
            #pragma unroll
            for (int t = 0; t < 2; t++)
                cp_async16(db + soff[t], src + (size_t)(sid0 + t * 128) * 16);
        }
        cp_commit();

        float2 Ar[8], Br[8];
        #pragma unroll
        for (int nt = 0; nt < 8; nt++) {
            int gc = m0 + nt * 8 + qc2;
            Ar[nt] = *(const float2*)&Amat[(size_t)ga + gc];
            Br[nt] = *(const float2*)&Amat[(size_t)gb + gc];
        }

        float sacc[8][4];
        #pragma unroll
        for (int nt = 0; nt < 8; nt++) {
            sacc[nt][0] = sacc[nt][1] = sacc[nt][2] = sacc[nt][3] = 0.f;
            uint32_t off = koff + pofs + (uint32_t)(nt * 8 * KP * 2);
            uint32_t bh[4];
            ldsm_x4(bh, khb + off);
            mma_bf16(sacc[nt], aQh[0], bh);
            mma_bf16(sacc[nt], aQh[1], bh + 2);
        }

        #pragma unroll
        for (int nt = 0; nt < 8; nt++) {
            sacc[nt][0] = ex2(sacc[nt][0] * Ar[nt].x);
            sacc[nt][1] = ex2(sacc[nt][1] * Ar[nt].y);
            sacc[nt][2] = ex2(sacc[nt][2] * Br[nt].x);
            sacc[nt][3] = ex2(sacc[nt][3] * Br[nt].y);
            ls0 += sacc[nt][0] + sacc[nt][1];
            ls1 += sacc[nt][2] + sacc[nt][3];
        }

        uint32_t ph[4][4];
        #pragma unroll
        for (int kc = 0; kc < 4; kc++) {
            ph[kc][0] = pack_bf16(sacc[2 * kc][0],     sacc[2 * kc][1]);
            ph[kc][1] = pack_bf16(sacc[2 * kc][2],     sacc[2 * kc][3]);
            ph[kc][2] = pack_bf16(sacc[2 * kc + 1][0], sacc[2 * kc + 1][1]);
            ph[kc][3] = pack_bf16(sacc[2 * kc + 1][2], sacc[2 * kc + 1][3]);
        }

        #pragma unroll
        for (int nt = 0; nt < 4; nt++) {
            uint32_t off = vtoff + pofs + (uint32_t)(nt * 16);
            uint32_t bh[8];
            ldsm_x4_t(bh,     vhb + off);
            ldsm_x4_t(bh + 4, vhb + off + 32 * KP * 2);
            #pragma unroll
            for (int kc = 0; kc < 4; kc++)
                mma_bf16(oacc[nt], ph[kc], bh + kc * 2);
        }

        cp_wait0();
        __syncthreads();
        p ^= 1;
    }

    ls0 += __shfl_xor_sync(0xffffffffu, ls0, 1);
    ls0 += __shfl_xor_sync(0xffffffffu, ls0, 2);
    ls1 += __shfl_xor_sync(0xffffffffu, ls1, 1);
    ls1 += __shfl_xor_sync(0xffffffffu, ls1, 2);
    float inv0 = 1.f / ls0, inv1 = 1.f / ls1;

    const size_t ra = hbase + (size_t)(row0 + r0 + qr) * HD;
    const size_t rb = ra + 8 * HD;
    #pragma unroll
    for (int nt = 0; nt < 4; nt++) {
        int c = nt * 8 + qc2;
        uint32_t h0, l0, h1, l1;
        split_pack(oacc[nt][0] * inv0, oacc[nt][1] * inv0, h0, l0);
        split_pack(oacc[nt][2] * inv1, oacc[nt][3] * inv1, h1, l1);
        *(uint32_t*)&AOh[ra + c] = h0;
        *(uint32_t*)&AOl[ra + c] = l0;
        *(uint32_t*)&AOh[rb + c] = h1;
        *(uint32_t*)&AOl[rb + c] = l1;
    }
}

// ------------------- batchnorm: finalize + apply -------------------
__global__ void col_finalize(const float* __restrict__ psum, const float* __restrict__ psq,
                             const float* __restrict__ g, const float* __restrict__ be,
                             float* __restrict__ scaleC, float* __restrict__ shiftC)
{
    int j = threadIdx.x;
    float s = 0.f, q = 0.f;
    #pragma unroll
    for (int b = 0; b < 64; b++) { s += psum[b * HID + j]; q += psq[b * HID + j]; }
    float m = s * (1.f / NTOK);
    float var = q * (1.f / NTOK) - m * m;
    var = fmaxf(var, 0.f);
    float sc = rsqrtf(var + EPSBN) * g[j];
    scaleC[j] = sc;
    shiftC[j] = be[j] - m * sc;
}

// reads X' (residual already included); out = X'*scale + shift (+opt planes)
__global__ void bn_apply(const float* __restrict__ a,
                         const float* __restrict__ scaleC, const float* __restrict__ shiftC,
                         float* __restrict__ out,
                         __nv_bfloat16* __restrict__ oh, __nv_bfloat16* __restrict__ ol,
                         int emit_planes)
{
    int idx = (blockIdx.x * blockDim.x + threadIdx.x) * 4;
    int j = idx & (HID - 1);
    float4 av = *(const float4*)&a[idx];
    float4 sc = *(const float4*)&scaleC[j];
    float4 sh = *(const float4*)&shiftC[j];
    float4 ov;
    ov.x = av.x * sc.x + sh.x;
    ov.y = av.y * sc.y + sh.y;
    ov.z = av.z * sc.z + sh.z;
    ov.w = av.w * sc.w + sh.w;
    *(float4*)&out[idx] = ov;
    if (emit_planes) {
        uint32_t h01, l01, h23, l23;
        split_pack(ov.x, ov.y, h01, l01);
        split_pack(ov.z, ov.w, h23, l23);
        *(uint32_t*)&oh[idx]     = h01;
        *(uint32_t*)&oh[idx + 2] = h23;
        *(uint32_t*)&ol[idx]     = l01;
        *(uint32_t*)&ol[idx + 2] = l23;
    }
}

// ------------------- launch -------------------
extern "C" void kernel_launch(void* const* d_in, const int* in_sizes, int n_in,
                              void* d_out, int out_size)
{
    const float* A   = (const float*)d_in[0];
    const float* h   = (const float*)d_in[1];
    const float* Wq  = (const float*)d_in[2];
    const float* bq  = (const float*)d_in[3];
    const float* Wk  = (const float*)d_in[4];
    const float* bk  = (const float*)d_in[5];
    const float* Wv  = (const float*)d_in[6];
    const float* bv  = (const float*)d_in[7];
    const float* Wo  = (const float*)d_in[8];
    const float* bo  = (const float*)d_in[9];
    const float* W1  = (const float*)d_in[10];
    const float* c1  = (const float*)d_in[11];
    const float* W2  = (const float*)d_in[12];
    const float* c2  = (const float*)d_in[13];
    const float* g1  = (const float*)d_in[14];
    const float* be1 = (const float*)d_in[15];
    const float* g2  = (const float*)d_in[16];
    const float* be2 = (const float*)d_in[17];
    float* out = (float*)d_out;

    __nv_bfloat16 *hh, *hl, *Wqh, *Wql, *Wkh, *Wkl, *Wvh, *Wvl, *Woh, *Wol,
                  *W1h, *W1l, *W2h, *W2l,
                  *Qh, *Kh, *Vh, *AOh, *AOl, *X1h, *X1l, *Mh, *Ml;
    float *X, *X1, *X2, *psum, *psq, *scaleC, *shiftC;
    cudaGetSymbolAddress((void**)&hh,  g_hh);  cudaGetSymbolAddress((void**)&hl,  g_hl);
    cudaGetSymbolAddress((void**)&Wqh, g_Wqh); cudaGetSymbolAddress((void**)&Wql, g_Wql);
    cudaGetSymbolAddress((void**)&Wkh, g_Wkh); cudaGetSymbolAddress((void**)&Wkl, g_Wkl);
    cudaGetSymbolAddress((void**)&Wvh, g_Wvh); cudaGetSymbolAddress((void**)&Wvl, g_Wvl);
    cudaGetSymbolAddress((void**)&Woh, g_Woh); cudaGetSymbolAddress((void**)&Wol, g_Wol);
    cudaGetSymbolAddress((void**)&W1h, g_W1h); cudaGetSymbolAddress((void**)&W1l, g_W1l);
    cudaGetSymbolAddress((void**)&W2h, g_W2h); cudaGetSymbolAddress((void**)&W2l, g_W2l);
    cudaGetSymbolAddress((void**)&Qh, g_Qh);
    cudaGetSymbolAddress((void**)&Kh, g_Kh);
    cudaGetSymbolAddress((void**)&Vh, g_Vh);
    cudaGetSymbolAddress((void**)&AOh, g_AOh); cudaGetSymbolAddress((void**)&AOl, g_AOl);
    cudaGetSymbolAddress((void**)&X1h, g_X1h); cudaGetSymbolAddress((void**)&X1l, g_X1l);
    cudaGetSymbolAddress((void**)&Mh, g_Mh);   cudaGetSymbolAddress((void**)&Ml, g_Ml);
    cudaGetSymbolAddress((void**)&X,   g_X);
    cudaGetSymbolAddress((void**)&X1,  g_X1);
    cudaGetSymbolAddress((void**)&X2,  g_X2);
    cudaGetSymbolAddress((void**)&psum,   g_psum);
    cudaGetSymbolAddress((void**)&psq,    g_psq);
    cudaGetSymbolAddress((void**)&scaleC, g_scaleC);
    cudaGetSymbolAddress((void**)&shiftC, g_shiftC);

    cudaFuncSetAttribute(flash_attn_mma,
                         cudaFuncAttributeMaxDynamicSharedMemorySize, FLASH_SMEM);
    cudaFuncSetAttribute(gemm_plane,
                         cudaFuncAttributeMaxDynamicSharedMemorySize, GEMM_SMEM);
    cudaFuncSetAttribute(gemm_qkv,
                         cudaFuncAttributeMaxDynamicSharedMemorySize, GEMM_SMEM);

    dim3 gqkv(HID / 64, NTOK / 64, 3);
    dim3 gproj(HID / 64, NTOK / 64);
    dim3 gffn1(2 * HID / 64, NTOK / 64);
    dim3 gattn(NTOK / 128, NHEADS);

    SplitJobs jobs;
    jobs.j[0] = { h,  hh,  hl,  NTOK * HID / 4 };
    jobs.j[1] = { Wq, Wqh, Wql, HID * HID / 4 };
    jobs.j[2] = { Wk, Wkh, Wkl, HID * HID / 4 };
    jobs.j[3] = { Wv, Wvh, Wvl, HID * HID / 4 };
    jobs.j[4] = { Wo, Woh, Wol, HID * HID / 4 };
    jobs.j[5] = { W1, W1h, W1l, 2 * HID * HID / 4 };
    jobs.j[6] = { W2, W2h, W2l, 2 * HID * HID / 4 };
    split_all<<<dim3(64, 7), 256>>>(jobs);

    gemm_qkv<<<gqkv, 128, GEMM_SMEM>>>(hh, hl, Wqh, Wql, bq, Qh,
                                       Wkh, Wkl, bk, Kh,
                                       Wvh, Wvl, bv, Vh);

    flash_attn_mma<<<gattn, 256, FLASH_SMEM>>>(Qh, Kh, Vh, A, AOh, AOl);

    // O-proj + residual(h) + BN1 partial stats (mode 2)
    gemm_plane<<<gproj, 128, GEMM_SMEM>>>(AOh, AOl, Woh, Wol, bo,
                                          X, nullptr, nullptr, h, psum, psq,
                                          HID, HID, 1.f, 0, 2);
    col_finalize<<<1, HID>>>(psum, psq, g1, be1, scaleC, shiftC);
    bn_apply<<<NTOK * HID / 1024, 256>>>(X, scaleC, shiftC, X1, X1h, X1l, 1);

    // FFN1 -> Mid planes (relu)
    gemm_plane<<<gffn1, 128, GEMM_SMEM>>>(X1h, X1l, W1h, W1l, c1,
                                          nullptr, Mh, Ml, nullptr, nullptr, nullptr,
                                          2 * HID, HID, 1.f, 1, 1);
    // FFN2 + residual(X1) + BN2 partial stats (mode 2)
    gemm_plane<<<gproj, 128, GEMM_SMEM>>>(Mh, Ml, W2h, W2l, c2,
                                          X2, nullptr, nullptr, X1, psum, psq,
                                          HID, 2 * HID, 1.f, 0, 2);
    col_finalize<<<1, HID>>>(psum, psq, g2, be2, scaleC, shiftC);
    bn_apply<<<NTOK * HID / 1024, 256>>>(X2, scaleC, shiftC, out, nullptr, nullptr, 0);
}

// round 15
// speedup vs baseline: 1.5501x; 1.0492x over previous
#include <cuda_runtime.h>
#include <cuda_bf16.h>
#include <cstdint>

#define NTOK 4096
#define HID 256
#define NHEADS 8
#define HD 32
#define EPSBN 1e-5f
#define QSCALE 0.17677669529663687f       // 1/sqrt(32)
#define LOG2E  1.4426950408889634f
#define QK2SCALE (QSCALE * LOG2E)         // folded so softmax uses exp2

// ------------------- scratch (device globals; no allocation) -------------------
__device__ __nv_bfloat16 g_hh[NTOK * HID];
__device__ __nv_bfloat16 g_Wqh[HID * HID];
__device__ __nv_bfloat16 g_Wkh[HID * HID];
__device__ __nv_bfloat16 g_Wvh[HID * HID];
__device__ __nv_bfloat16 g_Woh[HID * HID],  g_Wol[HID * HID];
__device__ __nv_bfloat16 g_W1h[2 * HID * HID], g_W1l[2 * HID * HID];
__device__ __nv_bfloat16 g_W2h[2 * HID * HID], g_W2l[2 * HID * HID];
__device__ __nv_bfloat16 g_Qh[NTOK * HID];
__device__ __nv_bfloat16 g_Kh[NTOK * HID];
__device__ __nv_bfloat16 g_Vh[NTOK * HID];
__device__ __nv_bfloat16 g_AOh[NTOK * HID], g_AOl[NTOK * HID];
__device__ __nv_bfloat16 g_X1h[NTOK * HID], g_X1l[NTOK * HID];
__device__ __nv_bfloat16 g_Mh[NTOK * 2 * HID], g_Ml[NTOK * 2 * HID];
__device__ float g_X[NTOK * HID];       // X' = O-proj + h (residual included)
__device__ float g_X1[NTOK * HID];
__device__ float g_X2[NTOK * HID];      // X2' = X1 + FFN2 (residual included)
__device__ float g_psum[64 * HID];
__device__ float g_psq[64 * HID];

// ------------------- helpers -------------------
__device__ __forceinline__ void mma_bf16(float* c, const uint32_t* a, const uint32_t* b)
{
    asm volatile(
        "mma.sync.aligned.m16n8k16.row.col.f32.bf16.bf16.f32 "
        "{%0,%1,%2,%3}, {%4,%5,%6,%7}, {%8,%9}, {%0,%1,%2,%3};"
        : "+f"(c[0]), "+f"(c[1]), "+f"(c[2]), "+f"(c[3])
        : "r"(a[0]), "r"(a[1]), "r"(a[2]), "r"(a[3]), "r"(b[0]), "r"(b[1]));
}

__device__ __forceinline__ void split_pack(float x, float y, uint32_t& hi, uint32_t& lo)
{
    uint32_t h;
    asm("cvt.rn.bf16x2.f32 %0, %1, %2;" : "=r"(h) : "f"(y), "f"(x));
    float xr = __uint_as_float(h << 16);
    float yr = __uint_as_float(h & 0xffff0000u);
    float xl = x - xr, yl = y - yr;
    uint32_t l;
    asm("cvt.rn.bf16x2.f32 %0, %1, %2;" : "=r"(l) : "f"(yl), "f"(xl));
    hi = h; lo = l;
}

__device__ __forceinline__ uint32_t pack_bf16(float x, float y)
{
    uint32_t h;
    asm("cvt.rn.bf16x2.f32 %0, %1, %2;" : "=r"(h) : "f"(y), "f"(x));
    return h;
}

__device__ __forceinline__ float ex2(float x)
{
    float r;
    asm("ex2.approx.ftz.f32 %0, %1;" : "=f"(r) : "f"(x));
    return r;
}

__device__ __forceinline__ uint32_t scvta(const void* p)
{
    return (uint32_t)__cvta_generic_to_shared(p);
}

__device__ __forceinline__ void ldsm_x4(uint32_t* d, uint32_t addr)
{
    asm volatile("ldmatrix.sync.aligned.m8n8.x4.shared.b16 {%0,%1,%2,%3}, [%4];"
                 : "=r"(d[0]), "=r"(d[1]), "=r"(d[2]), "=r"(d[3]) : "r"(addr));
}

__device__ __forceinline__ void ldsm_x4_t(uint32_t* d, uint32_t addr)
{
    asm volatile("ldmatrix.sync.aligned.m8n8.x4.trans.shared.b16 {%0,%1,%2,%3}, [%4];"
                 : "=r"(d[0]), "=r"(d[1]), "=r"(d[2]), "=r"(d[3]) : "r"(addr));
}

__device__ __forceinline__ void cp_async16(uint32_t dst, const void* src)
{
    asm volatile("cp.async.cg.shared.global [%0], [%1], 16;" :: "r"(dst), "l"(src));
}

__device__ __forceinline__ void cp_commit() { asm volatile("cp.async.commit_group;"); }
__device__ __forceinline__ void cp_wait0()  { asm volatile("cp.async.wait_group 0;"); }

// ------------------- split_all (lo pointer may be null = hi-only job) ------------
struct SplitJob { const float* src; __nv_bfloat16* hi; __nv_bfloat16* lo; int n4; };
struct SplitJobs { SplitJob j[7]; };

__global__ void split_all(SplitJobs jobs)
{
    SplitJob job = jobs.j[blockIdx.y];
    for (int i = blockIdx.x * blockDim.x + threadIdx.x; i < job.n4;
         i += gridDim.x * blockDim.x) {
        float4 v = *(const float4*)&job.src[(size_t)i * 4];
        uint32_t h01, l01, h23, l23;
        split_pack(v.x, v.y, h01, l01);
        split_pack(v.z, v.w, h23, l23);
        *(uint32_t*)&job.hi[(size_t)i * 4]     = h01;
        *(uint32_t*)&job.hi[(size_t)i * 4 + 2] = h23;
        if (job.lo) {
            *(uint32_t*)&job.lo[(size_t)i * 4]     = l01;
            *(uint32_t*)&job.lo[(size_t)i * 4 + 2] = l23;
        }
    }
}

// ------------------- templated tensor-core GEMM (BM=64, 128 thr) -------------------
// MODE 0: C f32. MODE 1: planes Ch/Cl (opt relu). MODE 2: C=acc+bias+Rin + BN stats.
// MODE 4: bf16 hi only. PURE=1: single-term bf16 inputs (hi planes only).
#define GKP 40
#define GPB (64 * GKP * 2)
#define GSMEM_FULL (2 * 4 * GPB)   // 40960
#define GSMEM_PURE (2 * 2 * GPB)   // 20480

template<int PURE>
__device__ __forceinline__ void gemm_stage(
    const __nv_bfloat16* __restrict__ Ahp, const __nv_bfloat16* __restrict__ Alp,
    const __nv_bfloat16* __restrict__ Whp, const __nv_bfloat16* __restrict__ Wlp,
    int i0, int j0, int K, int kk, uint32_t bufb, int tid)
{
    const uint32_t wofs = PURE ? GPB : 2 * GPB;
    #pragma unroll
    for (int t = 0; t < 2; t++) {
        int idx = tid + (t << 7);
        int r = idx >> 2, c8 = (idx & 3) * 8;
        uint32_t so = (uint32_t)((r * GKP + c8) * 2);
        cp_async16(bufb + so, Ahp + (size_t)(i0 + r) * K + kk + c8);
        cp_async16(bufb + wofs + so, Whp + (size_t)(j0 + r) * K + kk + c8);
        if (!PURE) {
            cp_async16(bufb + GPB + so, Alp + (size_t)(i0 + r) * K + kk + c8);
            cp_async16(bufb + 3 * GPB + so, Wlp + (size_t)(j0 + r) * K + kk + c8);
        }
    }
}

template<int MODE, int PURE>
__device__ __forceinline__ void gemm_core(
    const __nv_bfloat16* __restrict__ Ahp, const __nv_bfloat16* __restrict__ Alp,
    const __nv_bfloat16* __restrict__ Whp, const __nv_bfloat16* __restrict__ Wlp,
    const float* __restrict__ bias, float* __restrict__ C,
    __nv_bfloat16* __restrict__ Ch, __nv_bfloat16* __restrict__ Cl,
    const float* __restrict__ Rin, float* __restrict__ psum, float* __restrict__ psq,
    int Nout, int K, float scale, int relu, char* smemraw)
{
    const int tid = threadIdx.x, w = tid >> 5, lane = tid & 31;
    const int qr = lane >> 2, qc2 = (lane & 3) * 2;
    const int i0 = blockIdx.y * 64, j0 = blockIdx.x * 64;
    const int r0 = w * 16;
    const uint32_t PBUF = PURE ? 2 * GPB : 4 * GPB;

    float acc[8][4] = {};

    const int arow = r0 + ((lane >> 3) & 1) * 8 + (lane & 7);
    const int acol = (lane >> 4) * 8;
    const int brow = (lane & 7);
    const int bcol = (lane >> 3) * 8;
    const uint32_t wofs = PURE ? GPB : 2 * GPB;

    const uint32_t smb = scvta(smemraw);
    const int nch = K / 32;

    gemm_stage<PURE>(Ahp, Alp, Whp, Wlp, i0, j0, K, 0, smb, tid);
    cp_commit(); cp_wait0(); __syncthreads();

    int p = 0;
    for (int c = 0; c < nch; c++) {
        if (c + 1 < nch)
            gemm_stage<PURE>(Ahp, Alp, Whp, Wlp, i0, j0, K, (c + 1) * 32,
                             smb + (uint32_t)(p ^ 1) * PBUF, tid);
        cp_commit();

        const uint32_t base = smb + (uint32_t)p * PBUF;
        uint32_t ah[2][4], al[2][4];
        #pragma unroll
        for (int ks = 0; ks < 2; ks++) {
            uint32_t off = (uint32_t)((arow * GKP + ks * 16 + acol) * 2);
            ldsm_x4(ah[ks], base + off);
            if (!PURE) ldsm_x4(al[ks], base + GPB + off);
        }
        #pragma unroll
        for (int nt = 0; nt < 8; nt++) {
            uint32_t bh[4], bl[4];
            uint32_t off = (uint32_t)(((nt * 8 + brow) * GKP + bcol) * 2);
            ldsm_x4(bh, base + wofs + off);
            if (!PURE) ldsm_x4(bl, base + 3 * GPB + off);
            mma_bf16(acc[nt], ah[0], bh);
            mma_bf16(acc[nt], ah[1], bh + 2);
            if (!PURE) {
                mma_bf16(acc[nt], al[0], bh);
                mma_bf16(acc[nt], ah[0], bl);
                mma_bf16(acc[nt], al[1], bh + 2);
                mma_bf16(acc[nt], ah[1], bl + 2);
            }
        }
        cp_wait0();
        __syncthreads();
        p ^= 1;
    }

    const int ra = i0 + r0 + qr, rb = ra + 8;

    if (MODE != 2) {
        #pragma unroll
        for (int nt = 0; nt < 8; nt++) {
            int j = j0 + nt * 8 + qc2;
            float b0 = bias[j], b1 = bias[j + 1];
            float v00 = (acc[nt][0] + b0) * scale;
            float v01 = (acc[nt][1] + b1) * scale;
            float v10 = (acc[nt][2] + b0) * scale;
            float v11 = (acc[nt][3] + b1) * scale;
            if (relu) {
                v00 = fmaxf(v00, 0.f); v01 = fmaxf(v01, 0.f);
                v10 = fmaxf(v10, 0.f); v11 = fmaxf(v11, 0.f);
            }
            if (MODE == 0) {
                *(float2*)&C[(size_t)ra * Nout + j] = make_float2(v00, v01);
                *(float2*)&C[(size_t)rb * Nout + j] = make_float2(v10, v11);
            } else if (MODE == 4) {
                *(uint32_t*)&Ch[(size_t)ra * Nout + j] = pack_bf16(v00, v01);
                *(uint32_t*)&Ch[(size_t)rb * Nout + j] = pack_bf16(v10, v11);
            } else {  // MODE 1
                uint32_t h0, l0, h1, l1;
                split_pack(v00, v01, h0, l0);
                split_pack(v10, v11, h1, l1);
                *(uint32_t*)&Ch[(size_t)ra * Nout + j] = h0;
                *(uint32_t*)&Cl[(size_t)ra * Nout + j] = l0;
                *(uint32_t*)&Ch[(size_t)rb * Nout + j] = h1;
                *(uint32_t*)&Cl[(size_t)rb * Nout + j] = l1;
            }
        }
    } else {
        float cs[8][2], cq[8][2];
        #pragma unroll
        for (int nt = 0; nt < 8; nt++) {
            int j = j0 + nt * 8 + qc2;
            float b0 = bias[j], b1 = bias[j + 1];
            float2 r0v = *(const float2*)&Rin[(size_t)ra * Nout + j];
            float2 r1v = *(const float2*)&Rin[(size_t)rb * Nout + j];
            float x00 = acc[nt][0] + b0 + r0v.x;
            float x01 = acc[nt][1] + b1 + r0v.y;
            float x10 = acc[nt][2] + b0 + r1v.x;
            float x11 = acc[nt][3] + b1 + r1v.y;
            *(float2*)&C[(size_t)ra * Nout + j] = make_float2(x00, x01);
            *(float2*)&C[(size_t)rb * Nout + j] = make_float2(x10, x11);
            cs[nt][0] = x00 + x10;
            cs[nt][1] = x01 + x11;
            cq[nt][0] = x00 * x00 + x10 * x10;
            cq[nt][1] = x01 * x01 + x11 * x11;
        }
        #pragma unroll
        for (int m = 4; m <= 16; m <<= 1) {
            #pragma unroll
            for (int nt = 0; nt < 8; nt++) {
                cs[nt][0] += __shfl_xor_sync(0xffffffffu, cs[nt][0], m);
                cs[nt][1] += __shfl_xor_sync(0xffffffffu, cs[nt][1], m);
                cq[nt][0] += __shfl_xor_sync(0xffffffffu, cq[nt][0], m);
                cq[nt][1] += __shfl_xor_sync(0xffffffffu, cq[nt][1], m);
            }
        }
        float* sred = (float*)smemraw;
        float* qred = (float*)(smemraw + 4 * 64 * 4);
        if (lane < 4) {
            #pragma unroll
            for (int nt = 0; nt < 8; nt++) {
                int jj = nt * 8 + (lane & 3) * 2;
                sred[w * 64 + jj]     = cs[nt][0];
                sred[w * 64 + jj + 1] = cs[nt][1];
                qred[w * 64 + jj]     = cq[nt][0];
                qred[w * 64 + jj + 1] = cq[nt][1];
            }
        }
        __syncthreads();
        if (tid < 64) {
            float s = sred[tid] + sred[64 + tid] + sred[128 + tid] + sred[192 + tid];
            psum[(size_t)blockIdx.y * HID + j0 + tid] = s;
        } else if (tid < 128) {
            int t = tid - 64;
            float q = qred[t] + qred[64 + t] + qred[128 + t] + qred[192 + t];
            psq[(size_t)blockIdx.y * HID + j0 + t] = q;
        }
    }
}

__global__ void __launch_bounds__(128, 4)
gemm_resbn(const __nv_bfloat16* Ahp, const __nv_bfloat16* Alp,
           const __nv_bfloat16* Whp, const __nv_bfloat16* Wlp,
           const float* bias, float* C, const float* Rin,
           float* psum, float* psq, int Nout, int K)
{
    extern __shared__ __align__(16) char smemraw[];
    gemm_core<2, 0>(Ahp, Alp, Whp, Wlp, bias, C, nullptr, nullptr, Rin, psum, psq,
                    Nout, K, 1.f, 0, smemraw);
}

__global__ void __launch_bounds__(128, 4)
gemm_planes(const __nv_bfloat16* Ahp, const __nv_bfloat16* Alp,
            const __nv_bfloat16* Whp, const __nv_bfloat16* Wlp,
            const float* bias, __nv_bfloat16* Ch, __nv_bfloat16* Cl,
            int Nout, int K, int relu)
{
    extern __shared__ __align__(16) char smemraw[];
    gemm_core<1, 0>(Ahp, Alp, Whp, Wlp, bias, nullptr, Ch, Cl, nullptr, nullptr, nullptr,
                    Nout, K, 1.f, relu, smemraw);
}

__global__ void __launch_bounds__(128, 4)
gemm_qkv(const __nv_bfloat16* hh,
         const __nv_bfloat16* Wqh, const float* bq, __nv_bfloat16* Qh,
         const __nv_bfloat16* Wkh, const float* bk, __nv_bfloat16* Kh,
         const __nv_bfloat16* Wvh, const float* bv, __nv_bfloat16* Vh)
{
    extern __shared__ __align__(16) char smemraw[];
    const __nv_bfloat16* Wh; const float* b; __nv_bfloat16* Ch; float sc;
    if (blockIdx.z == 0)      { Wh = Wqh; b = bq; Ch = Qh; sc = QK2SCALE; }
    else if (blockIdx.z == 1) { Wh = Wkh; b = bk; Ch = Kh; sc = 1.f; }
    else                      { Wh = Wvh; b = bv; Ch = Vh; sc = 1.f; }
    gemm_core<4, 1>(hh, nullptr, Wh, nullptr, b, nullptr, Ch, nullptr,
                    nullptr, nullptr, nullptr, HID, HID, sc, 0, smemraw);
}

// ------------------- tensor-core flash attention (unchanged) -------------------
#define KP 56
#define BUFB (64 * KP * 2)
#define FLASH_SMEM (4 * BUFB)

__global__ void __launch_bounds__(256, 2)
flash_attn_mma(const __nv_bfloat16* __restrict__ Qhg,
               const __nv_bfloat16* __restrict__ Khg,
               const __nv_bfloat16* __restrict__ Vhg,
               const float* __restrict__ Amat,
               __nv_bfloat16* __restrict__ AOh, __nv_bfloat16* __restrict__ AOl)
{
    extern __shared__ __align__(16) char smemraw[];
    __nv_bfloat16* Khs = (__nv_bfloat16*)(smemraw);
    __nv_bfloat16* Vhs = (__nv_bfloat16*)(smemraw + 2 * BUFB);

    const int tid  = threadIdx.x;
    const int w    = tid >> 5;
    const int lane = tid & 31;
    const int qr   = lane >> 2;
    const int qc2  = (lane & 3) * 2;

    const int hh   = blockIdx.y;
    const int row0 = blockIdx.x * 128;
    const int r0   = w * 16;

    const size_t hbase = (size_t)hh * NTOK * HD;

    uint32_t aQh[2][4];
    {
        const size_t ra = hbase + (size_t)(row0 + r0 + qr) * HD;
        const size_t rb = ra + 8 * HD;
        #pragma unroll
        for (int ks = 0; ks < 2; ks++) {
            int cb = ks * 16 + qc2;
            aQh[ks][0] = *(const uint32_t*)&Qhg[ra + cb];
            aQh[ks][1] = *(const uint32_t*)&Qhg[rb + cb];
            aQh[ks][2] = *(const uint32_t*)&Qhg[ra + cb + 8];
            aQh[ks][3] = *(const uint32_t*)&Qhg[rb + cb + 8];
        }
    }

    float oacc[4][4] = {};
    float ls0 = 0.f, ls1 = 0.f;

    const int ga = (row0 + r0 + qr) * NTOK;
    const int gb = (row0 + r0 + qr + 8) * NTOK;

    const uint32_t khb = scvta(Khs);
    const uint32_t vhb = scvta(Vhs);
    const uint32_t koff = (uint32_t)(((lane & 7) * KP + (lane >> 3) * 8) * 2);
    const uint32_t vtoff = (uint32_t)(lane * KP * 2);

    const int sarr = tid >> 7;
    const int sid0 = tid & 127;
    const char* gsrc = sarr ? (const char*)(Vhg + hbase) : (const char*)(Khg + hbase);
    const uint32_t sdstb = sarr ? vhb : khb;
    uint32_t soff[2];
    #pragma unroll
    for (int t = 0; t < 2; t++) {
        int idx = sid0 + t * 128;
        int r = idx >> 2, c8 = (idx & 3) * 8;
        soff[t] = (uint32_t)((r * KP + c8) * 2);
    }

    #pragma unroll
    for (int t = 0; t < 2; t++)
        cp_async16(sdstb + soff[t], gsrc + (size_t)(sid0 + t * 128) * 16);
    cp_commit();
    cp_wait0();
    __syncthreads();

    int p = 0;
    for (int mt = 0; mt < NTOK / 64; mt++) {
        const int m0 = mt * 64;
        const uint32_t pofs = (uint32_t)p * BUFB;

        if (mt < NTOK / 64 - 1) {
            const char* src = gsrc + (size_t)(mt + 1) * 64 * HD * 2;
            const uint32_t db = sdstb + (pofs ^ BUFB);
            #pragma unroll
            for (int t = 0; t < 2; t++)
                cp_async16(db + soff[t], src + (size_t)(sid0 + t * 128) * 16);
        }
        cp_commit();

        float2 Ar[8], Br[8];
        #pragma unroll
        for (int nt = 0; nt < 8; nt++) {
            int gc = m0 + nt * 8 + qc2;
            Ar[nt] = *(const float2*)&Amat[(size_t)ga + gc];
            Br[nt] = *(const float2*)&Amat[(size_t)gb + gc];
        }

        float sacc[8][4];
        #pragma unroll
        for (int nt = 0; nt < 8; nt++) {
            sacc[nt][0] = sacc[nt][1] = sacc[nt][2] = sacc[nt][3] = 0.f;
            uint32_t off = koff + pofs + (uint32_t)(nt * 8 * KP * 2);
            uint32_t bh[4];
            ldsm_x4(bh, khb + off);
            mma_bf16(sacc[nt], aQh[0], bh);
            mma_bf16(sacc[nt], aQh[1], bh + 2);
        }

        #pragma unroll
        for (int nt = 0; nt < 8; nt++) {
            sacc[nt][0] = ex2(sacc[nt][0] * Ar[nt].x);
            sacc[nt][1] = ex2(sacc[nt][1] * Ar[nt].y);
            sacc[nt][2] = ex2(sacc[nt][2] * Br[nt].x);
            sacc[nt][3] = ex2(sacc[nt][3] * Br[nt].y);
            ls0 += sacc[nt][0] + sacc[nt][1];
            ls1 += sacc[nt][2] + sacc[nt][3];
        }

        uint32_t ph[4][4];
        #pragma unroll
        for (int kc = 0; kc < 4; kc++) {
            ph[kc][0] = pack_bf16(sacc[2 * kc][0],     sacc[2 * kc][1]);
            ph[kc][1] = pack_bf16(sacc[2 * kc][2],     sacc[2 * kc][3]);
            ph[kc][2] = pack_bf16(sacc[2 * kc + 1][0], sacc[2 * kc + 1][1]);
            ph[kc][3] = pack_bf16(sacc[2 * kc + 1][2], sacc[2 * kc + 1][3]);
        }

        #pragma unroll
        for (int nt = 0; nt < 4; nt++) {
            uint32_t off = vtoff + pofs + (uint32_t)(nt * 16);
            uint32_t bh[8];
            ldsm_x4_t(bh,     vhb + off);
            ldsm_x4_t(bh + 4, vhb + off + 32 * KP * 2);
            #pragma unroll
            for (int kc = 0; kc < 4; kc++)
                mma_bf16(oacc[nt], ph[kc], bh + kc * 2);
        }

        cp_wait0();
        __syncthreads();
        p ^= 1;
    }

    ls0 += __shfl_xor_sync(0xffffffffu, ls0, 1);
    ls0 += __shfl_xor_sync(0xffffffffu, ls0, 2);
    ls1 += __shfl_xor_sync(0xffffffffu, ls1, 1);
    ls1 += __shfl_xor_sync(0xffffffffu, ls1, 2);
    float inv0 = 1.f / ls0, inv1 = 1.f / ls1;

    const size_t ra = hbase + (size_t)(row0 + r0 + qr) * HD;
    const size_t rb = ra + 8 * HD;
    #pragma unroll
    for (int nt = 0; nt < 4; nt++) {
        int c = nt * 8 + qc2;
        uint32_t h0, l0, h1, l1;
        split_pack(oacc[nt][0] * inv0, oacc[nt][1] * inv0, h0, l0);
        split_pack(oacc[nt][2] * inv1, oacc[nt][3] * inv1, h1, l1);
        *(uint32_t*)&AOh[ra + c] = h0;
        *(uint32_t*)&AOl[ra + c] = l0;
        *(uint32_t*)&AOh[rb + c] = h1;
        *(uint32_t*)&AOl[rb + c] = l1;
    }
}

// ------------------- fused BN finalize + apply -------------------
// Each block: per-column reduce of 64 partials -> scale/shift in smem -> apply 32 rows.
__global__ void __launch_bounds__(256)
bn_fused(const float* __restrict__ Xp,
         const float* __restrict__ psum, const float* __restrict__ psq,
         const float* __restrict__ g, const float* __restrict__ be,
         float* __restrict__ out,
         __nv_bfloat16* __restrict__ oh, __nv_bfloat16* __restrict__ ol,
         int emit_planes)
{
    __shared__ float ssc[HID], ssh[HID];
    const int tid = threadIdx.x;
    float s = 0.f, q = 0.f;
    #pragma unroll
    for (int b = 0; b < 64; b++) {
        s += psum[b * HID + tid];
        q += psq[b * HID + tid];
    }
    float m = s * (1.f / NTOK);
    float var = fmaxf(q * (1.f / NTOK) - m * m, 0.f);
    float sc = rsqrtf(var + EPSBN) * g[tid];
    ssc[tid] = sc;
    ssh[tid] = be[tid] - m * sc;
    __syncthreads();

    const int j = (tid * 4) & (HID - 1);
    float4 sc4 = *(const float4*)&ssc[j];
    float4 sh4 = *(const float4*)&ssh[j];
    #pragma unroll
    for (int pass = 0; pass < 8; pass++) {
        size_t e = (size_t)blockIdx.x * 8192 + pass * 1024 + tid * 4;
        float4 av = *(const float4*)&Xp[e];
        float4 ov;
        ov.x = av.x * sc4.x + sh4.x;
        ov.y = av.y * sc4.y + sh4.y;
        ov.z = av.z * sc4.z + sh4.z;
        ov.w = av.w * sc4.w + sh4.w;
        *(float4*)&out[e] = ov;
        if (emit_planes) {
            uint32_t h01, l01, h23, l23;
            split_pack(ov.x, ov.y, h01, l01);
            split_pack(ov.z, ov.w, h23, l23);
            *(uint32_t*)&oh[e]     = h01;
            *(uint32_t*)&oh[e + 2] = h23;
            *(uint32_t*)&ol[e]     = l01;
            *(uint32_t*)&ol[e + 2] = l23;
        }
    }
}

// ------------------- launch -------------------
extern "C" void kernel_launch(void* const* d_in, const int* in_sizes, int n_in,
                              void* d_out, int out_size)
{
    const float* A   = (const float*)d_in[0];
    const float* h   = (const float*)d_in[1];
    const float* Wq  = (const float*)d_in[2];
    const float* bq  = (const float*)d_in[3];
    const float* Wk  = (const float*)d_in[4];
    const float* bk  = (const float*)d_in[5];
    const float* Wv  = (const float*)d_in[6];
    const float* bv  = (const float*)d_in[7];
    const float* Wo  = (const float*)d_in[8];
    const float* bo  = (const float*)d_in[9];
    const float* W1  = (const float*)d_in[10];
    const float* c1  = (const float*)d_in[11];
    const float* W2  = (const float*)d_in[12];
    const float* c2  = (const float*)d_in[13];
    const float* g1  = (const float*)d_in[14];
    const float* be1 = (const float*)d_in[15];
    const float* g2  = (const float*)d_in[16];
    const float* be2 = (const float*)d_in[17];
    float* out = (float*)d_out;

    __nv_bfloat16 *hh, *Wqh, *Wkh, *Wvh, *Woh, *Wol, *W1h, *W1l, *W2h, *W2l,
                  *Qh, *Kh, *Vh, *AOh, *AOl, *X1h, *X1l, *Mh, *Ml;
    float *X, *X1, *X2, *psum, *psq;
    cudaGetSymbolAddress((void**)&hh,  g_hh);
    cudaGetSymbolAddress((void**)&Wqh, g_Wqh);
    cudaGetSymbolAddress((void**)&Wkh, g_Wkh);
    cudaGetSymbolAddress((void**)&Wvh, g_Wvh);
    cudaGetSymbolAddress((void**)&Woh, g_Woh); cudaGetSymbolAddress((void**)&Wol, g_Wol);
    cudaGetSymbolAddress((void**)&W1h, g_W1h); cudaGetSymbolAddress((void**)&W1l, g_W1l);
    cudaGetSymbolAddress((void**)&W2h, g_W2h); cudaGetSymbolAddress((void**)&W2l, g_W2l);
    cudaGetSymbolAddress((void**)&Qh, g_Qh);
    cudaGetSymbolAddress((void**)&Kh, g_Kh);
    cudaGetSymbolAddress((void**)&Vh, g_Vh);
    cudaGetSymbolAddress((void**)&AOh, g_AOh); cudaGetSymbolAddress((void**)&AOl, g_AOl);
    cudaGetSymbolAddress((void**)&X1h, g_X1h); cudaGetSymbolAddress((void**)&X1l, g_X1l);
    cudaGetSymbolAddress((void**)&Mh, g_Mh);   cudaGetSymbolAddress((void**)&Ml, g_Ml);
    cudaGetSymbolAddress((void**)&X,   g_X);
    cudaGetSymbolAddress((void**)&X1,  g_X1);
    cudaGetSymbolAddress((void**)&X2,  g_X2);
    cudaGetSymbolAddress((void**)&psum, g_psum);
    cudaGetSymbolAddress((void**)&psq,  g_psq);

    cudaFuncSetAttribute(flash_attn_mma,
                         cudaFuncAttributeMaxDynamicSharedMemorySize, FLASH_SMEM);
    cudaFuncSetAttribute(gemm_resbn,
                         cudaFuncAttributeMaxDynamicSharedMemorySize, GSMEM_FULL);
    cudaFuncSetAttribute(gemm_planes,
                         cudaFuncAttributeMaxDynamicSharedMemorySize, GSMEM_FULL);
    cudaFuncSetAttribute(gemm_qkv,
                         cudaFuncAttributeMaxDynamicSharedMemorySize, GSMEM_PURE);

    dim3 gqkv(HID / 64, NTOK / 64, 3);
    dim3 gproj(HID / 64, NTOK / 64);
    dim3 gffn1(2 * HID / 64, NTOK / 64);
    dim3 gattn(NTOK / 128, NHEADS);

    SplitJobs jobs;
    jobs.j[0] = { h,  hh,  nullptr, NTOK * HID / 4 };      // hi-only (pure QKV)
    jobs.j[1] = { Wq, Wqh, nullptr, HID * HID / 4 };
    jobs.j[2] = { Wk, Wkh, nullptr, HID * HID / 4 };
    jobs.j[3] = { Wv, Wvh, nullptr, HID * HID / 4 };
    jobs.j[4] = { Wo, Woh, Wol, HID * HID / 4 };
    jobs.j[5] = { W1, W1h, W1l, 2 * HID * HID / 4 };
    jobs.j[6] = { W2, W2h, W2l, 2 * HID * HID / 4 };
    split_all<<<dim3(64, 7), 256>>>(jobs);

    // pure-bf16 QKV projections (Q carries qscale*log2e)
    gemm_qkv<<<gqkv, 128, GSMEM_PURE>>>(hh, Wqh, bq, Qh, Wkh, bk, Kh, Wvh, bv, Vh);

    // flash attention -> AO planes
    flash_attn_mma<<<gattn, 256, FLASH_SMEM>>>(Qh, Kh, Vh, A, AOh, AOl);

    // O-proj + residual(h) + BN1 partial stats
    gemm_resbn<<<gproj, 128, GSMEM_FULL>>>(AOh, AOl, Woh, Wol, bo, X, h,
                                           psum, psq, HID, HID);
    bn_fused<<<128, 256>>>(X, psum, psq, g1, be1, X1, X1h, X1l, 1);

    // FFN1 -> Mid planes (relu)
    gemm_planes<<<gffn1, 128, GSMEM_FULL>>>(X1h, X1l, W1h, W1l, c1, Mh, Ml,
                                            2 * HID, HID, 1);
    // FFN2 + residual(X1) + BN2 partial stats
    gemm_resbn<<<gproj, 128, GSMEM_FULL>>>(Mh, Ml, W2h, W2l, c2, X2, X1,
                                           psum, psq, HID, 2 * HID);
    bn_fused<<<128, 256>>>(X2, psum, psq, g2, be2, out, nullptr, nullptr, 0);
}

// round 17
// speedup vs baseline: 1.6365x; 1.0557x over previous
#include <cuda_runtime.h>
#include <cuda_bf16.h>
#include <cstdint>

#define NTOK 4096
#define HID 256
#define NHEADS 8
#define HD 32
#define EPSBN 1e-5f
#define QSCALE 0.17677669529663687f       // 1/sqrt(32)
#define LOG2E  1.4426950408889634f
#define QK2SCALE (QSCALE * LOG2E)         // folded so softmax uses exp2

// ------------------- scratch (device globals; no allocation) -------------------
__device__ __nv_bfloat16 g_hh[NTOK * HID];
__device__ __nv_bfloat16 g_Wqh[HID * HID];
__device__ __nv_bfloat16 g_Wkh[HID * HID];
__device__ __nv_bfloat16 g_Wvh[HID * HID];
__device__ __nv_bfloat16 g_Woh[HID * HID],  g_Wol[HID * HID];
__device__ __nv_bfloat16 g_W1h[2 * HID * HID], g_W1l[2 * HID * HID];
__device__ __nv_bfloat16 g_W2h[2 * HID * HID], g_W2l[2 * HID * HID];
__device__ __nv_bfloat16 g_Qh[NTOK * HID];
__device__ __nv_bfloat16 g_Kh[NTOK * HID];
__device__ __nv_bfloat16 g_Vh[NTOK * HID];
__device__ __nv_bfloat16 g_AOh[NTOK * HID], g_AOl[NTOK * HID];
__device__ __nv_bfloat16 g_X1h[NTOK * HID], g_X1l[NTOK * HID];
__device__ __nv_bfloat16 g_Mh[NTOK * 2 * HID], g_Ml[NTOK * 2 * HID];
__device__ float g_X[NTOK * HID];
__device__ float g_X1[NTOK * HID];
__device__ float g_X2[NTOK * HID];
__device__ float g_psum[64 * HID];
__device__ float g_psq[64 * HID];

// ------------------- helpers -------------------
__device__ __forceinline__ void mma_bf16(float* c, const uint32_t* a, const uint32_t* b)
{
    asm volatile(
        "mma.sync.aligned.m16n8k16.row.col.f32.bf16.bf16.f32 "
        "{%0,%1,%2,%3}, {%4,%5,%6,%7}, {%8,%9}, {%0,%1,%2,%3};"
        : "+f"(c[0]), "+f"(c[1]), "+f"(c[2]), "+f"(c[3])
        : "r"(a[0]), "r"(a[1]), "r"(a[2]), "r"(a[3]), "r"(b[0]), "r"(b[1]));
}

__device__ __forceinline__ void split_pack(float x, float y, uint32_t& hi, uint32_t& lo)
{
    uint32_t h;
    asm("cvt.rn.bf16x2.f32 %0, %1, %2;" : "=r"(h) : "f"(y), "f"(x));
    float xr = __uint_as_float(h << 16);
    float yr = __uint_as_float(h & 0xffff0000u);
    float xl = x - xr, yl = y - yr;
    uint32_t l;
    asm("cvt.rn.bf16x2.f32 %0, %1, %2;" : "=r"(l) : "f"(yl), "f"(xl));
    hi = h; lo = l;
}

__device__ __forceinline__ uint32_t pack_bf16(float x, float y)
{
    uint32_t h;
    asm("cvt.rn.bf16x2.f32 %0, %1, %2;" : "=r"(h) : "f"(y), "f"(x));
    return h;
}

__device__ __forceinline__ float ex2(float x)
{
    float r;
    asm("ex2.approx.ftz.f32 %0, %1;" : "=f"(r) : "f"(x));
    return r;
}

__device__ __forceinline__ uint32_t scvta(const void* p)
{
    return (uint32_t)__cvta_generic_to_shared(p);
}

__device__ __forceinline__ void ldsm_x4(uint32_t* d, uint32_t addr)
{
    asm volatile("ldmatrix.sync.aligned.m8n8.x4.shared.b16 {%0,%1,%2,%3}, [%4];"
                 : "=r"(d[0]), "=r"(d[1]), "=r"(d[2]), "=r"(d[3]) : "r"(addr));
}

__device__ __forceinline__ void ldsm_x4_t(uint32_t* d, uint32_t addr)
{
    asm volatile("ldmatrix.sync.aligned.m8n8.x4.trans.shared.b16 {%0,%1,%2,%3}, [%4];"
                 : "=r"(d[0]), "=r"(d[1]), "=r"(d[2]), "=r"(d[3]) : "r"(addr));
}

__device__ __forceinline__ void cp_async16(uint32_t dst, const void* src)
{
    asm volatile("cp.async.cg.shared.global [%0], [%1], 16;" :: "r"(dst), "l"(src));
}

__device__ __forceinline__ void cp_commit() { asm volatile("cp.async.commit_group;"); }
__device__ __forceinline__ void cp_wait0()  { asm volatile("cp.async.wait_group 0;"); }

// ------------------- split_all (lo pointer may be null = hi-only job) ------------
struct SplitJob { const float* src; __nv_bfloat16* hi; __nv_bfloat16* lo; int n4; };
struct SplitJobs { SplitJob j[7]; };

__global__ void split_all(SplitJobs jobs)
{
    SplitJob job = jobs.j[blockIdx.y];
    for (int i = blockIdx.x * blockDim.x + threadIdx.x; i < job.n4;
         i += gridDim.x * blockDim.x) {
        float4 v = *(const float4*)&job.src[(size_t)i * 4];
        uint32_t h01, l01, h23, l23;
        split_pack(v.x, v.y, h01, l01);
        split_pack(v.z, v.w, h23, l23);
        *(uint32_t*)&job.hi[(size_t)i * 4]     = h01;
        *(uint32_t*)&job.hi[(size_t)i * 4 + 2] = h23;
        if (job.lo) {
            *(uint32_t*)&job.lo[(size_t)i * 4]     = l01;
            *(uint32_t*)&job.lo[(size_t)i * 4 + 2] = l23;
        }
    }
}

// ------------------- templated tensor-core GEMM (BM=64, 128 thr) -------------------
#define GKP 40
#define GPB (64 * GKP * 2)
#define GSMEM_FULL (2 * 4 * GPB)
#define GSMEM_PURE (2 * 2 * GPB)

template<int PURE>
__device__ __forceinline__ void gemm_stage(
    const __nv_bfloat16* __restrict__ Ahp, const __nv_bfloat16* __restrict__ Alp,
    const __nv_bfloat16* __restrict__ Whp, const __nv_bfloat16* __restrict__ Wlp,
    int i0, int j0, int K, int kk, uint32_t bufb, int tid)
{
    const uint32_t wofs = PURE ? GPB : 2 * GPB;
    #pragma unroll
    for (int t = 0; t < 2; t++) {
        int idx = tid + (t << 7);
        int r = idx >> 2, c8 = (idx & 3) * 8;
        uint32_t so = (uint32_t)((r * GKP + c8) * 2);
        cp_async16(bufb + so, Ahp + (size_t)(i0 + r) * K + kk + c8);
        cp_async16(bufb + wofs + so, Whp + (size_t)(j0 + r) * K + kk + c8);
        if (!PURE) {
            cp_async16(bufb + GPB + so, Alp + (size_t)(i0 + r) * K + kk + c8);
            cp_async16(bufb + 3 * GPB + so, Wlp + (size_t)(j0 + r) * K + kk + c8);
        }
    }
}

template<int MODE, int PURE>
__device__ __forceinline__ void gemm_core(
    const __nv_bfloat16* __restrict__ Ahp, const __nv_bfloat16* __restrict__ Alp,
    const __nv_bfloat16* __restrict__ Whp, const __nv_bfloat16* __restrict__ Wlp,
    const float* __restrict__ bias, float* __restrict__ C,
    __nv_bfloat16* __restrict__ Ch, __nv_bfloat16* __restrict__ Cl,
    const float* __restrict__ Rin, float* __restrict__ psum, float* __restrict__ psq,
    int Nout, int K, float scale, int relu, char* smemraw)
{
    const int tid = threadIdx.x, w = tid >> 5, lane = tid & 31;
    const int qr = lane >> 2, qc2 = (lane & 3) * 2;
    const int i0 = blockIdx.y * 64, j0 = blockIdx.x * 64;
    const int r0 = w * 16;
    const uint32_t PBUF = PURE ? 2 * GPB : 4 * GPB;

    float acc[8][4] = {};

    const int arow = r0 + ((lane >> 3) & 1) * 8 + (lane & 7);
    const int acol = (lane >> 4) * 8;
    const int brow = (lane & 7);
    const int bcol = (lane >> 3) * 8;
    const uint32_t wofs = PURE ? GPB : 2 * GPB;

    const uint32_t smb = scvta(smemraw);
    const int nch = K / 32;

    gemm_stage<PURE>(Ahp, Alp, Whp, Wlp, i0, j0, K, 0, smb, tid);
    cp_commit(); cp_wait0(); __syncthreads();

    int p = 0;
    for (int c = 0; c < nch; c++) {
        if (c + 1 < nch)
            gemm_stage<PURE>(Ahp, Alp, Whp, Wlp, i0, j0, K, (c + 1) * 32,
                             smb + (uint32_t)(p ^ 1) * PBUF, tid);
        cp_commit();

        const uint32_t base = smb + (uint32_t)p * PBUF;
        uint32_t ah[2][4], al[2][4];
        #pragma unroll
        for (int ks = 0; ks < 2; ks++) {
            uint32_t off = (uint32_t)((arow * GKP + ks * 16 + acol) * 2);
            ldsm_x4(ah[ks], base + off);
            if (!PURE) ldsm_x4(al[ks], base + GPB + off);
        }
        #pragma unroll
        for (int nt = 0; nt < 8; nt++) {
            uint32_t bh[4], bl[4];
            uint32_t off = (uint32_t)(((nt * 8 + brow) * GKP + bcol) * 2);
            ldsm_x4(bh, base + wofs + off);
            if (!PURE) ldsm_x4(bl, base + 3 * GPB + off);
            mma_bf16(acc[nt], ah[0], bh);
            mma_bf16(acc[nt], ah[1], bh + 2);
            if (!PURE) {
                mma_bf16(acc[nt], al[0], bh);
                mma_bf16(acc[nt], ah[0], bl);
                mma_bf16(acc[nt], al[1], bh + 2);
                mma_bf16(acc[nt], ah[1], bl + 2);
            }
        }
        cp_wait0();
        __syncthreads();
        p ^= 1;
    }

    const int ra = i0 + r0 + qr, rb = ra + 8;

    if (MODE != 2) {
        #pragma unroll
        for (int nt = 0; nt < 8; nt++) {
            int j = j0 + nt * 8 + qc2;
            float b0 = bias[j], b1 = bias[j + 1];
            float v00 = (acc[nt][0] + b0) * scale;
            float v01 = (acc[nt][1] + b1) * scale;
            float v10 = (acc[nt][2] + b0) * scale;
            float v11 = (acc[nt][3] + b1) * scale;
            if (relu) {
                v00 = fmaxf(v00, 0.f); v01 = fmaxf(v01, 0.f);
                v10 = fmaxf(v10, 0.f); v11 = fmaxf(v11, 0.f);
            }
            if (MODE == 0) {
                *(float2*)&C[(size_t)ra * Nout + j] = make_float2(v00, v01);
                *(float2*)&C[(size_t)rb * Nout + j] = make_float2(v10, v11);
            } else if (MODE == 4) {
                *(uint32_t*)&Ch[(size_t)ra * Nout + j] = pack_bf16(v00, v01);
                *(uint32_t*)&Ch[(size_t)rb * Nout + j] = pack_bf16(v10, v11);
            } else {
                uint32_t h0, l0, h1, l1;
                split_pack(v00, v01, h0, l0);
                split_pack(v10, v11, h1, l1);
                *(uint32_t*)&Ch[(size_t)ra * Nout + j] = h0;
                *(uint32_t*)&Cl[(size_t)ra * Nout + j] = l0;
                *(uint32_t*)&Ch[(size_t)rb * Nout + j] = h1;
                *(uint32_t*)&Cl[(size_t)rb * Nout + j] = l1;
            }
        }
    } else {
        float cs[8][2], cq[8][2];
        #pragma unroll
        for (int nt = 0; nt < 8; nt++) {
            int j = j0 + nt * 8 + qc2;
            float b0 = bias[j], b1 = bias[j + 1];
            float2 r0v = *(const float2*)&Rin[(size_t)ra * Nout + j];
            float2 r1v = *(const float2*)&Rin[(size_t)rb * Nout + j];
            float x00 = acc[nt][0] + b0 + r0v.x;
            float x01 = acc[nt][1] + b1 + r0v.y;
            float x10 = acc[nt][2] + b0 + r1v.x;
            float x11 = acc[nt][3] + b1 + r1v.y;
            *(float2*)&C[(size_t)ra * Nout + j] = make_float2(x00, x01);
            *(float2*)&C[(size_t)rb * Nout + j] = make_float2(x10, x11);
            cs[nt][0] = x00 + x10;
            cs[nt][1] = x01 + x11;
            cq[nt][0] = x00 * x00 + x10 * x10;
            cq[nt][1] = x01 * x01 + x11 * x11;
        }
        #pragma unroll
        for (int m = 4; m <= 16; m <<= 1) {
            #pragma unroll
            for (int nt = 0; nt < 8; nt++) {
                cs[nt][0] += __shfl_xor_sync(0xffffffffu, cs[nt][0], m);
                cs[nt][1] += __shfl_xor_sync(0xffffffffu, cs[nt][1], m);
                cq[nt][0] += __shfl_xor_sync(0xffffffffu, cq[nt][0], m);
                cq[nt][1] += __shfl_xor_sync(0xffffffffu, cq[nt][1], m);
            }
        }
        float* sred = (float*)smemraw;
        float* qred = (float*)(smemraw + 4 * 64 * 4);
        if (lane < 4) {
            #pragma unroll
            for (int nt = 0; nt < 8; nt++) {
                int jj = nt * 8 + (lane & 3) * 2;
                sred[w * 64 + jj]     = cs[nt][0];
                sred[w * 64 + jj + 1] = cs[nt][1];
                qred[w * 64 + jj]     = cq[nt][0];
                qred[w * 64 + jj + 1] = cq[nt][1];
            }
        }
        __syncthreads();
        if (tid < 64) {
            float s = sred[tid] + sred[64 + tid] + sred[128 + tid] + sred[192 + tid];
            psum[(size_t)blockIdx.y * HID + j0 + tid] = s;
        } else if (tid < 128) {
            int t = tid - 64;
            float q = qred[t] + qred[64 + t] + qred[128 + t] + qred[192 + t];
            psq[(size_t)blockIdx.y * HID + j0 + t] = q;
        }
    }
}

__global__ void __launch_bounds__(128, 4)
gemm_resbn(const __nv_bfloat16* Ahp, const __nv_bfloat16* Alp,
           const __nv_bfloat16* Whp, const __nv_bfloat16* Wlp,
           const float* bias, float* C, const float* Rin,
           float* psum, float* psq, int Nout, int K)
{
    extern __shared__ __align__(16) char smemraw[];
    gemm_core<2, 0>(Ahp, Alp, Whp, Wlp, bias, C, nullptr, nullptr, Rin, psum, psq,
                    Nout, K, 1.f, 0, smemraw);
}

__global__ void __launch_bounds__(128, 4)
gemm_planes(const __nv_bfloat16* Ahp, const __nv_bfloat16* Alp,
            const __nv_bfloat16* Whp, const __nv_bfloat16* Wlp,
            const float* bias, __nv_bfloat16* Ch, __nv_bfloat16* Cl,
            int Nout, int K, int relu)
{
    extern __shared__ __align__(16) char smemraw[];
    gemm_core<1, 0>(Ahp, Alp, Whp, Wlp, bias, nullptr, Ch, Cl, nullptr, nullptr, nullptr,
                    Nout, K, 1.f, relu, smemraw);
}

__global__ void __launch_bounds__(128, 4)
gemm_qkv(const __nv_bfloat16* hh,
         const __nv_bfloat16* Wqh, const float* bq, __nv_bfloat16* Qh,
         const __nv_bfloat16* Wkh, const float* bk, __nv_bfloat16* Kh,
         const __nv_bfloat16* Wvh, const float* bv, __nv_bfloat16* Vh)
{
    extern __shared__ __align__(16) char smemraw[];
    const __nv_bfloat16* Wh; const float* b; __nv_bfloat16* Ch; float sc;
    if (blockIdx.z == 0)      { Wh = Wqh; b = bq; Ch = Qh; sc = QK2SCALE; }
    else if (blockIdx.z == 1) { Wh = Wkh; b = bk; Ch = Kh; sc = 1.f; }
    else                      { Wh = Wvh; b = bv; Ch = Vh; sc = 1.f; }
    gemm_core<4, 1>(hh, nullptr, Wh, nullptr, b, nullptr, Ch, nullptr,
                    nullptr, nullptr, nullptr, HID, HID, sc, 0, smemraw);
}

// ------------------- flash attention: 2 heads/CTA (warp-split), BM=64 -------------
// Warps 0-3: head 2y, warps 4-7: head 2y+1 — same rows, shared A tile (L1-hot).
// smem per buffer set: [K0][V0][K1][V1], each 64*KP bf16. Double-buffered.
#define KP 56
#define ARRB (64 * KP * 2)           // 7168 per array
#define SETB (4 * ARRB)              // 28672 per buffer set
#define FLASH_SMEM (2 * SETB)        // 57344

__global__ void __launch_bounds__(256, 2)
flash_attn_mma(const __nv_bfloat16* __restrict__ Qhg,
               const __nv_bfloat16* __restrict__ Khg,
               const __nv_bfloat16* __restrict__ Vhg,
               const float* __restrict__ Amat,
               __nv_bfloat16* __restrict__ AOh, __nv_bfloat16* __restrict__ AOl)
{
    extern __shared__ __align__(16) char smemraw[];

    const int tid  = threadIdx.x;
    const int w    = tid >> 5;
    const int lane = tid & 31;
    const int qr   = lane >> 2;
    const int qc2  = (lane & 3) * 2;

    const int hd0  = blockIdx.y * 2;          // first head of the pair
    const int whd  = w >> 2;                  // this warp's head (0/1 within pair)
    const int row0 = blockIdx.x * 64;
    const int r0   = (w & 3) * 16;

    const size_t hbase = (size_t)(hd0 + whd) * NTOK * HD;

    uint32_t aQh[2][4];
    {
        const size_t ra = hbase + (size_t)(row0 + r0 + qr) * HD;
        const size_t rb = ra + 8 * HD;
        #pragma unroll
        for (int ks = 0; ks < 2; ks++) {
            int cb = ks * 16 + qc2;
            aQh[ks][0] = *(const uint32_t*)&Qhg[ra + cb];
            aQh[ks][1] = *(const uint32_t*)&Qhg[rb + cb];
            aQh[ks][2] = *(const uint32_t*)&Qhg[ra + cb + 8];
            aQh[ks][3] = *(const uint32_t*)&Qhg[rb + cb + 8];
        }
    }

    float oacc[4][4] = {};
    float ls0 = 0.f, ls1 = 0.f;

    const int ga = (row0 + r0 + qr) * NTOK;
    const int gb = (row0 + r0 + qr + 8) * NTOK;

    const uint32_t smb = scvta(smemraw);
    const uint32_t khb = smb + (uint32_t)(whd * 2) * ARRB;
    const uint32_t vhb = khb + ARRB;
    const uint32_t koff = (uint32_t)(((lane & 7) * KP + (lane >> 3) * 8) * 2);
    const uint32_t vtoff = (uint32_t)(lane * KP * 2);

    // staging: thread tid stages array tid>>6 (K0,V0,K1,V1), 4 chunks each
    const int sarr = tid >> 6;
    const int sid0 = tid & 63;
    const __nv_bfloat16* sbase = (sarr & 1) ? Vhg : Khg;
    const char* gsrc = (const char*)(sbase + (size_t)(hd0 + (sarr >> 1)) * NTOK * HD);
    const uint32_t sdstb = smb + (uint32_t)sarr * ARRB;
    uint32_t soff[4];
    #pragma unroll
    for (int t = 0; t < 4; t++) {
        int idx = sid0 + t * 64;
        int r = idx >> 2, c8 = (idx & 3) * 8;
        soff[t] = (uint32_t)((r * KP + c8) * 2);
    }

    #pragma unroll
    for (int t = 0; t < 4; t++)
        cp_async16(sdstb + soff[t], gsrc + (size_t)(sid0 + t * 64) * 16);
    cp_commit();
    cp_wait0();
    __syncthreads();

    int p = 0;
    for (int mt = 0; mt < NTOK / 64; mt++) {
        const int m0 = mt * 64;
        const uint32_t pofs = (uint32_t)p * SETB;

        if (mt < NTOK / 64 - 1) {
            const char* src = gsrc + (size_t)(mt + 1) * 64 * HD * 2;
            const uint32_t db = sdstb + (pofs ^ SETB);
            #pragma unroll
            for (int t = 0; t < 4; t++)
                cp_async16(db + soff[t], src + (size_t)(sid0 + t * 64) * 16);
        }
        cp_commit();

        float2 Ar[8], Br[8];
        #pragma unroll
        for (int nt = 0; nt < 8; nt++) {
            int gc = m0 + nt * 8 + qc2;
            Ar[nt] = *(const float2*)&Amat[(size_t)ga + gc];
            Br[nt] = *(const float2*)&Amat[(size_t)gb + gc];
        }

        float sacc[8][4];
        #pragma unroll
        for (int nt = 0; nt < 8; nt++) {
            sacc[nt][0] = sacc[nt][1] = sacc[nt][2] = sacc[nt][3] = 0.f;
            uint32_t off = koff + pofs + (uint32_t)(nt * 8 * KP * 2);
            uint32_t bh[4];
            ldsm_x4(bh, khb + off);
            mma_bf16(sacc[nt], aQh[0], bh);
            mma_bf16(sacc[nt], aQh[1], bh + 2);
        }

        #pragma unroll
        for (int nt = 0; nt < 8; nt++) {
            sacc[nt][0] = ex2(sacc[nt][0] * Ar[nt].x);
            sacc[nt][1] = ex2(sacc[nt][1] * Ar[nt].y);
            sacc[nt][2] = ex2(sacc[nt][2] * Br[nt].x);
            sacc[nt][3] = ex2(sacc[nt][3] * Br[nt].y);
            ls0 += sacc[nt][0] + sacc[nt][1];
            ls1 += sacc[nt][2] + sacc[nt][3];
        }

        uint32_t ph[4][4];
        #pragma unroll
        for (int kc = 0; kc < 4; kc++) {
            ph[kc][0] = pack_bf16(sacc[2 * kc][0],     sacc[2 * kc][1]);
            ph[kc][1] = pack_bf16(sacc[2 * kc][2],     sacc[2 * kc][3]);
            ph[kc][2] = pack_bf16(sacc[2 * kc + 1][0], sacc[2 * kc + 1][1]);
            ph[kc][3] = pack_bf16(sacc[2 * kc + 1][2], sacc[2 * kc + 1][3]);
        }

        #pragma unroll
        for (int nt = 0; nt < 4; nt++) {
            uint32_t off = vtoff + pofs + (uint32_t)(nt * 16);
            uint32_t bh[8];
            ldsm_x4_t(bh,     vhb + off);
            ldsm_x4_t(bh + 4, vhb + off + 32 * KP * 2);
            #pragma unroll
            for (int kc = 0; kc < 4; kc++)
                mma_bf16(oacc[nt], ph[kc], bh + kc * 2);
        }

        cp_wait0();
        __syncthreads();
        p ^= 1;
    }

    ls0 += __shfl_xor_sync(0xffffffffu, ls0, 1);
    ls0 += __shfl_xor_sync(0xffffffffu, ls0, 2);
    ls1 += __shfl_xor_sync(0xffffffffu, ls1, 1);
    ls1 += __shfl_xor_sync(0xffffffffu, ls1, 2);
    float inv0 = 1.f / ls0, inv1 = 1.f / ls1;

    const size_t ra = hbase + (size_t)(row0 + r0 + qr) * HD;
    const size_t rb = ra + 8 * HD;
    #pragma unroll
    for (int nt = 0; nt < 4; nt++) {
        int c = nt * 8 + qc2;
        uint32_t h0, l0, h1, l1;
        split_pack(oacc[nt][0] * inv0, oacc[nt][1] * inv0, h0, l0);
        split_pack(oacc[nt][2] * inv1, oacc[nt][3] * inv1, h1, l1);
        *(uint32_t*)&AOh[ra + c] = h0;
        *(uint32_t*)&AOl[ra + c] = l0;
        *(uint32_t*)&AOh[rb + c] = h1;
        *(uint32_t*)&AOl[rb + c] = l1;
    }
}

// ------------------- fused BN finalize + apply -------------------
__global__ void __launch_bounds__(256)
bn_fused(const float* __restrict__ Xp,
         const float* __restrict__ psum, const float* __restrict__ psq,
         const float* __restrict__ g, const float* __restrict__ be,
         float* __restrict__ out,
         __nv_bfloat16* __restrict__ oh, __nv_bfloat16* __restrict__ ol,
         int emit_planes)
{
    __shared__ float ssc[HID], ssh[HID];
    const int tid = threadIdx.x;
    float s = 0.f, q = 0.f;
    #pragma unroll
    for (int b = 0; b < 64; b++) {
        s += psum[b * HID + tid];
        q += psq[b * HID + tid];
    }
    float m = s * (1.f / NTOK);
    float var = fmaxf(q * (1.f / NTOK) - m * m, 0.f);
    float sc = rsqrtf(var + EPSBN) * g[tid];
    ssc[tid] = sc;
    ssh[tid] = be[tid] - m * sc;
    __syncthreads();

    const int j = (tid * 4) & (HID - 1);
    float4 sc4 = *(const float4*)&ssc[j];
    float4 sh4 = *(const float4*)&ssh[j];
    #pragma unroll
    for (int pass = 0; pass < 8; pass++) {
        size_t e = (size_t)blockIdx.x * 8192 + pass * 1024 + tid * 4;
        float4 av = *(const float4*)&Xp[e];
        float4 ov;
        ov.x = av.x * sc4.x + sh4.x;
        ov.y = av.y * sc4.y + sh4.y;
        ov.z = av.z * sc4.z + sh4.z;
        ov.w = av.w * sc4.w + sh4.w;
        *(float4*)&out[e] = ov;
        if (emit_planes) {
            uint32_t h01, l01, h23, l23;
            split_pack(ov.x, ov.y, h01, l01);
            split_pack(ov.z, ov.w, h23, l23);
            *(uint32_t*)&oh[e]     = h01;
            *(uint32_t*)&oh[e + 2] = h23;
            *(uint32_t*)&ol[e]     = l01;
            *(uint32_t*)&ol[e + 2] = l23;
        }
    }
}

// ------------------- launch -------------------
extern "C" void kernel_launch(void* const* d_in, const int* in_sizes, int n_in,
                              void* d_out, int out_size)
{
    const float* A   = (const float*)d_in[0];
    const float* h   = (const float*)d_in[1];
    const float* Wq  = (const float*)d_in[2];
    const float* bq  = (const float*)d_in[3];
    const float* Wk  = (const float*)d_in[4];
    const float* bk  = (const float*)d_in[5];
    const float* Wv  = (const float*)d_in[6];
    const float* bv  = (const float*)d_in[7];
    const float* Wo  = (const float*)d_in[8];
    const float* bo  = (const float*)d_in[9];
    const float* W1  = (const float*)d_in[10];
    const float* c1  = (const float*)d_in[11];
    const float* W2  = (const float*)d_in[12];
    const float* c2  = (const float*)d_in[13];
    const float* g1  = (const float*)d_in[14];
    const float* be1 = (const float*)d_in[15];
    const float* g2  = (const float*)d_in[16];
    const float* be2 = (const float*)d_in[17];
    float* out = (float*)d_out;

    __nv_bfloat16 *hh, *Wqh, *Wkh, *Wvh, *Woh, *Wol, *W1h, *W1l, *W2h, *W2l,
                  *Qh, *Kh, *Vh, *AOh, *AOl, *X1h, *X1l, *Mh, *Ml;
    float *X, *X1, *X2, *psum, *psq;
    cudaGetSymbolAddress((void**)&hh,  g_hh);
    cudaGetSymbolAddress((void**)&Wqh, g_Wqh);
    cudaGetSymbolAddress((void**)&Wkh, g_Wkh);
    cudaGetSymbolAddress((void**)&Wvh, g_Wvh);
    cudaGetSymbolAddress((void**)&Woh, g_Woh); cudaGetSymbolAddress((void**)&Wol, g_Wol);
    cudaGetSymbolAddress((void**)&W1h, g_W1h); cudaGetSymbolAddress((void**)&W1l, g_W1l);
    cudaGetSymbolAddress((void**)&W2h, g_W2h); cudaGetSymbolAddress((void**)&W2l, g_W2l);
    cudaGetSymbolAddress((void**)&Qh, g_Qh);
    cudaGetSymbolAddress((void**)&Kh, g_Kh);
    cudaGetSymbolAddress((void**)&Vh, g_Vh);
    cudaGetSymbolAddress((void**)&AOh, g_AOh); cudaGetSymbolAddress((void**)&AOl, g_AOl);
    cudaGetSymbolAddress((void**)&X1h, g_X1h); cudaGetSymbolAddress((void**)&X1l, g_X1l);
    cudaGetSymbolAddress((void**)&Mh, g_Mh);   cudaGetSymbolAddress((void**)&Ml, g_Ml);
    cudaGetSymbolAddress((void**)&X,   g_X);
    cudaGetSymbolAddress((void**)&X1,  g_X1);
    cudaGetSymbolAddress((void**)&X2,  g_X2);
    cudaGetSymbolAddress((void**)&psum, g_psum);
    cudaGetSymbolAddress((void**)&psq,  g_psq);

    cudaFuncSetAttribute(flash_attn_mma,
                         cudaFuncAttributeMaxDynamicSharedMemorySize, FLASH_SMEM);
    cudaFuncSetAttribute(gemm_resbn,
                         cudaFuncAttributeMaxDynamicSharedMemorySize, GSMEM_FULL);
    cudaFuncSetAttribute(gemm_planes,
                         cudaFuncAttributeMaxDynamicSharedMemorySize, GSMEM_FULL);
    cudaFuncSetAttribute(gemm_qkv,
                         cudaFuncAttributeMaxDynamicSharedMemorySize, GSMEM_PURE);

    dim3 gqkv(HID / 64, NTOK / 64, 3);
    dim3 gproj(HID / 64, NTOK / 64);
    dim3 gffn1(2 * HID / 64, NTOK / 64);
    dim3 gattn(NTOK / 64, NHEADS / 2);      // 64 x 4 (2 heads per CTA)

    SplitJobs jobs;
    jobs.j[0] = { h,  hh,  nullptr, NTOK * HID / 4 };
    jobs.j[1] = { Wq, Wqh, nullptr, HID * HID / 4 };
    jobs.j[2] = { Wk, Wkh, nullptr, HID * HID / 4 };
    jobs.j[3] = { Wv, Wvh, nullptr, HID * HID / 4 };
    jobs.j[4] = { Wo, Woh, Wol, HID * HID / 4 };
    jobs.j[5] = { W1, W1h, W1l, 2 * HID * HID / 4 };
    jobs.j[6] = { W2, W2h, W2l, 2 * HID * HID / 4 };
    split_all<<<dim3(64, 7), 256>>>(jobs);

    gemm_qkv<<<gqkv, 128, GSMEM_PURE>>>(hh, Wqh, bq, Qh, Wkh, bk, Kh, Wvh, bv, Vh);

    flash_attn_mma<<<gattn, 256, FLASH_SMEM>>>(Qh, Kh, Vh, A, AOh, AOl);

    gemm_resbn<<<gproj, 128, GSMEM_FULL>>>(AOh, AOl, Woh, Wol, bo, X, h,
                                           psum, psq, HID, HID);
    bn_fused<<<128, 256>>>(X, psum, psq, g1, be1, X1, X1h, X1l, 1);

    gemm_planes<<<gffn1, 128, GSMEM_FULL>>>(X1h, X1l, W1h, W1l, c1, Mh, Ml,
                                            2 * HID, HID, 1);
    gemm_resbn<<<gproj, 128, GSMEM_FULL>>>(Mh, Ml, W2h, W2l, c2, X2, X1,
                                           psum, psq, HID, 2 * HID);
    bn_fused<<<128, 256>>>(X2, psum, psq, g2, be2, out, nullptr, nullptr, 0);
}